// round 1
// baseline (speedup 1.0000x reference)
#include <cuda_runtime.h>
#include <math.h>

#define S_    2048
#define HID_  2048
#define NH_   16
#define NKV_  4
#define D_    128
#define HB_   204
#define RB_   204
#define NEG_  (-3.4028234663852886e38f)

// ---------------- scratch (device globals; no allocations allowed) ----------------
__device__ float g_q[S_ * HID_];            // [s][h*128+d]
__device__ float g_k[S_ * NKV_ * D_];       // [s][kh*128+d]
__device__ float g_v[S_ * NKV_ * D_];
__device__ float g_scores[(size_t)NH_ * S_ * S_];   // 256 MB
__device__ float g_m1[NH_ * S_], g_invl1[NH_ * S_];
__device__ float g_m2[NH_ * S_], g_invl2[NH_ * S_];
__device__ float g_colsum[NH_ * S_];
__device__ int   g_heavy[NH_ * S_];
__device__ float g_attnout[S_ * HID_];

// ---------------- generic reg-blocked SGEMM: C[M,N] = A[M,K] @ B[K,N] ----------------
__global__ __launch_bounds__(256) void sgemm128(const float* __restrict__ A,
                                                const float* __restrict__ B,
                                                float* __restrict__ C,
                                                int M, int N, int K) {
    __shared__ float As[8][128];
    __shared__ float Bs[8][128];
    int tid = threadIdx.x;
    int i0 = blockIdx.y * 128, j0 = blockIdx.x * 128;
    int tx = tid & 15, ty = tid >> 4;
    int aRow = tid >> 1, aCol = (tid & 1) * 4;
    int bRow = tid >> 5, bCol = (tid & 31) * 4;
    float acc[8][8];
#pragma unroll
    for (int i = 0; i < 8; i++)
#pragma unroll
        for (int j = 0; j < 8; j++) acc[i][j] = 0.f;

    for (int k0 = 0; k0 < K; k0 += 8) {
        float4 av = *(const float4*)(A + (size_t)(i0 + aRow) * K + k0 + aCol);
        As[aCol + 0][aRow] = av.x; As[aCol + 1][aRow] = av.y;
        As[aCol + 2][aRow] = av.z; As[aCol + 3][aRow] = av.w;
        float4 bv = *(const float4*)(B + (size_t)(k0 + bRow) * N + j0 + bCol);
        *(float4*)&Bs[bRow][bCol] = bv;
        __syncthreads();
#pragma unroll
        for (int kk = 0; kk < 8; kk++) {
            float a[8], b[8];
#pragma unroll
            for (int i = 0; i < 8; i++) a[i] = As[kk][ty * 8 + i];
#pragma unroll
            for (int j = 0; j < 8; j++) b[j] = Bs[kk][tx * 8 + j];
#pragma unroll
            for (int i = 0; i < 8; i++)
#pragma unroll
                for (int j = 0; j < 8; j++) acc[i][j] = fmaf(a[i], b[j], acc[i][j]);
        }
        __syncthreads();
    }
#pragma unroll
    for (int i = 0; i < 8; i++)
#pragma unroll
        for (int j = 0; j < 8; j += 4) {
            float4 v = make_float4(acc[i][j], acc[i][j + 1], acc[i][j + 2], acc[i][j + 3]);
            *(float4*)(C + (size_t)(i0 + ty * 8 + i) * N + j0 + tx * 8 + j) = v;
        }
}

// ---------------- RoPE (in place; one thread per (s, h, d<64) pair) ----------------
__global__ void rope_kernel(float* x, int nh) {
    int idx = blockIdx.x * blockDim.x + threadIdx.x;
    int total = S_ * nh * 64;
    if (idx >= total) return;
    int d = idx & 63;
    int rest = idx >> 6;
    int h = rest % nh;
    int s = rest / nh;
    float* base = x + (size_t)s * nh * 128 + h * 128;
    float x1 = base[d], x2 = base[d + 64];
    float inv = powf(10000.f, -(float)d * (1.f / 64.f));
    float ang = (float)s * inv;
    float c, sn;
    sincosf(ang, &sn, &c);
    base[d]      = x1 * c - x2 * sn;
    base[d + 64] = x2 * c + x1 * sn;
}

// ---------------- scores[h][i][j] = q_i . k_j / sqrt(D), causal NEG ----------------
__global__ __launch_bounds__(256) void scores_kernel() {
    int h = blockIdx.z, kh = h >> 2;
    int i0 = blockIdx.y * 128, j0 = blockIdx.x * 128;
    float* out = g_scores + (size_t)h * S_ * S_;
    int tid = threadIdx.x;

    if (j0 >= i0 + 128) {  // fully above diagonal
        float4 n4 = make_float4(NEG_, NEG_, NEG_, NEG_);
        for (int e = tid * 4; e < 128 * 128; e += 1024) {
            int ii = e >> 7, jj = e & 127;
            *(float4*)(out + (size_t)(i0 + ii) * S_ + j0 + jj) = n4;
        }
        return;
    }

    __shared__ float Qs[8][128];
    __shared__ float Ks[8][128];
    int tx = tid & 15, ty = tid >> 4;
    int lRow = tid >> 1, lCol = (tid & 1) * 4;
    float acc[8][8];
#pragma unroll
    for (int i = 0; i < 8; i++)
#pragma unroll
        for (int j = 0; j < 8; j++) acc[i][j] = 0.f;

    for (int k0 = 0; k0 < D_; k0 += 8) {
        float4 qv = *(const float4*)(g_q + (size_t)(i0 + lRow) * HID_ + h * D_ + k0 + lCol);
        Qs[lCol + 0][lRow] = qv.x; Qs[lCol + 1][lRow] = qv.y;
        Qs[lCol + 2][lRow] = qv.z; Qs[lCol + 3][lRow] = qv.w;
        float4 kv = *(const float4*)(g_k + (size_t)(j0 + lRow) * (NKV_ * D_) + kh * D_ + k0 + lCol);
        Ks[lCol + 0][lRow] = kv.x; Ks[lCol + 1][lRow] = kv.y;
        Ks[lCol + 2][lRow] = kv.z; Ks[lCol + 3][lRow] = kv.w;
        __syncthreads();
#pragma unroll
        for (int kk = 0; kk < 8; kk++) {
            float a[8], b[8];
#pragma unroll
            for (int i = 0; i < 8; i++) a[i] = Qs[kk][ty * 8 + i];
#pragma unroll
            for (int j = 0; j < 8; j++) b[j] = Ks[kk][tx * 8 + j];
#pragma unroll
            for (int i = 0; i < 8; i++)
#pragma unroll
                for (int j = 0; j < 8; j++) acc[i][j] = fmaf(a[i], b[j], acc[i][j]);
        }
        __syncthreads();
    }
    const float sc = 0.08838834764831845f;  // 1/sqrt(128)
#pragma unroll
    for (int i = 0; i < 8; i++) {
        int gi = i0 + ty * 8 + i;
#pragma unroll
        for (int j = 0; j < 8; j++) {
            int gj = j0 + tx * 8 + j;
            float v = (gj <= gi) ? acc[i][j] * sc : NEG_;
            out[(size_t)gi * S_ + gj] = v;
        }
    }
}

// ---------------- per-row max + 1/sum(exp) (optionally with H2O keep mask) ----------------
__global__ __launch_bounds__(256) void rowstats_kernel(float* __restrict__ m_out,
                                                       float* __restrict__ invl_out,
                                                       int masked) {
    int i = blockIdx.x, h = blockIdx.y;
    const float* row = g_scores + (size_t)(h * S_ + i) * S_;
    int tid = threadIdx.x;
    __shared__ float red[256];

    float mloc = -INFINITY;
    for (int j = tid; j < S_; j += 256) {
        float s = row[j];
        if (masked) {
            int dd = i - j; if (dd < 0) dd = -dd;
            bool keep = (dd <= RB_) || g_heavy[h * S_ + j];
            if (!keep) s = NEG_;
        }
        mloc = fmaxf(mloc, s);
    }
    red[tid] = mloc; __syncthreads();
    for (int off = 128; off > 0; off >>= 1) {
        if (tid < off) red[tid] = fmaxf(red[tid], red[tid + off]);
        __syncthreads();
    }
    float m = red[0];
    __syncthreads();

    float lloc = 0.f;
    for (int j = tid; j < S_; j += 256) {
        float s = row[j];
        if (masked) {
            int dd = i - j; if (dd < 0) dd = -dd;
            bool keep = (dd <= RB_) || g_heavy[h * S_ + j];
            if (!keep) s = NEG_;
        }
        lloc += expf(s - m);
    }
    red[tid] = lloc; __syncthreads();
    for (int off = 128; off > 0; off >>= 1) {
        if (tid < off) red[tid] += red[tid + off];
        __syncthreads();
    }
    if (tid == 0) {
        m_out[h * S_ + i] = m;
        invl_out[h * S_ + i] = 1.f / red[0];
    }
}

// ---------------- colsum[h][j] = sum_i softmax(scores)[i][j] ----------------
__global__ __launch_bounds__(256) void colsum_kernel() {
    int h = blockIdx.y;
    int j = blockIdx.x * 256 + threadIdx.x;
    const float* base = g_scores + (size_t)h * S_ * S_;
    float acc = 0.f;
#pragma unroll 8
    for (int i = 0; i < S_; i++) {
        float s = base[(size_t)i * S_ + j];
        acc += expf(s - g_m1[h * S_ + i]) * g_invl1[h * S_ + i];
    }
    g_colsum[h * S_ + j] = acc;
}

// ---------------- per-head top-204 (value desc, index asc — matches lax.top_k) ----------------
__global__ __launch_bounds__(256) void topk_kernel() {
    int h = blockIdx.x;
    int tid = threadIdx.x;
    __shared__ float vals[S_];
    __shared__ float bv[256];
    __shared__ int bi[256];
    for (int j = tid; j < S_; j += 256) {
        vals[j] = g_colsum[h * S_ + j];
        g_heavy[h * S_ + j] = 0;
    }
    __syncthreads();
    for (int it = 0; it < HB_; it++) {
        float best = -INFINITY; int besti = 1 << 30;
        for (int j = tid; j < S_; j += 256) {
            float v = vals[j];
            if (v > best || (v == best && j < besti)) { best = v; besti = j; }
        }
        bv[tid] = best; bi[tid] = besti; __syncthreads();
        for (int off = 128; off > 0; off >>= 1) {
            if (tid < off) {
                if (bv[tid + off] > bv[tid] ||
                    (bv[tid + off] == bv[tid] && bi[tid + off] < bi[tid])) {
                    bv[tid] = bv[tid + off]; bi[tid] = bi[tid + off];
                }
            }
            __syncthreads();
        }
        if (tid == 0) { g_heavy[h * S_ + bi[0]] = 1; vals[bi[0]] = -INFINITY; }
        __syncthreads();
    }
}

// ---------------- PV: out[i][h*128+d] = sum_j p[i][j] * v[j][d] ----------------
__global__ __launch_bounds__(256) void pv_kernel() {
    int h = blockIdx.y, kh = h >> 2;
    int i0 = blockIdx.x * 64;
    __shared__ float Ps[64][64];     // 16 KB
    __shared__ float Vs[64][128];    // 32 KB
    int tid = threadIdx.x;
    int tx = tid & 15, ty = tid >> 4;
    float acc[4][8];
#pragma unroll
    for (int r = 0; r < 4; r++)
#pragma unroll
        for (int c = 0; c < 8; c++) acc[r][c] = 0.f;

    const float* srow = g_scores + (size_t)h * S_ * S_;
    int jmax = i0 + 64;  // causal: only chunks with j0 <= i0+63 contribute
    for (int j0 = 0; j0 < jmax; j0 += 64) {
        // build P tile
        for (int e = tid; e < 64 * 64; e += 256) {
            int ii = e >> 6, jj = e & 63;
            int gi = i0 + ii, gj = j0 + jj;
            float s = srow[(size_t)gi * S_ + gj];
            int dd = gi - gj; if (dd < 0) dd = -dd;
            bool keep = (dd <= RB_) || g_heavy[h * S_ + gj];
            float p = 0.f;
            if (keep) p = expf(s - g_m2[h * S_ + gi]) * g_invl2[h * S_ + gi];
            Ps[ii][jj] = p;
        }
        // load V chunk
        for (int e = tid * 4; e < 64 * 128; e += 1024) {
            int jj = e >> 7, d = e & 127;
            float4 v4 = *(const float4*)(g_v + (size_t)(j0 + jj) * (NKV_ * D_) + kh * D_ + d);
            *(float4*)&Vs[jj][d] = v4;
        }
        __syncthreads();
#pragma unroll
        for (int kk4 = 0; kk4 < 16; kk4++) {
            float4 a4[4];
#pragma unroll
            for (int r = 0; r < 4; r++) a4[r] = *(const float4*)&Ps[ty * 4 + r][kk4 * 4];
#pragma unroll
            for (int u = 0; u < 4; u++) {
                float b[8];
#pragma unroll
                for (int c = 0; c < 8; c++) b[c] = Vs[kk4 * 4 + u][tx * 8 + c];
#pragma unroll
                for (int r = 0; r < 4; r++) {
                    float av = ((const float*)&a4[r])[u];
#pragma unroll
                    for (int c = 0; c < 8; c++) acc[r][c] = fmaf(av, b[c], acc[r][c]);
                }
            }
        }
        __syncthreads();
    }
#pragma unroll
    for (int r = 0; r < 4; r++) {
        int gi = i0 + ty * 4 + r;
#pragma unroll
        for (int c = 0; c < 8; c += 4) {
            float4 v = make_float4(acc[r][c], acc[r][c + 1], acc[r][c + 2], acc[r][c + 3]);
            *(float4*)(g_attnout + (size_t)gi * HID_ + h * D_ + tx * 8 + c) = v;
        }
    }
}

// ---------------- host launcher ----------------
extern "C" void kernel_launch(void* const* d_in, const int* in_sizes, int n_in,
                              void* d_out, int out_size) {
    const float* hidden = (const float*)d_in[0];
    const float* Wq = (const float*)d_in[1];
    const float* Wk = (const float*)d_in[2];
    const float* Wv = (const float*)d_in[3];
    const float* Wo = (const float*)d_in[4];
    float* out = (float*)d_out;

    float *q, *k, *v, *ao, *m1, *il1, *m2, *il2;
    cudaGetSymbolAddress((void**)&q,  g_q);
    cudaGetSymbolAddress((void**)&k,  g_k);
    cudaGetSymbolAddress((void**)&v,  g_v);
    cudaGetSymbolAddress((void**)&ao, g_attnout);
    cudaGetSymbolAddress((void**)&m1, g_m1);
    cudaGetSymbolAddress((void**)&il1, g_invl1);
    cudaGetSymbolAddress((void**)&m2, g_m2);
    cudaGetSymbolAddress((void**)&il2, g_invl2);

    // QKV projections
    sgemm128<<<dim3(HID_ / 128, S_ / 128), 256>>>(hidden, Wq, q, S_, HID_, HID_);
    sgemm128<<<dim3((NKV_ * D_) / 128, S_ / 128), 256>>>(hidden, Wk, k, S_, NKV_ * D_, HID_);
    sgemm128<<<dim3((NKV_ * D_) / 128, S_ / 128), 256>>>(hidden, Wv, v, S_, NKV_ * D_, HID_);

    // RoPE on Q and K
    rope_kernel<<<(S_ * NH_ * 64 + 255) / 256, 256>>>(q, NH_);
    rope_kernel<<<(S_ * NKV_ * 64 + 255) / 256, 256>>>(k, NKV_);

    // scores with causal mask
    scores_kernel<<<dim3(S_ / 128, S_ / 128, NH_), 256>>>();

    // pass-1 softmax stats + column sums + top-k heavy set
    rowstats_kernel<<<dim3(S_, NH_), 256>>>(m1, il1, 0);
    colsum_kernel<<<dim3(S_ / 256, NH_), 256>>>();
    topk_kernel<<<NH_, 256>>>();

    // pass-2 masked softmax stats + PV
    rowstats_kernel<<<dim3(S_, NH_), 256>>>(m2, il2, 1);
    pv_kernel<<<dim3(S_ / 64, NH_), 256>>>();

    // output projection
    sgemm128<<<dim3(HID_ / 128, S_ / 128), 256>>>(ao, Wo, out, S_, HID_, HID_);
}

// round 3
// speedup vs baseline: 1.7412x; 1.7412x over previous
#include <cuda_runtime.h>
#include <cuda_bf16.h>
#include <math.h>
#include <stdint.h>

#define S_    2048
#define HID_  2048
#define NH_   16
#define NKV_  4
#define D_    128
#define HB_   204
#define RB_   204
#define NEG_  (-3.4028234663852886e38f)
#define SCALE_ 0.08838834764831845f

// ----------------------------- scratch ---------------------------------
__device__ float g_q[S_ * HID_];
__device__ float g_k[S_ * NKV_ * D_];
__device__ float g_v[S_ * NKV_ * D_];
__device__ float g_scores[(size_t)NH_ * S_ * S_];
__device__ float g_m1[NH_ * S_], g_invl1[NH_ * S_];
__device__ float g_m2[NH_ * S_], g_invl2[NH_ * S_];
__device__ float g_colsum[NH_ * S_];
__device__ int   g_heavy[NH_ * S_];
__device__ float g_attnout[S_ * HID_];

__device__ __nv_bfloat16 g_xhat[(size_t)S_ * 3 * HID_];          // A-pattern [hi|lo|hi]
__device__ __nv_bfloat16 g_wqt[(size_t)HID_ * 3 * HID_];         // B-pattern [hi|hi|lo] (W^T)
__device__ __nv_bfloat16 g_wkt[(size_t)(NKV_*D_) * 3 * HID_];
__device__ __nv_bfloat16 g_wvt[(size_t)(NKV_*D_) * 3 * HID_];
__device__ __nv_bfloat16 g_wot[(size_t)HID_ * 3 * HID_];
__device__ __nv_bfloat16 g_qhat[(size_t)NH_ * S_ * 3 * D_];      // A-pattern
__device__ __nv_bfloat16 g_khat[(size_t)NKV_ * S_ * 3 * D_];     // B-pattern
__device__ __nv_bfloat16 g_vthat[(size_t)NKV_ * D_ * 3 * S_];    // B-pattern (V^T)
__device__ __nv_bfloat16 g_aohat[(size_t)S_ * 3 * HID_];         // A-pattern
__device__ __nv_bfloat16 g_phat[(size_t)NH_ * S_ * 3 * S_];      // A-pattern

// ----------------------------- PTX helpers ------------------------------
__device__ __forceinline__ uint32_t smem_u32(const void* p) {
    uint32_t a;
    asm("{ .reg .u64 t; cvta.to.shared.u64 t, %1; cvt.u32.u64 %0, t; }" : "=r"(a) : "l"(p));
    return a;
}
__device__ __forceinline__ void cp16(uint32_t saddr, const void* gptr) {
    asm volatile("cp.async.cg.shared.global [%0], [%1], 16;" :: "r"(saddr), "l"(gptr));
}
__device__ __forceinline__ void cp_commit() { asm volatile("cp.async.commit_group;"); }
__device__ __forceinline__ void cp_wait0() { asm volatile("cp.async.wait_group 0;" ::: "memory"); }
__device__ __forceinline__ void cp_wait1() { asm volatile("cp.async.wait_group 1;" ::: "memory"); }

__device__ __forceinline__ void ldsm4(uint32_t& r0, uint32_t& r1, uint32_t& r2, uint32_t& r3,
                                      uint32_t addr) {
    asm volatile("ldmatrix.sync.aligned.m8n8.x4.shared.b16 {%0,%1,%2,%3}, [%4];"
                 : "=r"(r0), "=r"(r1), "=r"(r2), "=r"(r3) : "r"(addr));
}
__device__ __forceinline__ void mma16816(float* d, const uint32_t* a, const uint32_t* b) {
    asm volatile(
        "mma.sync.aligned.m16n8k16.row.col.f32.bf16.bf16.f32 "
        "{%0,%1,%2,%3}, {%4,%5,%6,%7}, {%8,%9}, {%0,%1,%2,%3};"
        : "+f"(d[0]), "+f"(d[1]), "+f"(d[2]), "+f"(d[3])
        : "r"(a[0]), "r"(a[1]), "r"(a[2]), "r"(a[3]), "r"(b[0]), "r"(b[1]));
}

// ------------------------- HMMA GEMM -------------------------
// C[z][128,128] tile = A[z][M,Kp] * Bt[z>>bShift][N,Kp]^T, fp32 out.
// mode 0: plain store. mode 1: scores (scale + causal NEG).
__device__ __forceinline__ void load_tile_async(uint32_t sbase, const __nv_bfloat16* src,
                                                int ld, int row0, int kbase, int tid) {
#pragma unroll
    for (int t = 0; t < 4; t++) {
        int u = tid + t * 256;
        int row = u >> 3, seg = u & 7;
        uint32_t bo = (uint32_t)(row * 128 + seg * 16);
        bo ^= (bo >> 3) & 0x70;
        cp16(sbase + bo, src + (size_t)(row0 + row) * ld + kbase + seg * 8);
    }
}

__global__ __launch_bounds__(256) void mma_gemm(
    const __nv_bfloat16* __restrict__ A, size_t aStrideZ,
    const __nv_bfloat16* __restrict__ Bt, size_t bStrideZ, int bShift,
    float* __restrict__ C, size_t cStrideZ, int ldc,
    int Kp, int mode) {
    int z = blockIdx.z;
    int i0 = blockIdx.y * 128, j0 = blockIdx.x * 128;
    const __nv_bfloat16* Az = A + (size_t)z * aStrideZ;
    const __nv_bfloat16* Bz = Bt + (size_t)(z >> bShift) * bStrideZ;
    float* Cz = C + (size_t)z * cStrideZ;
    int tid = threadIdx.x, wid = tid >> 5;
    uint32_t lane = tid & 31;

    if (mode == 1 && j0 > i0 + 127) {   // fully above diagonal: NEG fill, no MMA
        float4 n4 = make_float4(NEG_, NEG_, NEG_, NEG_);
        for (int u = tid; u < 128 * 32; u += 256) {
            int r = u >> 5, cq = u & 31;
            *(float4*)(Cz + (size_t)(i0 + r) * ldc + j0 + cq * 4) = n4;
        }
        return;
    }

    extern __shared__ char dsm[];
    char* tile = (char*)(((uintptr_t)dsm + 1023) & ~(uintptr_t)1023);
    uint32_t sA[2] = { smem_u32(tile), smem_u32(tile) + 16384 };
    uint32_t sB[2] = { smem_u32(tile) + 32768, smem_u32(tile) + 49152 };

    int warp_m = wid >> 2;   // 0..1 -> m offset 64*warp_m
    int warp_n = wid & 3;    // 0..3 -> n offset 32*warp_n

    float acc[4][4][4];
#pragma unroll
    for (int i = 0; i < 4; i++)
#pragma unroll
        for (int j = 0; j < 4; j++)
#pragma unroll
            for (int r = 0; r < 4; r++) acc[i][j][r] = 0.f;

    load_tile_async(sA[0], Az, Kp, i0, 0, tid);
    load_tile_async(sB[0], Bz, Kp, j0, 0, tid);
    cp_commit();

    const int NC = Kp >> 6;
    for (int c = 0; c < NC; c++) {
        if (c + 1 < NC) {
            load_tile_async(sA[(c + 1) & 1], Az, Kp, i0, (c + 1) * 64, tid);
            load_tile_async(sB[(c + 1) & 1], Bz, Kp, j0, (c + 1) * 64, tid);
            cp_commit();
            cp_wait1();
        } else {
            cp_wait0();
        }
        __syncthreads();

        uint32_t a_base = sA[c & 1], b_base = sB[c & 1];
#pragma unroll
        for (int ks = 0; ks < 4; ks++) {
            uint32_t a[4][4], b[2][4];
#pragma unroll
            for (int mf = 0; mf < 4; mf++) {
                int row = 64 * warp_m + 16 * mf + (lane & 7) + (((lane >> 3) & 1) << 3);
                int colb = (16 * ks + (((lane >> 4) & 1) << 3)) * 2;
                uint32_t off = (uint32_t)(row * 128 + colb);
                off ^= (off >> 3) & 0x70;
                ldsm4(a[mf][0], a[mf][1], a[mf][2], a[mf][3], a_base + off);
            }
#pragma unroll
            for (int nf2 = 0; nf2 < 2; nf2++) {
                int row = 32 * warp_n + 16 * nf2 + (lane & 7) + (((lane >> 4) & 1) << 3);
                int colb = (16 * ks + (((lane >> 3) & 1) << 3)) * 2;
                uint32_t off = (uint32_t)(row * 128 + colb);
                off ^= (off >> 3) & 0x70;
                ldsm4(b[nf2][0], b[nf2][1], b[nf2][2], b[nf2][3], b_base + off);
            }
#pragma unroll
            for (int mf = 0; mf < 4; mf++)
#pragma unroll
                for (int nf = 0; nf < 4; nf++)
                    mma16816(acc[mf][nf], a[mf], &b[nf >> 1][(nf & 1) * 2]);
        }
        __syncthreads();
    }

    // epilogue: direct stores (float2), per-element causal for mode 1
#pragma unroll
    for (int mf = 0; mf < 4; mf++) {
        int r0 = i0 + 64 * warp_m + 16 * mf + (int)(lane >> 2);
#pragma unroll
        for (int nf = 0; nf < 4; nf++) {
            int c0 = j0 + 32 * warp_n + 8 * nf + (int)(lane & 3) * 2;
            float d0 = acc[mf][nf][0], d1 = acc[mf][nf][1];
            float d2 = acc[mf][nf][2], d3 = acc[mf][nf][3];
            if (mode == 1) {
                d0 = (c0     <= r0)     ? d0 * SCALE_ : NEG_;
                d1 = (c0 + 1 <= r0)     ? d1 * SCALE_ : NEG_;
                d2 = (c0     <= r0 + 8) ? d2 * SCALE_ : NEG_;
                d3 = (c0 + 1 <= r0 + 8) ? d3 * SCALE_ : NEG_;
            }
            *(float2*)(Cz + (size_t)r0 * ldc + c0) = make_float2(d0, d1);
            *(float2*)(Cz + (size_t)(r0 + 8) * ldc + c0) = make_float2(d2, d3);
        }
    }
}

// ----------------------- split-bf16 conversion kernels -------------------
__global__ void split_plain(const float* __restrict__ A, __nv_bfloat16* __restrict__ out,
                            int M, int K) {  // pattern A
    int idx = blockIdx.x * blockDim.x + threadIdx.x;
    if (idx >= M * K) return;
    int m = idx / K, k = idx - m * K;
    float x = A[idx];
    __nv_bfloat16 hi = __float2bfloat16(x);
    __nv_bfloat16 lo = __float2bfloat16(x - __bfloat162float(hi));
    size_t base = (size_t)m * 3 * K;
    out[base + k] = hi; out[base + K + k] = lo; out[base + 2 * K + k] = hi;
}

__global__ void split_heads(const float* __restrict__ src, __nv_bfloat16* __restrict__ out,
                            int nh, int patternB) {
    int idx = blockIdx.x * blockDim.x + threadIdx.x;
    if (idx >= S_ * nh * D_) return;
    int d = idx & 127;
    int h = (idx >> 7) % nh;
    int s = idx / (nh * D_);
    float x = src[(size_t)s * nh * D_ + h * D_ + d];
    __nv_bfloat16 hi = __float2bfloat16(x);
    __nv_bfloat16 lo = __float2bfloat16(x - __bfloat162float(hi));
    size_t base = ((size_t)h * S_ + s) * (3 * D_);
    if (patternB) { out[base + d] = hi; out[base + D_ + d] = hi; out[base + 2 * D_ + d] = lo; }
    else          { out[base + d] = hi; out[base + D_ + d] = lo; out[base + 2 * D_ + d] = hi; }
}

__global__ void transpose_split(const float* __restrict__ src, int ldsrc, int K, int Nper,
                                __nv_bfloat16* __restrict__ out) {  // pattern B
    int z = blockIdx.z;
    const float* s = src + (size_t)z * Nper;
    __nv_bfloat16* o = out + (size_t)z * Nper * 3 * K;
    __shared__ float t[32][33];
    int k0 = blockIdx.y * 32, n0 = blockIdx.x * 32;
    int tx = threadIdx.x, ty = threadIdx.y;   // (32, 8)
#pragma unroll
    for (int r = 0; r < 4; r++) {
        int k = k0 + ty + 8 * r;
        t[ty + 8 * r][tx] = s[(size_t)k * ldsrc + n0 + tx];
    }
    __syncthreads();
#pragma unroll
    for (int r = 0; r < 4; r++) {
        int n = n0 + ty + 8 * r, k = k0 + tx;
        float x = t[tx][ty + 8 * r];
        __nv_bfloat16 hi = __float2bfloat16(x);
        __nv_bfloat16 lo = __float2bfloat16(x - __bfloat162float(hi));
        size_t base = (size_t)n * 3 * K;
        o[base + k] = hi; o[base + K + k] = hi; o[base + 2 * K + k] = lo;
    }
}

// --------------------------------- RoPE ---------------------------------
__global__ void rope_kernel(float* x, int nh) {
    int idx = blockIdx.x * blockDim.x + threadIdx.x;
    if (idx >= S_ * nh * 64) return;
    int d = idx & 63;
    int rest = idx >> 6;
    int h = rest % nh;
    int s = rest / nh;
    float* base = x + (size_t)s * nh * 128 + h * 128;
    float x1 = base[d], x2 = base[d + 64];
    float inv = powf(10000.f, -(float)d * (1.f / 64.f));
    float ang = (float)s * inv;
    float c, sn;
    sincosf(ang, &sn, &c);
    base[d] = x1 * c - x2 * sn;
    base[d + 64] = x2 * c + x1 * sn;
}

// ----------------------------- softmax stats -----------------------------
__global__ __launch_bounds__(256) void rowstats_kernel(float* __restrict__ m_out,
                                                       float* __restrict__ invl_out,
                                                       int masked) {
    int i = blockIdx.x, h = blockIdx.y;
    const float* row = g_scores + (size_t)(h * S_ + i) * S_;
    int tid = threadIdx.x;
    __shared__ float red[256];
    int bound = i + 1;

    float mloc = -INFINITY;
    for (int j = tid; j < bound; j += 256) {
        float s = row[j];
        if (masked) {
            bool keep = (i - j <= RB_) || g_heavy[h * S_ + j];
            if (!keep) s = NEG_;
        }
        mloc = fmaxf(mloc, s);
    }
    red[tid] = mloc; __syncthreads();
    for (int off = 128; off > 0; off >>= 1) {
        if (tid < off) red[tid] = fmaxf(red[tid], red[tid + off]);
        __syncthreads();
    }
    float m = red[0];
    __syncthreads();

    float lloc = 0.f;
    for (int j = tid; j < bound; j += 256) {
        float s = row[j];
        if (masked) {
            bool keep = (i - j <= RB_) || g_heavy[h * S_ + j];
            if (!keep) s = NEG_;
        }
        lloc += expf(s - m);
    }
    red[tid] = lloc; __syncthreads();
    for (int off = 128; off > 0; off >>= 1) {
        if (tid < off) red[tid] += red[tid + off];
        __syncthreads();
    }
    if (tid == 0) {
        m_out[h * S_ + i] = m;
        invl_out[h * S_ + i] = 1.f / red[0];
    }
}

__global__ __launch_bounds__(256) void colsum_kernel() {
    int h = blockIdx.y;
    int j0 = blockIdx.x * 256;
    int j = j0 + threadIdx.x;
    const float* base = g_scores + (size_t)h * S_ * S_;
    float acc = 0.f;
    for (int i = j0; i < S_; i++) {
        float s = base[(size_t)i * S_ + j];
        acc += expf(s - g_m1[h * S_ + i]) * g_invl1[h * S_ + i];
    }
    g_colsum[h * S_ + j] = acc;
}

__global__ __launch_bounds__(256) void topk_kernel() {
    int h = blockIdx.x;
    int tid = threadIdx.x;
    __shared__ float vals[S_];
    __shared__ float bv[256];
    __shared__ int bi[256];
    for (int j = tid; j < S_; j += 256) {
        vals[j] = g_colsum[h * S_ + j];
        g_heavy[h * S_ + j] = 0;
    }
    __syncthreads();
    for (int it = 0; it < HB_; it++) {
        float best = -INFINITY; int besti = 1 << 30;
        for (int j = tid; j < S_; j += 256) {
            float v = vals[j];
            if (v > best || (v == best && j < besti)) { best = v; besti = j; }
        }
        bv[tid] = best; bi[tid] = besti; __syncthreads();
        for (int off = 128; off > 0; off >>= 1) {
            if (tid < off) {
                if (bv[tid + off] > bv[tid] ||
                    (bv[tid + off] == bv[tid] && bi[tid + off] < bi[tid])) {
                    bv[tid] = bv[tid + off]; bi[tid] = bi[tid + off];
                }
            }
            __syncthreads();
        }
        if (tid == 0) { g_heavy[h * S_ + bi[0]] = 1; vals[bi[0]] = -INFINITY; }
        __syncthreads();
    }
}

// --------- P-hat: masked softmax probs, split bf16 (pattern A) -----------
__global__ __launch_bounds__(256) void phat_kernel() {
    size_t idx = (size_t)blockIdx.x * 256 + threadIdx.x;
    int h = (int)(idx >> 22);
    int i = (int)((idx >> 11) & 2047);
    int j = (int)(idx & 2047);
    float s = g_scores[idx];
    int dd = i - j; if (dd < 0) dd = -dd;
    bool keep = (dd <= RB_) || g_heavy[h * S_ + j];
    float p = 0.f;
    if (keep) p = expf(s - g_m2[h * S_ + i]) * g_invl2[h * S_ + i];
    __nv_bfloat16 hi = __float2bfloat16(p);
    __nv_bfloat16 lo = __float2bfloat16(p - __bfloat162float(hi));
    size_t base = ((size_t)h * S_ + i) * (3 * S_);
    g_phat[base + j] = hi;
    g_phat[base + S_ + j] = lo;
    g_phat[base + 2 * S_ + j] = hi;
}

// ------------------------------ launcher ---------------------------------
extern "C" void kernel_launch(void* const* d_in, const int* in_sizes, int n_in,
                              void* d_out, int out_size) {
    const float* hidden = (const float*)d_in[0];
    const float* Wq = (const float*)d_in[1];
    const float* Wk = (const float*)d_in[2];
    const float* Wv = (const float*)d_in[3];
    const float* Wo = (const float*)d_in[4];
    float* out = (float*)d_out;

    float *q, *k, *v, *ao, *m1, *il1, *m2, *il2, *scores;
    __nv_bfloat16 *xhat, *wqt, *wkt, *wvt, *wot, *qhat, *khat, *vthat, *aohat, *phat;
    cudaGetSymbolAddress((void**)&q, g_q);
    cudaGetSymbolAddress((void**)&k, g_k);
    cudaGetSymbolAddress((void**)&v, g_v);
    cudaGetSymbolAddress((void**)&ao, g_attnout);
    cudaGetSymbolAddress((void**)&m1, g_m1);
    cudaGetSymbolAddress((void**)&il1, g_invl1);
    cudaGetSymbolAddress((void**)&m2, g_m2);
    cudaGetSymbolAddress((void**)&il2, g_invl2);
    cudaGetSymbolAddress((void**)&xhat, g_xhat);
    cudaGetSymbolAddress((void**)&wqt, g_wqt);
    cudaGetSymbolAddress((void**)&wkt, g_wkt);
    cudaGetSymbolAddress((void**)&wvt, g_wvt);
    cudaGetSymbolAddress((void**)&wot, g_wot);
    cudaGetSymbolAddress((void**)&qhat, g_qhat);
    cudaGetSymbolAddress((void**)&khat, g_khat);
    cudaGetSymbolAddress((void**)&vthat, g_vthat);
    cudaGetSymbolAddress((void**)&aohat, g_aohat);
    cudaGetSymbolAddress((void**)&phat, g_phat);
    cudaGetSymbolAddress((void**)&scores, g_scores);

    const int SMEM_DYN = 66560;
    cudaFuncSetAttribute(mma_gemm, cudaFuncAttributeMaxDynamicSharedMemorySize, SMEM_DYN);

    // 1. split inputs / weights to bf16 hi-lo
    split_plain<<<(S_ * HID_ + 255) / 256, 256>>>(hidden, xhat, S_, HID_);
    transpose_split<<<dim3(HID_ / 32, HID_ / 32, 1), dim3(32, 8)>>>(Wq, HID_, HID_, HID_, wqt);
    transpose_split<<<dim3((NKV_ * D_) / 32, HID_ / 32, 1), dim3(32, 8)>>>(Wk, NKV_ * D_, HID_, NKV_ * D_, wkt);
    transpose_split<<<dim3((NKV_ * D_) / 32, HID_ / 32, 1), dim3(32, 8)>>>(Wv, NKV_ * D_, HID_, NKV_ * D_, wvt);
    transpose_split<<<dim3(HID_ / 32, HID_ / 32, 1), dim3(32, 8)>>>(Wo, HID_, HID_, HID_, wot);

    // 2. QKV projections (tensor core)
    mma_gemm<<<dim3(HID_ / 128, S_ / 128, 1), 256, SMEM_DYN>>>(xhat, 0, wqt, 0, 0, q, 0, HID_, 3 * HID_, 0);
    mma_gemm<<<dim3((NKV_ * D_) / 128, S_ / 128, 1), 256, SMEM_DYN>>>(xhat, 0, wkt, 0, 0, k, 0, NKV_ * D_, 3 * HID_, 0);
    mma_gemm<<<dim3((NKV_ * D_) / 128, S_ / 128, 1), 256, SMEM_DYN>>>(xhat, 0, wvt, 0, 0, v, 0, NKV_ * D_, 3 * HID_, 0);

    // 3. RoPE
    rope_kernel<<<(S_ * NH_ * 64 + 255) / 256, 256>>>(q, NH_);
    rope_kernel<<<(S_ * NKV_ * 64 + 255) / 256, 256>>>(k, NKV_);

    // 4. split roped Q/K, transpose-split V
    split_heads<<<(S_ * NH_ * D_ + 255) / 256, 256>>>(q, qhat, NH_, 0);
    split_heads<<<(S_ * NKV_ * D_ + 255) / 256, 256>>>(k, khat, NKV_, 1);
    transpose_split<<<dim3(D_ / 32, S_ / 32, NKV_), dim3(32, 8)>>>(v, NKV_ * D_, S_, D_, vthat);

    // 5. scores = QK^T (tensor core, causal mask in epilogue)
    mma_gemm<<<dim3(S_ / 128, S_ / 128, NH_), 256, SMEM_DYN>>>(
        qhat, (size_t)S_ * 3 * D_, khat, (size_t)S_ * 3 * D_, 2,
        scores, (size_t)S_ * S_, S_, 3 * D_, 1);

    // 6. H2O: pass-1 stats, colsum, topk
    rowstats_kernel<<<dim3(S_, NH_), 256>>>(m1, il1, 0);
    colsum_kernel<<<dim3(S_ / 256, NH_), 256>>>();
    topk_kernel<<<NH_, 256>>>();

    // 7. pass-2 masked stats + P-hat
    rowstats_kernel<<<dim3(S_, NH_), 256>>>(m2, il2, 1);
    phat_kernel<<<(int)(((size_t)NH_ * S_ * S_) / 256), 256>>>();

    // 8. PV (tensor core)
    mma_gemm<<<dim3(1, S_ / 128, NH_), 256, SMEM_DYN>>>(
        phat, (size_t)S_ * 3 * S_, vthat, (size_t)D_ * 3 * S_, 2,
        ao, (size_t)D_, HID_, 3 * S_, 0);

    // 9. output projection (tensor core)
    split_plain<<<(S_ * HID_ + 255) / 256, 256>>>(ao, aohat, S_, HID_);
    mma_gemm<<<dim3(HID_ / 128, S_ / 128, 1), 256, SMEM_DYN>>>(aohat, 0, wot, 0, 0, out, 0, HID_, 3 * HID_, 0);
}

// round 6
// speedup vs baseline: 2.1471x; 1.2331x over previous
#include <cuda_runtime.h>
#include <cuda_bf16.h>
#include <math.h>
#include <stdint.h>

#define S_    2048
#define HID_  2048
#define NH_   16
#define NKV_  4
#define D_    128
#define HB_   204
#define RB_   204
#define NEG_  (-3.4028234663852886e38f)
#define SCALE_ 0.08838834764831845f
#define L2E_  1.4426950408889634f

// ----------------------------- scratch ---------------------------------
__device__ float g_q[S_ * HID_];
__device__ float g_k[S_ * NKV_ * D_];
__device__ float g_v[S_ * NKV_ * D_];
__device__ float g_scores[(size_t)NH_ * S_ * S_];   // lower triangle only
__device__ float g_e[(size_t)NH_ * S_ * S_];        // exp buffer (pass1 then pass2)
__device__ float g_invl1[NH_ * S_], g_invl2[NH_ * S_];
__device__ float g_colsum[NH_ * S_];
__device__ int   g_heavylist[NH_ * HB_];

__device__ __nv_bfloat16 g_xhat[(size_t)S_ * 3 * HID_];          // A-pattern [hi|lo|hi]
__device__ __nv_bfloat16 g_wqt[(size_t)HID_ * 3 * HID_];         // B-pattern [hi|hi|lo]
__device__ __nv_bfloat16 g_wkt[(size_t)(NKV_*D_) * 3 * HID_];
__device__ __nv_bfloat16 g_wvt[(size_t)(NKV_*D_) * 3 * HID_];
__device__ __nv_bfloat16 g_wot[(size_t)HID_ * 3 * HID_];
__device__ __nv_bfloat16 g_qhat[(size_t)NH_ * S_ * 3 * D_];      // A-pattern
__device__ __nv_bfloat16 g_khat[(size_t)NKV_ * S_ * 3 * D_];     // B-pattern
__device__ __nv_bfloat16 g_vthat[(size_t)NKV_ * D_ * 3 * S_];    // B-pattern (V^T)
__device__ __nv_bfloat16 g_aohat[(size_t)S_ * 3 * HID_];         // A-pattern

// ----------------------------- PTX helpers ------------------------------
__device__ __forceinline__ uint32_t smem_u32(const void* p) {
    uint32_t a;
    asm("{ .reg .u64 t; cvta.to.shared.u64 t, %1; cvt.u32.u64 %0, t; }" : "=r"(a) : "l"(p));
    return a;
}
__device__ __forceinline__ void cp16(uint32_t saddr, const void* gptr) {
    asm volatile("cp.async.cg.shared.global [%0], [%1], 16;" :: "r"(saddr), "l"(gptr));
}
__device__ __forceinline__ void cp_commit() { asm volatile("cp.async.commit_group;"); }
__device__ __forceinline__ void cp_wait0() { asm volatile("cp.async.wait_group 0;" ::: "memory"); }
__device__ __forceinline__ void cp_wait1() { asm volatile("cp.async.wait_group 1;" ::: "memory"); }

__device__ __forceinline__ void ldsm4(uint32_t& r0, uint32_t& r1, uint32_t& r2, uint32_t& r3,
                                      uint32_t addr) {
    asm volatile("ldmatrix.sync.aligned.m8n8.x4.shared.b16 {%0,%1,%2,%3}, [%4];"
                 : "=r"(r0), "=r"(r1), "=r"(r2), "=r"(r3) : "r"(addr));
}
__device__ __forceinline__ void mma16816(float* d, const uint32_t* a, const uint32_t* b) {
    asm volatile(
        "mma.sync.aligned.m16n8k16.row.col.f32.bf16.bf16.f32 "
        "{%0,%1,%2,%3}, {%4,%5,%6,%7}, {%8,%9}, {%0,%1,%2,%3};"
        : "+f"(d[0]), "+f"(d[1]), "+f"(d[2]), "+f"(d[3])
        : "r"(a[0]), "r"(a[1]), "r"(a[2]), "r"(a[3]), "r"(b[0]), "r"(b[1]));
}
__device__ __forceinline__ float fexp(float x) {
    float y;
    asm("ex2.approx.ftz.f32 %0, %1;" : "=f"(y) : "f"(x * L2E_));
    return y;
}
__device__ __forceinline__ uint32_t split_pack(float p0, float p1, uint32_t& lo) {
    __nv_bfloat16 h0 = __float2bfloat16(p0), h1 = __float2bfloat16(p1);
    float f0 = __bfloat162float(h0), f1 = __bfloat162float(h1);
    __nv_bfloat16 l0 = __float2bfloat16(p0 - f0), l1 = __float2bfloat16(p1 - f1);
    lo = (uint32_t)__bfloat16_as_ushort(l0) | ((uint32_t)__bfloat16_as_ushort(l1) << 16);
    return (uint32_t)__bfloat16_as_ushort(h0) | ((uint32_t)__bfloat16_as_ushort(h1) << 16);
}

// ------------------------- HMMA GEMM -------------------------
__device__ __forceinline__ void load_tile_async(uint32_t sbase, const __nv_bfloat16* src,
                                                int ld, int row0, int kbase, int tid) {
#pragma unroll
    for (int t = 0; t < 4; t++) {
        int u = tid + t * 256;
        int row = u >> 3, seg = u & 7;
        uint32_t bo = (uint32_t)(row * 128 + seg * 16);
        bo ^= (bo >> 3) & 0x70;
        cp16(sbase + bo, src + (size_t)(row0 + row) * ld + kbase + seg * 8);
    }
}

__global__ __launch_bounds__(256) void mma_gemm(
    const __nv_bfloat16* __restrict__ A, size_t aStrideZ,
    const __nv_bfloat16* __restrict__ Bt, size_t bStrideZ, int bShift,
    float* __restrict__ C, size_t cStrideZ, int ldc,
    int Kp, int mode) {
    int z = blockIdx.z;
    int i0 = blockIdx.y * 128, j0 = blockIdx.x * 128;
    if (mode == 1 && j0 > i0 + 127) return;   // upper tiles: nothing (nobody reads them)

    const __nv_bfloat16* Az = A + (size_t)z * aStrideZ;
    const __nv_bfloat16* Bz = Bt + (size_t)(z >> bShift) * bStrideZ;
    float* Cz = C + (size_t)z * cStrideZ;
    int tid = threadIdx.x, wid = tid >> 5;
    uint32_t lane = tid & 31;

    extern __shared__ char dsm[];
    char* tile = (char*)(((uintptr_t)dsm + 1023) & ~(uintptr_t)1023);
    uint32_t sA[2] = { smem_u32(tile), smem_u32(tile) + 16384 };
    uint32_t sB[2] = { smem_u32(tile) + 32768, smem_u32(tile) + 49152 };

    int warp_m = wid >> 2;
    int warp_n = wid & 3;

    float acc[4][4][4];
#pragma unroll
    for (int i = 0; i < 4; i++)
#pragma unroll
        for (int j = 0; j < 4; j++)
#pragma unroll
            for (int r = 0; r < 4; r++) acc[i][j][r] = 0.f;

    load_tile_async(sA[0], Az, Kp, i0, 0, tid);
    load_tile_async(sB[0], Bz, Kp, j0, 0, tid);
    cp_commit();

    const int NC = Kp >> 6;
    for (int c = 0; c < NC; c++) {
        if (c + 1 < NC) {
            load_tile_async(sA[(c + 1) & 1], Az, Kp, i0, (c + 1) * 64, tid);
            load_tile_async(sB[(c + 1) & 1], Bz, Kp, j0, (c + 1) * 64, tid);
            cp_commit();
            cp_wait1();
        } else {
            cp_wait0();
        }
        __syncthreads();

        uint32_t a_base = sA[c & 1], b_base = sB[c & 1];
#pragma unroll
        for (int ks = 0; ks < 4; ks++) {
            uint32_t a[4][4], b[2][4];
#pragma unroll
            for (int mf = 0; mf < 4; mf++) {
                int row = 64 * warp_m + 16 * mf + (lane & 7) + (((lane >> 3) & 1) << 3);
                int colb = (16 * ks + (((lane >> 4) & 1) << 3)) * 2;
                uint32_t off = (uint32_t)(row * 128 + colb);
                off ^= (off >> 3) & 0x70;
                ldsm4(a[mf][0], a[mf][1], a[mf][2], a[mf][3], a_base + off);
            }
#pragma unroll
            for (int nf2 = 0; nf2 < 2; nf2++) {
                int row = 32 * warp_n + 16 * nf2 + (lane & 7) + (((lane >> 4) & 1) << 3);
                int colb = (16 * ks + (((lane >> 3) & 1) << 3)) * 2;
                uint32_t off = (uint32_t)(row * 128 + colb);
                off ^= (off >> 3) & 0x70;
                ldsm4(b[nf2][0], b[nf2][1], b[nf2][2], b[nf2][3], b_base + off);
            }
#pragma unroll
            for (int mf = 0; mf < 4; mf++)
#pragma unroll
                for (int nf = 0; nf < 4; nf++)
                    mma16816(acc[mf][nf], a[mf], &b[nf >> 1][(nf & 1) * 2]);
        }
        __syncthreads();
    }

#pragma unroll
    for (int mf = 0; mf < 4; mf++) {
        int r0 = i0 + 64 * warp_m + 16 * mf + (int)(lane >> 2);
#pragma unroll
        for (int nf = 0; nf < 4; nf++) {
            int c0 = j0 + 32 * warp_n + 8 * nf + (int)(lane & 3) * 2;
            float d0 = acc[mf][nf][0], d1 = acc[mf][nf][1];
            float d2 = acc[mf][nf][2], d3 = acc[mf][nf][3];
            if (mode == 1) {
                d0 = (c0     <= r0)     ? d0 * SCALE_ : NEG_;
                d1 = (c0 + 1 <= r0)     ? d1 * SCALE_ : NEG_;
                d2 = (c0     <= r0 + 8) ? d2 * SCALE_ : NEG_;
                d3 = (c0 + 1 <= r0 + 8) ? d3 * SCALE_ : NEG_;
            }
            *(float2*)(Cz + (size_t)r0 * ldc + c0) = make_float2(d0, d1);
            *(float2*)(Cz + (size_t)(r0 + 8) * ldc + c0) = make_float2(d2, d3);
        }
    }
}

// ------------------------ fused PV (P on the fly) ------------------------
__global__ __launch_bounds__(256) void pv_mma(
    const __nv_bfloat16* __restrict__ vthat,
    const float* __restrict__ e2, const float* __restrict__ invl2,
    __nv_bfloat16* __restrict__ aohat) {
    int i0 = blockIdx.x * 128, h = blockIdx.y, kh = h >> 2;
    int tid = threadIdx.x, wid = tid >> 5;
    uint32_t lane = tid & 31;
    int warp_m = wid >> 2, warp_n = wid & 3;

    extern __shared__ char dsm[];
    char* tile = (char*)(((uintptr_t)dsm + 1023) & ~(uintptr_t)1023);
    char* pPhi = tile;
    char* pPlo = tile + 16384;
    uint32_t sPhi = smem_u32(pPhi), sPlo = smem_u32(pPlo);
    uint32_t sVh[2] = { smem_u32(tile) + 32768, smem_u32(tile) + 49152 };
    uint32_t sVl[2] = { smem_u32(tile) + 65536, smem_u32(tile) + 81920 };

    int r = tid >> 1, half = tid & 1;
    int gi = i0 + r;
    float il = invl2[h * S_ + gi];
    const float* erow = e2 + ((size_t)h * S_ + gi) * S_ + half * 32;
    const __nv_bfloat16* Vz = vthat + (size_t)kh * D_ * 3 * S_;

    float acc[4][4][4];
#pragma unroll
    for (int i = 0; i < 4; i++)
#pragma unroll
        for (int j = 0; j < 4; j++)
#pragma unroll
            for (int q = 0; q < 4; q++) acc[i][j][q] = 0.f;

    const int NCH = (i0 >> 6) + 2;
    load_tile_async(sVh[0], Vz, 3 * S_, 0, 0, tid);
    load_tile_async(sVl[0], Vz, 3 * S_, 0, 2 * S_ + 0, tid);
    cp_commit();

    for (int c = 0; c < NCH; c++) {
        int j0 = c * 64;
        bool pre = (c + 1 < NCH);
        if (pre) {
            load_tile_async(sVh[(c + 1) & 1], Vz, 3 * S_, 0, (c + 1) * 64, tid);
            load_tile_async(sVl[(c + 1) & 1], Vz, 3 * S_, 0, 2 * S_ + (c + 1) * 64, tid);
            cp_commit();
        }
        // build split P tile (row r, cols half*32..half*32+31 of this 64-chunk)
        uint32_t hib[16], lob[16];
        const float* ep = erow + j0;
#pragma unroll
        for (int q = 0; q < 8; q++) {
            float4 e4 = *(const float4*)(ep + q * 4);
            hib[q * 2]     = split_pack(e4.x * il, e4.y * il, lob[q * 2]);
            hib[q * 2 + 1] = split_pack(e4.z * il, e4.w * il, lob[q * 2 + 1]);
        }
#pragma unroll
        for (int sg = 0; sg < 4; sg++) {
            uint32_t bo = (uint32_t)(r * 128 + half * 64 + sg * 16);
            bo ^= (bo >> 3) & 0x70;
            *(uint4*)(pPhi + bo) = make_uint4(hib[sg * 4], hib[sg * 4 + 1], hib[sg * 4 + 2], hib[sg * 4 + 3]);
            *(uint4*)(pPlo + bo) = make_uint4(lob[sg * 4], lob[sg * 4 + 1], lob[sg * 4 + 2], lob[sg * 4 + 3]);
        }
        if (pre) cp_wait1(); else cp_wait0();
        __syncthreads();

        uint32_t abases[3] = { sPhi, sPlo, sPhi };
        uint32_t bbases[3] = { sVh[c & 1], sVh[c & 1], sVl[c & 1] };
#pragma unroll
        for (int t = 0; t < 3; t++) {
            uint32_t a_base = abases[t], b_base = bbases[t];
#pragma unroll
            for (int ks = 0; ks < 4; ks++) {
                uint32_t a[4][4], b[2][4];
#pragma unroll
                for (int mf = 0; mf < 4; mf++) {
                    int row = 64 * warp_m + 16 * mf + (lane & 7) + (((lane >> 3) & 1) << 3);
                    int colb = (16 * ks + (((lane >> 4) & 1) << 3)) * 2;
                    uint32_t off = (uint32_t)(row * 128 + colb);
                    off ^= (off >> 3) & 0x70;
                    ldsm4(a[mf][0], a[mf][1], a[mf][2], a[mf][3], a_base + off);
                }
#pragma unroll
                for (int nf2 = 0; nf2 < 2; nf2++) {
                    int row = 32 * warp_n + 16 * nf2 + (lane & 7) + (((lane >> 4) & 1) << 3);
                    int colb = (16 * ks + (((lane >> 3) & 1) << 3)) * 2;
                    uint32_t off = (uint32_t)(row * 128 + colb);
                    off ^= (off >> 3) & 0x70;
                    ldsm4(b[nf2][0], b[nf2][1], b[nf2][2], b[nf2][3], b_base + off);
                }
#pragma unroll
                for (int mf = 0; mf < 4; mf++)
#pragma unroll
                    for (int nf = 0; nf < 4; nf++)
                        mma16816(acc[mf][nf], a[mf], &b[nf >> 1][(nf & 1) * 2]);
            }
        }
        __syncthreads();
    }

    // epilogue: write split aohat directly (pattern A: hi | lo | hi)
#pragma unroll
    for (int mf = 0; mf < 4; mf++) {
        int r0 = i0 + 64 * warp_m + 16 * mf + (int)(lane >> 2);
#pragma unroll
        for (int nf = 0; nf < 4; nf++) {
            int c0 = 32 * warp_n + 8 * nf + (int)(lane & 3) * 2;
#pragma unroll
            for (int rr = 0; rr < 2; rr++) {
                float d0 = acc[mf][nf][rr * 2], d1 = acc[mf][nf][rr * 2 + 1];
                uint32_t lo, hi = split_pack(d0, d1, lo);
                size_t b0 = (size_t)(r0 + rr * 8) * (3 * HID_) + h * D_ + c0;
                *(uint32_t*)(aohat + b0) = hi;
                *(uint32_t*)(aohat + b0 + HID_) = lo;
                *(uint32_t*)(aohat + b0 + 2 * HID_) = hi;
            }
        }
    }
}

// ----------------------- split-bf16 conversion kernels -------------------
__global__ void split_plain(const float* __restrict__ A, __nv_bfloat16* __restrict__ out,
                            int M, int K) {  // pattern A
    int idx = blockIdx.x * blockDim.x + threadIdx.x;
    if (idx >= M * K) return;
    int m = idx / K, k = idx - m * K;
    float x = A[idx];
    __nv_bfloat16 hi = __float2bfloat16(x);
    __nv_bfloat16 lo = __float2bfloat16(x - __bfloat162float(hi));
    size_t base = (size_t)m * 3 * K;
    out[base + k] = hi; out[base + K + k] = lo; out[base + 2 * K + k] = hi;
}

__global__ void split_heads(const float* __restrict__ src, __nv_bfloat16* __restrict__ out,
                            int nh, int patternB) {
    int idx = blockIdx.x * blockDim.x + threadIdx.x;
    if (idx >= S_ * nh * D_) return;
    int d = idx & 127;
    int h = (idx >> 7) % nh;
    int s = idx / (nh * D_);
    float x = src[(size_t)s * nh * D_ + h * D_ + d];
    __nv_bfloat16 hi = __float2bfloat16(x);
    __nv_bfloat16 lo = __float2bfloat16(x - __bfloat162float(hi));
    size_t base = ((size_t)h * S_ + s) * (3 * D_);
    if (patternB) { out[base + d] = hi; out[base + D_ + d] = hi; out[base + 2 * D_ + d] = lo; }
    else          { out[base + d] = hi; out[base + D_ + d] = lo; out[base + 2 * D_ + d] = hi; }
}

__global__ void transpose_split(const float* __restrict__ src, int ldsrc, int K, int Nper,
                                __nv_bfloat16* __restrict__ out) {  // pattern B
    int z = blockIdx.z;
    const float* s = src + (size_t)z * Nper;
    __nv_bfloat16* o = out + (size_t)z * Nper * 3 * K;
    __shared__ float t[32][33];
    int k0 = blockIdx.y * 32, n0 = blockIdx.x * 32;
    int tx = threadIdx.x, ty = threadIdx.y;
#pragma unroll
    for (int r = 0; r < 4; r++) {
        int k = k0 + ty + 8 * r;
        t[ty + 8 * r][tx] = s[(size_t)k * ldsrc + n0 + tx];
    }
    __syncthreads();
#pragma unroll
    for (int r = 0; r < 4; r++) {
        int n = n0 + ty + 8 * r, k = k0 + tx;
        float x = t[tx][ty + 8 * r];
        __nv_bfloat16 hi = __float2bfloat16(x);
        __nv_bfloat16 lo = __float2bfloat16(x - __bfloat162float(hi));
        size_t base = (size_t)n * 3 * K;
        o[base + k] = hi; o[base + K + k] = hi; o[base + 2 * K + k] = lo;
    }
}

// --------------------------------- RoPE ---------------------------------
__global__ void rope_kernel(float* x, int nh) {
    int idx = blockIdx.x * blockDim.x + threadIdx.x;
    if (idx >= S_ * nh * 64) return;
    int d = idx & 63;
    int rest = idx >> 6;
    int h = rest % nh;
    int s = rest / nh;
    float* base = x + (size_t)s * nh * 128 + h * 128;
    float x1 = base[d], x2 = base[d + 64];
    float inv = powf(10000.f, -(float)d * (1.f / 64.f));
    float ang = (float)s * inv;
    float c, sn;
    sincosf(ang, &sn, &c);
    base[d] = x1 * c - x2 * sn;
    base[d + 64] = x2 * c + x1 * sn;
}

// ------------------ pass-1: e = exp(s), l-sum (no max needed) ------------
__global__ __launch_bounds__(256) void rowstats1_kernel() {
    int i = blockIdx.x, h = blockIdx.y;
    const float* row = g_scores + (size_t)(h * S_ + i) * S_;
    float* erow = g_e + (size_t)(h * S_ + i) * S_;
    int tid = threadIdx.x;
    __shared__ float red[256];
    float l = 0.f;
    for (int j = tid; j <= i; j += 256) {
        float e = fexp(row[j]);
        erow[j] = e;
        l += e;
    }
    red[tid] = l; __syncthreads();
    for (int off = 128; off > 0; off >>= 1) {
        if (tid < off) red[tid] += red[tid + off];
        __syncthreads();
    }
    if (tid == 0) g_invl1[h * S_ + i] = 1.f / red[0];
}

__global__ __launch_bounds__(256) void colsum_kernel() {
    int h = blockIdx.y;
    int j = blockIdx.x * 256 + threadIdx.x;
    const float* base = g_e + (size_t)h * S_ * S_;
    const float* il = g_invl1 + h * S_;
    float acc = 0.f;
    for (int i = j; i < S_; i++)
        acc += base[(size_t)i * S_ + j] * il[i];
    g_colsum[h * S_ + j] = acc;
}

__global__ __launch_bounds__(256) void topk_kernel() {
    int h = blockIdx.x;
    int tid = threadIdx.x;
    __shared__ float vals[S_];
    __shared__ float bv[256];
    __shared__ int bi[256];
    for (int j = tid; j < S_; j += 256) vals[j] = g_colsum[h * S_ + j];
    __syncthreads();
    for (int it = 0; it < HB_; it++) {
        float best = -INFINITY; int besti = 1 << 30;
        for (int j = tid; j < S_; j += 256) {
            float v = vals[j];
            if (v > best || (v == best && j < besti)) { best = v; besti = j; }
        }
        bv[tid] = best; bi[tid] = besti; __syncthreads();
        for (int off = 128; off > 0; off >>= 1) {
            if (tid < off) {
                if (bv[tid + off] > bv[tid] ||
                    (bv[tid + off] == bv[tid] && bi[tid + off] < bi[tid])) {
                    bv[tid] = bv[tid + off]; bi[tid] = bi[tid + off];
                }
            }
            __syncthreads();
        }
        if (tid == 0) { g_heavylist[h * HB_ + it] = bi[0]; vals[bi[0]] = -INFINITY; }
        __syncthreads();
    }
}

// ------ pass-2: masked e2 (band + heavy gather), zero elsewhere ---------
__global__ __launch_bounds__(256) void rowstats2_kernel() {
    int h = blockIdx.y;
    int tid = threadIdx.x;
    __shared__ int hl[HB_];
    for (int t = tid; t < HB_; t += 256) hl[t] = g_heavylist[h * HB_ + t];
    __syncthreads();

    int w = tid >> 5, lane = tid & 31;
    int i = blockIdx.x * 8 + w;
    float* erow = g_e + (size_t)(h * S_ + i) * S_;
    const float* srow = g_scores + (size_t)(h * S_ + i) * S_;
    int lo = i - RB_; if (lo < 0) lo = 0;
    int zend = ((i >> 7) + 1) << 7;   // covers all j PV will read for this row

    float4 z4 = make_float4(0.f, 0.f, 0.f, 0.f);
    for (int j4 = lane * 4; j4 < zend; j4 += 128)
        *(float4*)(erow + j4) = z4;
    __syncwarp();

    float l = 0.f;
    for (int j = lo + lane; j <= i; j += 32) {
        float e = fexp(srow[j]);
        erow[j] = e;
        l += e;
    }
    for (int t = lane; t < HB_; t += 32) {
        int j = hl[t];
        if (j < lo) {
            float e = fexp(srow[j]);
            erow[j] = e;
            l += e;
        }
    }
#pragma unroll
    for (int off = 16; off > 0; off >>= 1)
        l += __shfl_xor_sync(0xFFFFFFFF, l, off);
    if (lane == 0) g_invl2[h * S_ + i] = 1.f / l;
}

// ------------------------------ launcher ---------------------------------
extern "C" void kernel_launch(void* const* d_in, const int* in_sizes, int n_in,
                              void* d_out, int out_size) {
    const float* hidden = (const float*)d_in[0];
    const float* Wq = (const float*)d_in[1];
    const float* Wk = (const float*)d_in[2];
    const float* Wv = (const float*)d_in[3];
    const float* Wo = (const float*)d_in[4];
    float* out = (float*)d_out;

    float *q, *k, *v, *scores, *e, *il2;
    __nv_bfloat16 *xhat, *wqt, *wkt, *wvt, *wot, *qhat, *khat, *vthat, *aohat;
    cudaGetSymbolAddress((void**)&q, g_q);
    cudaGetSymbolAddress((void**)&k, g_k);
    cudaGetSymbolAddress((void**)&v, g_v);
    cudaGetSymbolAddress((void**)&scores, g_scores);
    cudaGetSymbolAddress((void**)&e, g_e);
    cudaGetSymbolAddress((void**)&il2, g_invl2);
    cudaGetSymbolAddress((void**)&xhat, g_xhat);
    cudaGetSymbolAddress((void**)&wqt, g_wqt);
    cudaGetSymbolAddress((void**)&wkt, g_wkt);
    cudaGetSymbolAddress((void**)&wvt, g_wvt);
    cudaGetSymbolAddress((void**)&wot, g_wot);
    cudaGetSymbolAddress((void**)&qhat, g_qhat);
    cudaGetSymbolAddress((void**)&khat, g_khat);
    cudaGetSymbolAddress((void**)&vthat, g_vthat);
    cudaGetSymbolAddress((void**)&aohat, g_aohat);

    const int SMEM_GEMM = 66560;
    const int SMEM_PV = 99328;
    cudaFuncSetAttribute(mma_gemm, cudaFuncAttributeMaxDynamicSharedMemorySize, SMEM_GEMM);
    cudaFuncSetAttribute(pv_mma, cudaFuncAttributeMaxDynamicSharedMemorySize, SMEM_PV);

    // 1. split inputs / weights to bf16 hi-lo
    split_plain<<<(S_ * HID_ + 255) / 256, 256>>>(hidden, xhat, S_, HID_);
    transpose_split<<<dim3(HID_ / 32, HID_ / 32, 1), dim3(32, 8)>>>(Wq, HID_, HID_, HID_, wqt);
    transpose_split<<<dim3((NKV_ * D_) / 32, HID_ / 32, 1), dim3(32, 8)>>>(Wk, NKV_ * D_, HID_, NKV_ * D_, wkt);
    transpose_split<<<dim3((NKV_ * D_) / 32, HID_ / 32, 1), dim3(32, 8)>>>(Wv, NKV_ * D_, HID_, NKV_ * D_, wvt);
    transpose_split<<<dim3(HID_ / 32, HID_ / 32, 1), dim3(32, 8)>>>(Wo, HID_, HID_, HID_, wot);

    // 2. QKV projections
    mma_gemm<<<dim3(HID_ / 128, S_ / 128, 1), 256, SMEM_GEMM>>>(xhat, 0, wqt, 0, 0, q, 0, HID_, 3 * HID_, 0);
    mma_gemm<<<dim3((NKV_ * D_) / 128, S_ / 128, 1), 256, SMEM_GEMM>>>(xhat, 0, wkt, 0, 0, k, 0, NKV_ * D_, 3 * HID_, 0);
    mma_gemm<<<dim3((NKV_ * D_) / 128, S_ / 128, 1), 256, SMEM_GEMM>>>(xhat, 0, wvt, 0, 0, v, 0, NKV_ * D_, 3 * HID_, 0);

    // 3. RoPE
    rope_kernel<<<(S_ * NH_ * 64 + 255) / 256, 256>>>(q, NH_);
    rope_kernel<<<(S_ * NKV_ * 64 + 255) / 256, 256>>>(k, NKV_);

    // 4. split roped Q/K, transpose-split V
    split_heads<<<(S_ * NH_ * D_ + 255) / 256, 256>>>(q, qhat, NH_, 0);
    split_heads<<<(S_ * NKV_ * D_ + 255) / 256, 256>>>(k, khat, NKV_, 1);
    transpose_split<<<dim3(D_ / 32, S_ / 32, NKV_), dim3(32, 8)>>>(v, NKV_ * D_, S_, D_, vthat);

    // 5. scores = QK^T (lower triangle only)
    mma_gemm<<<dim3(S_ / 128, S_ / 128, NH_), 256, SMEM_GEMM>>>(
        qhat, (size_t)S_ * 3 * D_, khat, (size_t)S_ * 3 * D_, 2,
        scores, (size_t)S_ * S_, S_, 3 * D_, 1);

    // 6. H2O: e1 + invl1, colsum (exp-free), topk
    rowstats1_kernel<<<dim3(S_, NH_), 256>>>();
    colsum_kernel<<<dim3(S_ / 256, NH_), 256>>>();
    topk_kernel<<<NH_, 256>>>();

    // 7. masked e2 + invl2
    rowstats2_kernel<<<dim3(S_ / 8, NH_), 256>>>();

    // 8. fused PV -> aohat (split, pattern A)
    pv_mma<<<dim3(S_ / 128, NH_), 256, SMEM_PV>>>(vthat, e, il2, aohat);

    // 9. output projection
    mma_gemm<<<dim3(HID_ / 128, S_ / 128, 1), 256, SMEM_GEMM>>>(aohat, 0, wot, 0, 0, out, 0, HID_, 3 * HID_, 0);
}

// round 7
// speedup vs baseline: 2.3320x; 1.0861x over previous
#include <cuda_runtime.h>
#include <cuda_bf16.h>
#include <math.h>
#include <stdint.h>

#define S_    2048
#define HID_  2048
#define NH_   16
#define NKV_  4
#define D_    128
#define HB_   204
#define RB_   204
#define NEG_  (-3.4028234663852886e38f)
#define SCALE_ 0.08838834764831845f
#define L2E_  1.4426950408889634f
#define QKVN_ 3072

// ----------------------------- scratch ---------------------------------
__device__ float g_qkv[S_ * QKVN_];                 // [s][ q(2048) | k(512) | v(512) ]
__device__ float g_e[(size_t)NH_ * S_ * S_];        // exp(score) lower triangle
__device__ float g_invl1[NH_ * S_], g_invl2[NH_ * S_];
__device__ float g_colsum[NH_ * S_];
__device__ int   g_heavylist[NH_ * HB_];
__device__ uint32_t g_heavybits[NH_ * 64];

__device__ __nv_bfloat16 g_xhat[(size_t)S_ * 3 * HID_];          // A-pattern [hi|lo|hi]
__device__ __nv_bfloat16 g_wqkvt[(size_t)QKVN_ * 3 * HID_];      // B-pattern [hi|hi|lo] (Wq|Wk|Wv)^T
__device__ __nv_bfloat16 g_wot[(size_t)HID_ * 3 * HID_];
__device__ __nv_bfloat16 g_qhat[(size_t)NH_ * S_ * 3 * D_];      // A-pattern
__device__ __nv_bfloat16 g_khat[(size_t)NKV_ * S_ * 3 * D_];     // B-pattern
__device__ __nv_bfloat16 g_vthat[(size_t)NKV_ * D_ * 3 * S_];    // B-pattern (V^T)
__device__ __nv_bfloat16 g_aohat[(size_t)S_ * 3 * HID_];         // A-pattern

// ----------------------------- PTX helpers ------------------------------
__device__ __forceinline__ uint32_t smem_u32(const void* p) {
    uint32_t a;
    asm("{ .reg .u64 t; cvta.to.shared.u64 t, %1; cvt.u32.u64 %0, t; }" : "=r"(a) : "l"(p));
    return a;
}
__device__ __forceinline__ void cp16(uint32_t saddr, const void* gptr) {
    asm volatile("cp.async.cg.shared.global [%0], [%1], 16;" :: "r"(saddr), "l"(gptr));
}
__device__ __forceinline__ void cp_commit() { asm volatile("cp.async.commit_group;"); }
__device__ __forceinline__ void cp_wait0() { asm volatile("cp.async.wait_group 0;" ::: "memory"); }
__device__ __forceinline__ void cp_wait1() { asm volatile("cp.async.wait_group 1;" ::: "memory"); }

__device__ __forceinline__ void ldsm4(uint32_t& r0, uint32_t& r1, uint32_t& r2, uint32_t& r3,
                                      uint32_t addr) {
    asm volatile("ldmatrix.sync.aligned.m8n8.x4.shared.b16 {%0,%1,%2,%3}, [%4];"
                 : "=r"(r0), "=r"(r1), "=r"(r2), "=r"(r3) : "r"(addr));
}
__device__ __forceinline__ void mma16816(float* d, const uint32_t* a, const uint32_t* b) {
    asm volatile(
        "mma.sync.aligned.m16n8k16.row.col.f32.bf16.bf16.f32 "
        "{%0,%1,%2,%3}, {%4,%5,%6,%7}, {%8,%9}, {%0,%1,%2,%3};"
        : "+f"(d[0]), "+f"(d[1]), "+f"(d[2]), "+f"(d[3])
        : "r"(a[0]), "r"(a[1]), "r"(a[2]), "r"(a[3]), "r"(b[0]), "r"(b[1]));
}
__device__ __forceinline__ float fexp(float x) {
    float y;
    asm("ex2.approx.ftz.f32 %0, %1;" : "=f"(y) : "f"(x * L2E_));
    return y;
}
__device__ __forceinline__ uint32_t split_pack(float p0, float p1, uint32_t& lo) {
    __nv_bfloat16 h0 = __float2bfloat16(p0), h1 = __float2bfloat16(p1);
    float f0 = __bfloat162float(h0), f1 = __bfloat162float(h1);
    __nv_bfloat16 l0 = __float2bfloat16(p0 - f0), l1 = __float2bfloat16(p1 - f1);
    lo = (uint32_t)__bfloat16_as_ushort(l0) | ((uint32_t)__bfloat16_as_ushort(l1) << 16);
    return (uint32_t)__bfloat16_as_ushort(h0) | ((uint32_t)__bfloat16_as_ushort(h1) << 16);
}

// ------------------------- HMMA GEMM -------------------------
__device__ __forceinline__ void load_tile_async(uint32_t sbase, const __nv_bfloat16* src,
                                                int ld, int row0, int kbase, int tid) {
#pragma unroll
    for (int t = 0; t < 4; t++) {
        int u = tid + t * 256;
        int row = u >> 3, seg = u & 7;
        uint32_t bo = (uint32_t)(row * 128 + seg * 16);
        bo ^= (bo >> 3) & 0x70;
        cp16(sbase + bo, src + (size_t)(row0 + row) * ld + kbase + seg * 8);
    }
}

// mode 0: plain fp32 store. mode 2: store e = exp(scale*s) for j<=i, 0 above.
__global__ __launch_bounds__(256) void mma_gemm(
    const __nv_bfloat16* __restrict__ A, size_t aStrideZ,
    const __nv_bfloat16* __restrict__ Bt, size_t bStrideZ, int bShift,
    float* __restrict__ C, size_t cStrideZ, int ldc,
    int Kp, int mode) {
    int z = blockIdx.z;
    int i0 = blockIdx.y * 128, j0 = blockIdx.x * 128;
    if (mode == 2 && j0 > i0 + 127) return;   // fully above diagonal: skip

    const __nv_bfloat16* Az = A + (size_t)z * aStrideZ;
    const __nv_bfloat16* Bz = Bt + (size_t)(z >> bShift) * bStrideZ;
    float* Cz = C + (size_t)z * cStrideZ;
    int tid = threadIdx.x, wid = tid >> 5;
    uint32_t lane = tid & 31;

    extern __shared__ char dsm[];
    char* tile = (char*)(((uintptr_t)dsm + 1023) & ~(uintptr_t)1023);
    uint32_t sA[2] = { smem_u32(tile), smem_u32(tile) + 16384 };
    uint32_t sB[2] = { smem_u32(tile) + 32768, smem_u32(tile) + 49152 };

    int warp_m = wid >> 2;
    int warp_n = wid & 3;

    float acc[4][4][4];
#pragma unroll
    for (int i = 0; i < 4; i++)
#pragma unroll
        for (int j = 0; j < 4; j++)
#pragma unroll
            for (int r = 0; r < 4; r++) acc[i][j][r] = 0.f;

    load_tile_async(sA[0], Az, Kp, i0, 0, tid);
    load_tile_async(sB[0], Bz, Kp, j0, 0, tid);
    cp_commit();

    const int NC = Kp >> 6;
    for (int c = 0; c < NC; c++) {
        if (c + 1 < NC) {
            load_tile_async(sA[(c + 1) & 1], Az, Kp, i0, (c + 1) * 64, tid);
            load_tile_async(sB[(c + 1) & 1], Bz, Kp, j0, (c + 1) * 64, tid);
            cp_commit();
            cp_wait1();
        } else {
            cp_wait0();
        }
        __syncthreads();

        uint32_t a_base = sA[c & 1], b_base = sB[c & 1];
#pragma unroll
        for (int ks = 0; ks < 4; ks++) {
            uint32_t a[4][4], b[2][4];
#pragma unroll
            for (int mf = 0; mf < 4; mf++) {
                int row = 64 * warp_m + 16 * mf + (lane & 7) + (((lane >> 3) & 1) << 3);
                int colb = (16 * ks + (((lane >> 4) & 1) << 3)) * 2;
                uint32_t off = (uint32_t)(row * 128 + colb);
                off ^= (off >> 3) & 0x70;
                ldsm4(a[mf][0], a[mf][1], a[mf][2], a[mf][3], a_base + off);
            }
#pragma unroll
            for (int nf2 = 0; nf2 < 2; nf2++) {
                int row = 32 * warp_n + 16 * nf2 + (lane & 7) + (((lane >> 4) & 1) << 3);
                int colb = (16 * ks + (((lane >> 3) & 1) << 3)) * 2;
                uint32_t off = (uint32_t)(row * 128 + colb);
                off ^= (off >> 3) & 0x70;
                ldsm4(b[nf2][0], b[nf2][1], b[nf2][2], b[nf2][3], b_base + off);
            }
#pragma unroll
            for (int mf = 0; mf < 4; mf++)
#pragma unroll
                for (int nf = 0; nf < 4; nf++)
                    mma16816(acc[mf][nf], a[mf], &b[nf >> 1][(nf & 1) * 2]);
        }
        __syncthreads();
    }

#pragma unroll
    for (int mf = 0; mf < 4; mf++) {
        int r0 = i0 + 64 * warp_m + 16 * mf + (int)(lane >> 2);
#pragma unroll
        for (int nf = 0; nf < 4; nf++) {
            int c0 = j0 + 32 * warp_n + 8 * nf + (int)(lane & 3) * 2;
            float d0 = acc[mf][nf][0], d1 = acc[mf][nf][1];
            float d2 = acc[mf][nf][2], d3 = acc[mf][nf][3];
            if (mode == 2) {
                d0 = (c0     <= r0)     ? fexp(d0 * SCALE_) : 0.f;
                d1 = (c0 + 1 <= r0)     ? fexp(d1 * SCALE_) : 0.f;
                d2 = (c0     <= r0 + 8) ? fexp(d2 * SCALE_) : 0.f;
                d3 = (c0 + 1 <= r0 + 8) ? fexp(d3 * SCALE_) : 0.f;
            }
            *(float2*)(Cz + (size_t)r0 * ldc + c0) = make_float2(d0, d1);
            *(float2*)(Cz + (size_t)(r0 + 8) * ldc + c0) = make_float2(d2, d3);
        }
    }
}

// ------------------------ fused PV (masked P on the fly) ------------------------
__global__ __launch_bounds__(256) void pv_mma(
    const __nv_bfloat16* __restrict__ vthat,
    const float* __restrict__ e, const float* __restrict__ invl2,
    const uint32_t* __restrict__ heavybits,
    __nv_bfloat16* __restrict__ aohat) {
    int i0 = blockIdx.x * 128, h = blockIdx.y, kh = h >> 2;
    int tid = threadIdx.x, wid = tid >> 5;
    uint32_t lane = tid & 31;
    int warp_m = wid >> 2, warp_n = wid & 3;

    extern __shared__ char dsm[];
    char* tile = (char*)(((uintptr_t)dsm + 1023) & ~(uintptr_t)1023);
    char* pPhi = tile;
    char* pPlo = tile + 16384;
    uint32_t sPhi = smem_u32(pPhi), sPlo = smem_u32(pPlo);
    uint32_t sVh[2] = { smem_u32(tile) + 32768, smem_u32(tile) + 49152 };
    uint32_t sVl[2] = { smem_u32(tile) + 65536, smem_u32(tile) + 81920 };

    __shared__ uint32_t sbits[64];
    if (tid < 64) sbits[tid] = heavybits[h * 64 + tid];

    int r = tid >> 1, half = tid & 1;
    int gi = i0 + r;
    float il = invl2[h * S_ + gi];
    const float* erow = e + ((size_t)h * S_ + gi) * S_ + half * 32;
    const __nv_bfloat16* Vz = vthat + (size_t)kh * D_ * 3 * S_;

    float acc[4][4][4];
#pragma unroll
    for (int i = 0; i < 4; i++)
#pragma unroll
        for (int j = 0; j < 4; j++)
#pragma unroll
            for (int q = 0; q < 4; q++) acc[i][j][q] = 0.f;

    const int NCH = (i0 >> 6) + 2;
    load_tile_async(sVh[0], Vz, 3 * S_, 0, 0, tid);
    load_tile_async(sVl[0], Vz, 3 * S_, 0, 2 * S_ + 0, tid);
    cp_commit();
    __syncthreads();   // sbits visible

    for (int c = 0; c < NCH; c++) {
        int j0 = c * 64;
        bool pre = (c + 1 < NCH);
        if (pre) {
            load_tile_async(sVh[(c + 1) & 1], Vz, 3 * S_, 0, (c + 1) * 64, tid);
            load_tile_async(sVl[(c + 1) & 1], Vz, 3 * S_, 0, 2 * S_ + (c + 1) * 64, tid);
            cp_commit();
        }
        // build masked split P tile (row r, 32 cols starting at j0 + half*32)
        uint32_t hib[16], lob[16];
        const float* ep = erow + j0;
        int gjb = j0 + half * 32;
#pragma unroll
        for (int q = 0; q < 8; q++) {
            float4 e4 = *(const float4*)(ep + q * 4);
            float pv[4] = { e4.x, e4.y, e4.z, e4.w };
#pragma unroll
            for (int u = 0; u < 4; u++) {
                int gj = gjb + q * 4 + u;
                bool keep = (gj <= gi) &&
                            ((gi - gj <= RB_) || ((sbits[gj >> 5] >> (gj & 31)) & 1u));
                pv[u] = keep ? pv[u] * il : 0.f;
            }
            hib[q * 2]     = split_pack(pv[0], pv[1], lob[q * 2]);
            hib[q * 2 + 1] = split_pack(pv[2], pv[3], lob[q * 2 + 1]);
        }
#pragma unroll
        for (int sg = 0; sg < 4; sg++) {
            uint32_t bo = (uint32_t)(r * 128 + half * 64 + sg * 16);
            bo ^= (bo >> 3) & 0x70;
            *(uint4*)(pPhi + bo) = make_uint4(hib[sg * 4], hib[sg * 4 + 1], hib[sg * 4 + 2], hib[sg * 4 + 3]);
            *(uint4*)(pPlo + bo) = make_uint4(lob[sg * 4], lob[sg * 4 + 1], lob[sg * 4 + 2], lob[sg * 4 + 3]);
        }
        if (pre) cp_wait1(); else cp_wait0();
        __syncthreads();

        uint32_t abases[3] = { sPhi, sPlo, sPhi };
        uint32_t bbases[3] = { sVh[c & 1], sVh[c & 1], sVl[c & 1] };
#pragma unroll
        for (int t = 0; t < 3; t++) {
            uint32_t a_base = abases[t], b_base = bbases[t];
#pragma unroll
            for (int ks = 0; ks < 4; ks++) {
                uint32_t a[4][4], b[2][4];
#pragma unroll
                for (int mf = 0; mf < 4; mf++) {
                    int row = 64 * warp_m + 16 * mf + (lane & 7) + (((lane >> 3) & 1) << 3);
                    int colb = (16 * ks + (((lane >> 4) & 1) << 3)) * 2;
                    uint32_t off = (uint32_t)(row * 128 + colb);
                    off ^= (off >> 3) & 0x70;
                    ldsm4(a[mf][0], a[mf][1], a[mf][2], a[mf][3], a_base + off);
                }
#pragma unroll
                for (int nf2 = 0; nf2 < 2; nf2++) {
                    int row = 32 * warp_n + 16 * nf2 + (lane & 7) + (((lane >> 4) & 1) << 3);
                    int colb = (16 * ks + (((lane >> 3) & 1) << 3)) * 2;
                    uint32_t off = (uint32_t)(row * 128 + colb);
                    off ^= (off >> 3) & 0x70;
                    ldsm4(b[nf2][0], b[nf2][1], b[nf2][2], b[nf2][3], b_base + off);
                }
#pragma unroll
                for (int mf = 0; mf < 4; mf++)
#pragma unroll
                    for (int nf = 0; nf < 4; nf++)
                        mma16816(acc[mf][nf], a[mf], &b[nf >> 1][(nf & 1) * 2]);
            }
        }
        __syncthreads();
    }

    // epilogue: write split aohat directly (pattern A: hi | lo | hi)
#pragma unroll
    for (int mf = 0; mf < 4; mf++) {
        int r0 = i0 + 64 * warp_m + 16 * mf + (int)(lane >> 2);
#pragma unroll
        for (int nf = 0; nf < 4; nf++) {
            int c0 = 32 * warp_n + 8 * nf + (int)(lane & 3) * 2;
#pragma unroll
            for (int rr = 0; rr < 2; rr++) {
                float d0 = acc[mf][nf][rr * 2], d1 = acc[mf][nf][rr * 2 + 1];
                uint32_t lo, hi = split_pack(d0, d1, lo);
                size_t b0 = (size_t)(r0 + rr * 8) * (3 * HID_) + h * D_ + c0;
                *(uint32_t*)(aohat + b0) = hi;
                *(uint32_t*)(aohat + b0 + HID_) = lo;
                *(uint32_t*)(aohat + b0 + 2 * HID_) = hi;
            }
        }
    }
}

// ----------------------- split-bf16 conversion kernels -------------------
__global__ void split_plain(const float* __restrict__ A, __nv_bfloat16* __restrict__ out,
                            int M, int K) {  // pattern A
    int idx = blockIdx.x * blockDim.x + threadIdx.x;
    if (idx >= M * K) return;
    int m = idx / K, k = idx - m * K;
    float x = A[idx];
    __nv_bfloat16 hi = __float2bfloat16(x);
    __nv_bfloat16 lo = __float2bfloat16(x - __bfloat162float(hi));
    size_t base = (size_t)m * 3 * K;
    out[base + k] = hi; out[base + K + k] = lo; out[base + 2 * K + k] = hi;
}

__global__ void split_heads(const float* __restrict__ src, int ld,
                            __nv_bfloat16* __restrict__ out, int nh, int patternB) {
    int idx = blockIdx.x * blockDim.x + threadIdx.x;
    if (idx >= S_ * nh * D_) return;
    int d = idx & 127;
    int h = (idx >> 7) % nh;
    int s = idx / (nh * D_);
    float x = src[(size_t)s * ld + h * D_ + d];
    __nv_bfloat16 hi = __float2bfloat16(x);
    __nv_bfloat16 lo = __float2bfloat16(x - __bfloat162float(hi));
    size_t base = ((size_t)h * S_ + s) * (3 * D_);
    if (patternB) { out[base + d] = hi; out[base + D_ + d] = hi; out[base + 2 * D_ + d] = lo; }
    else          { out[base + d] = hi; out[base + D_ + d] = lo; out[base + 2 * D_ + d] = hi; }
}

__global__ void transpose_split(const float* __restrict__ src, int ldsrc, int K, int Nper,
                                __nv_bfloat16* __restrict__ out) {  // pattern B
    int z = blockIdx.z;
    const float* s = src + (size_t)z * Nper;
    __nv_bfloat16* o = out + (size_t)z * Nper * 3 * K;
    __shared__ float t[32][33];
    int k0 = blockIdx.y * 32, n0 = blockIdx.x * 32;
    int tx = threadIdx.x, ty = threadIdx.y;
#pragma unroll
    for (int r = 0; r < 4; r++) {
        int k = k0 + ty + 8 * r;
        t[ty + 8 * r][tx] = s[(size_t)k * ldsrc + n0 + tx];
    }
    __syncthreads();
#pragma unroll
    for (int r = 0; r < 4; r++) {
        int n = n0 + ty + 8 * r, k = k0 + tx;
        float x = t[tx][ty + 8 * r];
        __nv_bfloat16 hi = __float2bfloat16(x);
        __nv_bfloat16 lo = __float2bfloat16(x - __bfloat162float(hi));
        size_t base = (size_t)n * 3 * K;
        o[base + k] = hi; o[base + K + k] = hi; o[base + 2 * K + k] = lo;
    }
}

// --------------------------------- RoPE ---------------------------------
__global__ void rope_kernel(float* x, int nh, int ld) {
    int idx = blockIdx.x * blockDim.x + threadIdx.x;
    if (idx >= S_ * nh * 64) return;
    int d = idx & 63;
    int rest = idx >> 6;
    int h = rest % nh;
    int s = rest / nh;
    float* base = x + (size_t)s * ld + h * 128;
    float x1 = base[d], x2 = base[d + 64];
    float inv = powf(10000.f, -(float)d * (1.f / 64.f));
    float ang = (float)s * inv;
    float c, sn;
    sincosf(ang, &sn, &c);
    base[d] = x1 * c - x2 * sn;
    base[d + 64] = x2 * c + x1 * sn;
}

// ------------------ pass-1: row sums of e -> invl1 ------------
__global__ __launch_bounds__(256) void rowsum1_kernel() {
    int h = blockIdx.y;
    int w = threadIdx.x >> 5, lane = threadIdx.x & 31;
    int i = blockIdx.x * 8 + w;
    const float* erow = g_e + (size_t)(h * S_ + i) * S_;
    float l = 0.f;
    for (int j = lane; j <= i; j += 32) l += erow[j];
#pragma unroll
    for (int off = 16; off > 0; off >>= 1)
        l += __shfl_xor_sync(0xFFFFFFFF, l, off);
    if (lane == 0) g_invl1[h * S_ + i] = 1.f / l;
}

__global__ __launch_bounds__(256) void colsum_kernel() {
    int h = blockIdx.y;
    int j = blockIdx.x * 256 + threadIdx.x;
    const float* base = g_e + (size_t)h * S_ * S_;
    const float* il = g_invl1 + h * S_;
    float acc = 0.f;
    for (int i = j; i < S_; i++)
        acc += base[(size_t)i * S_ + j] * il[i];
    g_colsum[h * S_ + j] = acc;
}

__global__ __launch_bounds__(256) void topk_kernel() {
    int h = blockIdx.x;
    int tid = threadIdx.x;
    __shared__ float vals[S_];
    __shared__ float bv[256];
    __shared__ int bi[256];
    __shared__ uint32_t bits[64];
    for (int j = tid; j < S_; j += 256) vals[j] = g_colsum[h * S_ + j];
    if (tid < 64) bits[tid] = 0;
    __syncthreads();
    for (int it = 0; it < HB_; it++) {
        float best = -INFINITY; int besti = 1 << 30;
        for (int j = tid; j < S_; j += 256) {
            float v = vals[j];
            if (v > best || (v == best && j < besti)) { best = v; besti = j; }
        }
        bv[tid] = best; bi[tid] = besti; __syncthreads();
        for (int off = 128; off > 0; off >>= 1) {
            if (tid < off) {
                if (bv[tid + off] > bv[tid] ||
                    (bv[tid + off] == bv[tid] && bi[tid + off] < bi[tid])) {
                    bv[tid] = bv[tid + off]; bi[tid] = bi[tid + off];
                }
            }
            __syncthreads();
        }
        if (tid == 0) {
            int b0 = bi[0];
            g_heavylist[h * HB_ + it] = b0;
            bits[b0 >> 5] |= (1u << (b0 & 31));
            vals[b0] = -INFINITY;
        }
        __syncthreads();
    }
    if (tid < 64) g_heavybits[h * 64 + tid] = bits[tid];
}

// ------ pass-2: invl2 = 1/sum(e over band + heavy) -- no exp, no writes to e -----
__global__ __launch_bounds__(256) void rowsum2_kernel() {
    int h = blockIdx.y;
    int tid = threadIdx.x;
    __shared__ int hl[HB_];
    for (int t = tid; t < HB_; t += 256) hl[t] = g_heavylist[h * HB_ + t];
    __syncthreads();

    int w = tid >> 5, lane = tid & 31;
    int i = blockIdx.x * 8 + w;
    const float* erow = g_e + (size_t)(h * S_ + i) * S_;
    int lo = i - RB_; if (lo < 0) lo = 0;

    float l = 0.f;
    for (int j = lo + lane; j <= i; j += 32) l += erow[j];
    for (int t = lane; t < HB_; t += 32) {
        int j = hl[t];
        if (j < lo) l += erow[j];
    }
#pragma unroll
    for (int off = 16; off > 0; off >>= 1)
        l += __shfl_xor_sync(0xFFFFFFFF, l, off);
    if (lane == 0) g_invl2[h * S_ + i] = 1.f / l;
}

// ------------------------------ launcher ---------------------------------
extern "C" void kernel_launch(void* const* d_in, const int* in_sizes, int n_in,
                              void* d_out, int out_size) {
    const float* hidden = (const float*)d_in[0];
    const float* Wq = (const float*)d_in[1];
    const float* Wk = (const float*)d_in[2];
    const float* Wv = (const float*)d_in[3];
    const float* Wo = (const float*)d_in[4];
    float* out = (float*)d_out;

    float *qkv, *e, *il2;
    uint32_t* hbits;
    __nv_bfloat16 *xhat, *wqkvt, *wot, *qhat, *khat, *vthat, *aohat;
    cudaGetSymbolAddress((void**)&qkv, g_qkv);
    cudaGetSymbolAddress((void**)&e, g_e);
    cudaGetSymbolAddress((void**)&il2, g_invl2);
    cudaGetSymbolAddress((void**)&hbits, g_heavybits);
    cudaGetSymbolAddress((void**)&xhat, g_xhat);
    cudaGetSymbolAddress((void**)&wqkvt, g_wqkvt);
    cudaGetSymbolAddress((void**)&wot, g_wot);
    cudaGetSymbolAddress((void**)&qhat, g_qhat);
    cudaGetSymbolAddress((void**)&khat, g_khat);
    cudaGetSymbolAddress((void**)&vthat, g_vthat);
    cudaGetSymbolAddress((void**)&aohat, g_aohat);

    const int SMEM_GEMM = 66560;
    const int SMEM_PV = 99328;
    cudaFuncSetAttribute(mma_gemm, cudaFuncAttributeMaxDynamicSharedMemorySize, SMEM_GEMM);
    cudaFuncSetAttribute(pv_mma, cudaFuncAttributeMaxDynamicSharedMemorySize, SMEM_PV);

    // 1. split inputs / weights to bf16 hi-lo (Wq|Wk|Wv concatenated transposed)
    split_plain<<<(S_ * HID_ + 255) / 256, 256>>>(hidden, xhat, S_, HID_);
    transpose_split<<<dim3(HID_ / 32, HID_ / 32, 1), dim3(32, 8)>>>(Wq, HID_, HID_, HID_, wqkvt);
    transpose_split<<<dim3((NKV_ * D_) / 32, HID_ / 32, 1), dim3(32, 8)>>>(
        Wk, NKV_ * D_, HID_, NKV_ * D_, wqkvt + (size_t)HID_ * 3 * HID_);
    transpose_split<<<dim3((NKV_ * D_) / 32, HID_ / 32, 1), dim3(32, 8)>>>(
        Wv, NKV_ * D_, HID_, NKV_ * D_, wqkvt + (size_t)(HID_ + NKV_ * D_) * 3 * HID_);
    transpose_split<<<dim3(HID_ / 32, HID_ / 32, 1), dim3(32, 8)>>>(Wo, HID_, HID_, HID_, wot);

    // 2. fused QKV projection (one GEMM, N=3072)
    mma_gemm<<<dim3(QKVN_ / 128, S_ / 128, 1), 256, SMEM_GEMM>>>(
        xhat, 0, wqkvt, 0, 0, qkv, 0, QKVN_, 3 * HID_, 0);

    // 3. RoPE (in place inside g_qkv)
    rope_kernel<<<(S_ * NH_ * 64 + 255) / 256, 256>>>(qkv, NH_, QKVN_);
    rope_kernel<<<(S_ * NKV_ * 64 + 255) / 256, 256>>>(qkv + HID_, NKV_, QKVN_);

    // 4. split roped Q/K, transpose-split V
    split_heads<<<(S_ * NH_ * D_ + 255) / 256, 256>>>(qkv, QKVN_, qhat, NH_, 0);
    split_heads<<<(S_ * NKV_ * D_ + 255) / 256, 256>>>(qkv + HID_, QKVN_, khat, NKV_, 1);
    transpose_split<<<dim3(D_ / 32, S_ / 32, NKV_), dim3(32, 8)>>>(
        qkv + HID_ + NKV_ * D_, QKVN_, S_, D_, vthat);

    // 5. e = exp(scale * QK^T) directly (lower triangle; zeros above diag in diag tiles)
    mma_gemm<<<dim3(S_ / 128, S_ / 128, NH_), 256, SMEM_GEMM>>>(
        qhat, (size_t)S_ * 3 * D_, khat, (size_t)S_ * 3 * D_, 2,
        e, (size_t)S_ * S_, S_, 3 * D_, 2);

    // 6. H2O: invl1, colsum, topk (emits heavy bitmask)
    rowsum1_kernel<<<dim3(S_ / 8, NH_), 256>>>();
    colsum_kernel<<<dim3(S_ / 256, NH_), 256>>>();
    topk_kernel<<<NH_, 256>>>();

    // 7. invl2 (sum-only; e untouched)
    rowsum2_kernel<<<dim3(S_ / 8, NH_), 256>>>();

    // 8. fused masked PV -> aohat (split, pattern A)
    pv_mma<<<dim3(S_ / 128, NH_), 256, SMEM_PV>>>(vthat, e, il2, hbits, aohat);

    // 9. output projection
    mma_gemm<<<dim3(HID_ / 128, S_ / 128, 1), 256, SMEM_GEMM>>>(
        aohat, 0, wot, 0, 0, out, 0, HID_, 3 * HID_, 0);
}

// round 8
// speedup vs baseline: 2.5662x; 1.1004x over previous
#include <cuda_runtime.h>
#include <cuda_bf16.h>
#include <math.h>
#include <stdint.h>

#define S_    2048
#define HID_  2048
#define NH_   16
#define NKV_  4
#define D_    128
#define HB_   204
#define RB_   204
#define SCALE_ 0.08838834764831845f
#define L2E_  1.4426950408889634f
#define QKVN_ 3072

// ----------------------------- scratch ---------------------------------
__device__ float g_qkv[S_ * QKVN_];                 // [s][ q(2048) | k(512) | v(512) ]
__device__ float g_e[(size_t)NH_ * S_ * S_];        // exp(score); zero above diagonal
__device__ float g_invl1[NH_ * S_], g_invl2[NH_ * S_];
__device__ float g_colsum[NH_ * S_];
__device__ int   g_heavylist[NH_ * HB_];
__device__ uint32_t g_heavybits[NH_ * 64];

__device__ __nv_bfloat16 g_xhat[(size_t)S_ * 3 * HID_];          // A-pattern [hi|lo|hi]
__device__ __nv_bfloat16 g_wqkvt[(size_t)QKVN_ * 3 * HID_];      // B-pattern [hi|hi|lo] (Wq|Wk|Wv)^T
__device__ __nv_bfloat16 g_wot[(size_t)HID_ * 3 * HID_];
__device__ __nv_bfloat16 g_qhat[(size_t)NH_ * S_ * 3 * D_];      // A-pattern
__device__ __nv_bfloat16 g_khat[(size_t)NKV_ * S_ * 3 * D_];     // B-pattern
__device__ __nv_bfloat16 g_vthat[(size_t)NKV_ * D_ * 3 * S_];    // B-pattern (V^T)
__device__ __nv_bfloat16 g_aohat[(size_t)S_ * 3 * HID_];         // A-pattern

// ----------------------------- PTX helpers ------------------------------
__device__ __forceinline__ uint32_t smem_u32(const void* p) {
    uint32_t a;
    asm("{ .reg .u64 t; cvta.to.shared.u64 t, %1; cvt.u32.u64 %0, t; }" : "=r"(a) : "l"(p));
    return a;
}
__device__ __forceinline__ void cp16(uint32_t saddr, const void* gptr) {
    asm volatile("cp.async.cg.shared.global [%0], [%1], 16;" :: "r"(saddr), "l"(gptr));
}
__device__ __forceinline__ void cp_commit() { asm volatile("cp.async.commit_group;"); }
__device__ __forceinline__ void cp_wait0() { asm volatile("cp.async.wait_group 0;" ::: "memory"); }
__device__ __forceinline__ void cp_wait1() { asm volatile("cp.async.wait_group 1;" ::: "memory"); }

__device__ __forceinline__ void ldsm4(uint32_t& r0, uint32_t& r1, uint32_t& r2, uint32_t& r3,
                                      uint32_t addr) {
    asm volatile("ldmatrix.sync.aligned.m8n8.x4.shared.b16 {%0,%1,%2,%3}, [%4];"
                 : "=r"(r0), "=r"(r1), "=r"(r2), "=r"(r3) : "r"(addr));
}
__device__ __forceinline__ void mma16816(float* d, const uint32_t* a, const uint32_t* b) {
    asm volatile(
        "mma.sync.aligned.m16n8k16.row.col.f32.bf16.bf16.f32 "
        "{%0,%1,%2,%3}, {%4,%5,%6,%7}, {%8,%9}, {%0,%1,%2,%3};"
        : "+f"(d[0]), "+f"(d[1]), "+f"(d[2]), "+f"(d[3])
        : "r"(a[0]), "r"(a[1]), "r"(a[2]), "r"(a[3]), "r"(b[0]), "r"(b[1]));
}
__device__ __forceinline__ float fexp(float x) {
    float y;
    asm("ex2.approx.ftz.f32 %0, %1;" : "=f"(y) : "f"(x * L2E_));
    return y;
}
__device__ __forceinline__ uint32_t split_pack(float p0, float p1, uint32_t& lo) {
    __nv_bfloat16 h0 = __float2bfloat16(p0), h1 = __float2bfloat16(p1);
    float f0 = __bfloat162float(h0), f1 = __bfloat162float(h1);
    __nv_bfloat16 l0 = __float2bfloat16(p0 - f0), l1 = __float2bfloat16(p1 - f1);
    lo = (uint32_t)__bfloat16_as_ushort(l0) | ((uint32_t)__bfloat16_as_ushort(l1) << 16);
    return (uint32_t)__bfloat16_as_ushort(h0) | ((uint32_t)__bfloat16_as_ushort(h1) << 16);
}

// ------------------------- HMMA GEMM -------------------------
__device__ __forceinline__ void load_tile_async(uint32_t sbase, const __nv_bfloat16* src,
                                                int ld, int row0, int kbase, int tid) {
#pragma unroll
    for (int t = 0; t < 4; t++) {
        int u = tid + t * 256;
        int row = u >> 3, seg = u & 7;
        uint32_t bo = (uint32_t)(row * 128 + seg * 16);
        bo ^= (bo >> 3) & 0x70;
        cp16(sbase + bo, src + (size_t)(row0 + row) * ld + kbase + seg * 8);
    }
}

// mode 0: plain fp32 store. mode 2: store e = exp(scale*s) for j<=i, 0 above.
__global__ __launch_bounds__(256, 2) void mma_gemm(
    const __nv_bfloat16* __restrict__ A, size_t aStrideZ,
    const __nv_bfloat16* __restrict__ Bt, size_t bStrideZ, int bShift,
    float* __restrict__ C, size_t cStrideZ, int ldc,
    int Kp, int mode) {
    int z = blockIdx.z;
    int i0 = blockIdx.y * 128, j0 = blockIdx.x * 128;
    if (mode == 2 && j0 > i0 + 127) return;   // fully above diagonal: skip

    const __nv_bfloat16* Az = A + (size_t)z * aStrideZ;
    const __nv_bfloat16* Bz = Bt + (size_t)(z >> bShift) * bStrideZ;
    float* Cz = C + (size_t)z * cStrideZ;
    int tid = threadIdx.x, wid = tid >> 5;
    uint32_t lane = tid & 31;

    extern __shared__ char dsm[];
    char* tile = (char*)(((uintptr_t)dsm + 1023) & ~(uintptr_t)1023);
    uint32_t sA[2] = { smem_u32(tile), smem_u32(tile) + 16384 };
    uint32_t sB[2] = { smem_u32(tile) + 32768, smem_u32(tile) + 49152 };

    int warp_m = wid >> 2;
    int warp_n = wid & 3;

    float acc[4][4][4];
#pragma unroll
    for (int i = 0; i < 4; i++)
#pragma unroll
        for (int j = 0; j < 4; j++)
#pragma unroll
            for (int r = 0; r < 4; r++) acc[i][j][r] = 0.f;

    load_tile_async(sA[0], Az, Kp, i0, 0, tid);
    load_tile_async(sB[0], Bz, Kp, j0, 0, tid);
    cp_commit();

    const int NC = Kp >> 6;
    for (int c = 0; c < NC; c++) {
        if (c + 1 < NC) {
            load_tile_async(sA[(c + 1) & 1], Az, Kp, i0, (c + 1) * 64, tid);
            load_tile_async(sB[(c + 1) & 1], Bz, Kp, j0, (c + 1) * 64, tid);
            cp_commit();
            cp_wait1();
        } else {
            cp_wait0();
        }
        __syncthreads();

        uint32_t a_base = sA[c & 1], b_base = sB[c & 1];
#pragma unroll
        for (int ks = 0; ks < 4; ks++) {
            uint32_t a[4][4], b[2][4];
#pragma unroll
            for (int mf = 0; mf < 4; mf++) {
                int row = 64 * warp_m + 16 * mf + (lane & 7) + (((lane >> 3) & 1) << 3);
                int colb = (16 * ks + (((lane >> 4) & 1) << 3)) * 2;
                uint32_t off = (uint32_t)(row * 128 + colb);
                off ^= (off >> 3) & 0x70;
                ldsm4(a[mf][0], a[mf][1], a[mf][2], a[mf][3], a_base + off);
            }
#pragma unroll
            for (int nf2 = 0; nf2 < 2; nf2++) {
                int row = 32 * warp_n + 16 * nf2 + (lane & 7) + (((lane >> 4) & 1) << 3);
                int colb = (16 * ks + (((lane >> 3) & 1) << 3)) * 2;
                uint32_t off = (uint32_t)(row * 128 + colb);
                off ^= (off >> 3) & 0x70;
                ldsm4(b[nf2][0], b[nf2][1], b[nf2][2], b[nf2][3], b_base + off);
            }
#pragma unroll
            for (int mf = 0; mf < 4; mf++)
#pragma unroll
                for (int nf = 0; nf < 4; nf++)
                    mma16816(acc[mf][nf], a[mf], &b[nf >> 1][(nf & 1) * 2]);
        }
        __syncthreads();
    }

#pragma unroll
    for (int mf = 0; mf < 4; mf++) {
        int r0 = i0 + 64 * warp_m + 16 * mf + (int)(lane >> 2);
#pragma unroll
        for (int nf = 0; nf < 4; nf++) {
            int c0 = j0 + 32 * warp_n + 8 * nf + (int)(lane & 3) * 2;
            float d0 = acc[mf][nf][0], d1 = acc[mf][nf][1];
            float d2 = acc[mf][nf][2], d3 = acc[mf][nf][3];
            if (mode == 2) {
                d0 = (c0     <= r0)     ? fexp(d0 * SCALE_) : 0.f;
                d1 = (c0 + 1 <= r0)     ? fexp(d1 * SCALE_) : 0.f;
                d2 = (c0     <= r0 + 8) ? fexp(d2 * SCALE_) : 0.f;
                d3 = (c0 + 1 <= r0 + 8) ? fexp(d3 * SCALE_) : 0.f;
            }
            *(float2*)(Cz + (size_t)r0 * ldc + c0) = make_float2(d0, d1);
            *(float2*)(Cz + (size_t)(r0 + 8) * ldc + c0) = make_float2(d2, d3);
        }
    }
}

// ------------------------ fused PV (masked P on the fly) ------------------------
__global__ __launch_bounds__(256) void pv_mma(
    const __nv_bfloat16* __restrict__ vthat,
    const float* __restrict__ e, const float* __restrict__ invl2,
    const uint32_t* __restrict__ heavybits,
    __nv_bfloat16* __restrict__ aohat) {
    int i0 = blockIdx.x * 128, h = blockIdx.y, kh = h >> 2;
    int tid = threadIdx.x, wid = tid >> 5;
    uint32_t lane = tid & 31;
    int warp_m = wid >> 2, warp_n = wid & 3;

    extern __shared__ char dsm[];
    char* tile = (char*)(((uintptr_t)dsm + 1023) & ~(uintptr_t)1023);
    char* pPhi = tile;
    char* pPlo = tile + 16384;
    uint32_t sPhi = smem_u32(pPhi), sPlo = smem_u32(pPlo);
    uint32_t sVh[2] = { smem_u32(tile) + 32768, smem_u32(tile) + 49152 };
    uint32_t sVl[2] = { smem_u32(tile) + 65536, smem_u32(tile) + 81920 };

    __shared__ uint32_t sbits[64];
    if (tid < 64) sbits[tid] = heavybits[h * 64 + tid];

    int r = tid >> 1, half = tid & 1;
    int gi = i0 + r;
    float il = invl2[h * S_ + gi];
    const float* erow = e + ((size_t)h * S_ + gi) * S_ + half * 32;
    const __nv_bfloat16* Vz = vthat + (size_t)kh * D_ * 3 * S_;

    float acc[4][4][4];
#pragma unroll
    for (int i = 0; i < 4; i++)
#pragma unroll
        for (int j = 0; j < 4; j++)
#pragma unroll
            for (int q = 0; q < 4; q++) acc[i][j][q] = 0.f;

    const int NCH = (i0 >> 6) + 2;
    load_tile_async(sVh[0], Vz, 3 * S_, 0, 0, tid);
    load_tile_async(sVl[0], Vz, 3 * S_, 0, 2 * S_ + 0, tid);
    cp_commit();
    __syncthreads();   // sbits visible

    for (int c = 0; c < NCH; c++) {
        int j0 = c * 64;
        bool pre = (c + 1 < NCH);
        if (pre) {
            load_tile_async(sVh[(c + 1) & 1], Vz, 3 * S_, 0, (c + 1) * 64, tid);
            load_tile_async(sVl[(c + 1) & 1], Vz, 3 * S_, 0, 2 * S_ + (c + 1) * 64, tid);
            cp_commit();
        }
        // build masked split P tile (row r, 32 cols starting at j0 + half*32)
        uint32_t hib[16], lob[16];
        const float* ep = erow + j0;
        int gjb = j0 + half * 32;
#pragma unroll
        for (int q = 0; q < 8; q++) {
            float4 e4 = *(const float4*)(ep + q * 4);
            float pv[4] = { e4.x, e4.y, e4.z, e4.w };
#pragma unroll
            for (int u = 0; u < 4; u++) {
                int gj = gjb + q * 4 + u;
                bool keep = (gj <= gi) &&
                            ((gi - gj <= RB_) || ((sbits[gj >> 5] >> (gj & 31)) & 1u));
                pv[u] = keep ? pv[u] * il : 0.f;
            }
            hib[q * 2]     = split_pack(pv[0], pv[1], lob[q * 2]);
            hib[q * 2 + 1] = split_pack(pv[2], pv[3], lob[q * 2 + 1]);
        }
#pragma unroll
        for (int sg = 0; sg < 4; sg++) {
            uint32_t bo = (uint32_t)(r * 128 + half * 64 + sg * 16);
            bo ^= (bo >> 3) & 0x70;
            *(uint4*)(pPhi + bo) = make_uint4(hib[sg * 4], hib[sg * 4 + 1], hib[sg * 4 + 2], hib[sg * 4 + 3]);
            *(uint4*)(pPlo + bo) = make_uint4(lob[sg * 4], lob[sg * 4 + 1], lob[sg * 4 + 2], lob[sg * 4 + 3]);
        }
        if (pre) cp_wait1(); else cp_wait0();
        __syncthreads();

        uint32_t abases[3] = { sPhi, sPlo, sPhi };
        uint32_t bbases[3] = { sVh[c & 1], sVh[c & 1], sVl[c & 1] };
#pragma unroll
        for (int t = 0; t < 3; t++) {
            uint32_t a_base = abases[t], b_base = bbases[t];
#pragma unroll
            for (int ks = 0; ks < 4; ks++) {
                uint32_t a[4][4], b[2][4];
#pragma unroll
                for (int mf = 0; mf < 4; mf++) {
                    int row = 64 * warp_m + 16 * mf + (lane & 7) + (((lane >> 3) & 1) << 3);
                    int colb = (16 * ks + (((lane >> 4) & 1) << 3)) * 2;
                    uint32_t off = (uint32_t)(row * 128 + colb);
                    off ^= (off >> 3) & 0x70;
                    ldsm4(a[mf][0], a[mf][1], a[mf][2], a[mf][3], a_base + off);
                }
#pragma unroll
                for (int nf2 = 0; nf2 < 2; nf2++) {
                    int row = 32 * warp_n + 16 * nf2 + (lane & 7) + (((lane >> 4) & 1) << 3);
                    int colb = (16 * ks + (((lane >> 3) & 1) << 3)) * 2;
                    uint32_t off = (uint32_t)(row * 128 + colb);
                    off ^= (off >> 3) & 0x70;
                    ldsm4(b[nf2][0], b[nf2][1], b[nf2][2], b[nf2][3], b_base + off);
                }
#pragma unroll
                for (int mf = 0; mf < 4; mf++)
#pragma unroll
                    for (int nf = 0; nf < 4; nf++)
                        mma16816(acc[mf][nf], a[mf], &b[nf >> 1][(nf & 1) * 2]);
            }
        }
        __syncthreads();
    }

    // epilogue: write split aohat directly (pattern A: hi | lo | hi)
#pragma unroll
    for (int mf = 0; mf < 4; mf++) {
        int r0 = i0 + 64 * warp_m + 16 * mf + (int)(lane >> 2);
#pragma unroll
        for (int nf = 0; nf < 4; nf++) {
            int c0 = 32 * warp_n + 8 * nf + (int)(lane & 3) * 2;
#pragma unroll
            for (int rr = 0; rr < 2; rr++) {
                float d0 = acc[mf][nf][rr * 2], d1 = acc[mf][nf][rr * 2 + 1];
                uint32_t lo, hi = split_pack(d0, d1, lo);
                size_t b0 = (size_t)(r0 + rr * 8) * (3 * HID_) + h * D_ + c0;
                *(uint32_t*)(aohat + b0) = hi;
                *(uint32_t*)(aohat + b0 + HID_) = lo;
                *(uint32_t*)(aohat + b0 + 2 * HID_) = hi;
            }
        }
    }
}

// ----------------------- split-bf16 conversion kernels -------------------
__global__ void split_plain(const float* __restrict__ A, __nv_bfloat16* __restrict__ out,
                            int M, int K) {  // pattern A
    int idx = blockIdx.x * blockDim.x + threadIdx.x;
    if (idx >= M * K) return;
    int m = idx / K, k = idx - m * K;
    float x = A[idx];
    __nv_bfloat16 hi = __float2bfloat16(x);
    __nv_bfloat16 lo = __float2bfloat16(x - __bfloat162float(hi));
    size_t base = (size_t)m * 3 * K;
    out[base + k] = hi; out[base + K + k] = lo; out[base + 2 * K + k] = hi;
}

__global__ void split_heads(const float* __restrict__ src, int ld,
                            __nv_bfloat16* __restrict__ out, int nh, int patternB) {
    int idx = blockIdx.x * blockDim.x + threadIdx.x;
    if (idx >= S_ * nh * D_) return;
    int d = idx & 127;
    int h = (idx >> 7) % nh;
    int s = idx / (nh * D_);
    float x = src[(size_t)s * ld + h * D_ + d];
    __nv_bfloat16 hi = __float2bfloat16(x);
    __nv_bfloat16 lo = __float2bfloat16(x - __bfloat162float(hi));
    size_t base = ((size_t)h * S_ + s) * (3 * D_);
    if (patternB) { out[base + d] = hi; out[base + D_ + d] = hi; out[base + 2 * D_ + d] = lo; }
    else          { out[base + d] = hi; out[base + D_ + d] = lo; out[base + 2 * D_ + d] = hi; }
}

__global__ void transpose_split(const float* __restrict__ src, int ldsrc, int K, int Nper,
                                __nv_bfloat16* __restrict__ out) {  // pattern B
    int z = blockIdx.z;
    const float* s = src + (size_t)z * Nper;
    __nv_bfloat16* o = out + (size_t)z * Nper * 3 * K;
    __shared__ float t[32][33];
    int k0 = blockIdx.y * 32, n0 = blockIdx.x * 32;
    int tx = threadIdx.x, ty = threadIdx.y;
#pragma unroll
    for (int r = 0; r < 4; r++) {
        int k = k0 + ty + 8 * r;
        t[ty + 8 * r][tx] = s[(size_t)k * ldsrc + n0 + tx];
    }
    __syncthreads();
#pragma unroll
    for (int r = 0; r < 4; r++) {
        int n = n0 + ty + 8 * r, k = k0 + tx;
        float x = t[tx][ty + 8 * r];
        __nv_bfloat16 hi = __float2bfloat16(x);
        __nv_bfloat16 lo = __float2bfloat16(x - __bfloat162float(hi));
        size_t base = (size_t)n * 3 * K;
        o[base + k] = hi; o[base + K + k] = hi; o[base + 2 * K + k] = lo;
    }
}

// --------------------------------- RoPE ---------------------------------
__global__ void rope_kernel(float* x, int nh, int ld) {
    int idx = blockIdx.x * blockDim.x + threadIdx.x;
    if (idx >= S_ * nh * 64) return;
    int d = idx & 63;
    int rest = idx >> 6;
    int h = rest % nh;
    int s = rest / nh;
    float* base = x + (size_t)s * ld + h * 128;
    float x1 = base[d], x2 = base[d + 64];
    float inv = powf(10000.f, -(float)d * (1.f / 64.f));
    float ang = (float)s * inv;
    float c, sn;
    sincosf(ang, &sn, &c);
    base[d] = x1 * c - x2 * sn;
    base[d + 64] = x2 * c + x1 * sn;
}

// ------------------ pass-1: row sums of e -> invl1 ------------
__global__ __launch_bounds__(256) void rowsum1_kernel() {
    int h = blockIdx.y;
    int w = threadIdx.x >> 5, lane = threadIdx.x & 31;
    int i = blockIdx.x * 8 + w;
    const float* erow = g_e + (size_t)(h * S_ + i) * S_;
    float l = 0.f;
    for (int j = lane; j <= i; j += 32) l += erow[j];
#pragma unroll
    for (int off = 16; off > 0; off >>= 1)
        l += __shfl_xor_sync(0xFFFFFFFF, l, off);
    if (lane == 0) g_invl1[h * S_ + i] = 1.f / l;
}

// coalesced column sums: block-uniform row start (rows above the diagonal
// are exactly zero in g_e, so the extra terms are no-ops)
__global__ __launch_bounds__(256) void colsum_kernel() {
    int h = blockIdx.y;
    int j0 = blockIdx.x * 256;
    int j = j0 + threadIdx.x;
    const float* base = g_e + (size_t)h * S_ * S_;
    __shared__ float il[S_];
    for (int i = j0 + threadIdx.x; i < S_; i += 256)
        il[i] = g_invl1[h * S_ + i];
    __syncthreads();
    float a0 = 0.f, a1 = 0.f, a2 = 0.f, a3 = 0.f;
    for (int i = j0; i < S_; i += 4) {
        a0 += base[(size_t)(i    ) * S_ + j] * il[i];
        a1 += base[(size_t)(i + 1) * S_ + j] * il[i + 1];
        a2 += base[(size_t)(i + 2) * S_ + j] * il[i + 2];
        a3 += base[(size_t)(i + 3) * S_ + j] * il[i + 3];
    }
    g_colsum[h * S_ + j] = (a0 + a1) + (a2 + a3);
}

__global__ __launch_bounds__(256) void topk_kernel() {
    int h = blockIdx.x;
    int tid = threadIdx.x;
    __shared__ float vals[S_];
    __shared__ float bv[256];
    __shared__ int bi[256];
    __shared__ uint32_t bits[64];
    for (int j = tid; j < S_; j += 256) vals[j] = g_colsum[h * S_ + j];
    if (tid < 64) bits[tid] = 0;
    __syncthreads();
    for (int it = 0; it < HB_; it++) {
        float best = -INFINITY; int besti = 1 << 30;
        for (int j = tid; j < S_; j += 256) {
            float v = vals[j];
            if (v > best || (v == best && j < besti)) { best = v; besti = j; }
        }
        bv[tid] = best; bi[tid] = besti; __syncthreads();
        for (int off = 128; off > 0; off >>= 1) {
            if (tid < off) {
                if (bv[tid + off] > bv[tid] ||
                    (bv[tid + off] == bv[tid] && bi[tid + off] < bi[tid])) {
                    bv[tid] = bv[tid + off]; bi[tid] = bi[tid + off];
                }
            }
            __syncthreads();
        }
        if (tid == 0) {
            int b0 = bi[0];
            g_heavylist[h * HB_ + it] = b0;
            bits[b0 >> 5] |= (1u << (b0 & 31));
            vals[b0] = -INFINITY;
        }
        __syncthreads();
    }
    if (tid < 64) g_heavybits[h * 64 + tid] = bits[tid];
}

// ------ pass-2: invl2 = 1/sum(e over band + heavy) -- no exp, no writes to e -----
__global__ __launch_bounds__(256) void rowsum2_kernel() {
    int h = blockIdx.y;
    int tid = threadIdx.x;
    __shared__ int hl[HB_];
    for (int t = tid; t < HB_; t += 256) hl[t] = g_heavylist[h * HB_ + t];
    __syncthreads();

    int w = tid >> 5, lane = tid & 31;
    int i = blockIdx.x * 8 + w;
    const float* erow = g_e + (size_t)(h * S_ + i) * S_;
    int lo = i - RB_; if (lo < 0) lo = 0;

    float l = 0.f;
    for (int j = lo + lane; j <= i; j += 32) l += erow[j];
    for (int t = lane; t < HB_; t += 32) {
        int j = hl[t];
        if (j < lo) l += erow[j];
    }
#pragma unroll
    for (int off = 16; off > 0; off >>= 1)
        l += __shfl_xor_sync(0xFFFFFFFF, l, off);
    if (lane == 0) g_invl2[h * S_ + i] = 1.f / l;
}

// ------------------------------ launcher ---------------------------------
extern "C" void kernel_launch(void* const* d_in, const int* in_sizes, int n_in,
                              void* d_out, int out_size) {
    const float* hidden = (const float*)d_in[0];
    const float* Wq = (const float*)d_in[1];
    const float* Wk = (const float*)d_in[2];
    const float* Wv = (const float*)d_in[3];
    const float* Wo = (const float*)d_in[4];
    float* out = (float*)d_out;

    float *qkv, *e, *il2;
    uint32_t* hbits;
    __nv_bfloat16 *xhat, *wqkvt, *wot, *qhat, *khat, *vthat, *aohat;
    cudaGetSymbolAddress((void**)&qkv, g_qkv);
    cudaGetSymbolAddress((void**)&e, g_e);
    cudaGetSymbolAddress((void**)&il2, g_invl2);
    cudaGetSymbolAddress((void**)&hbits, g_heavybits);
    cudaGetSymbolAddress((void**)&xhat, g_xhat);
    cudaGetSymbolAddress((void**)&wqkvt, g_wqkvt);
    cudaGetSymbolAddress((void**)&wot, g_wot);
    cudaGetSymbolAddress((void**)&qhat, g_qhat);
    cudaGetSymbolAddress((void**)&khat, g_khat);
    cudaGetSymbolAddress((void**)&vthat, g_vthat);
    cudaGetSymbolAddress((void**)&aohat, g_aohat);

    const int SMEM_GEMM = 66560;
    const int SMEM_PV = 99328;
    cudaFuncSetAttribute(mma_gemm, cudaFuncAttributeMaxDynamicSharedMemorySize, SMEM_GEMM);
    cudaFuncSetAttribute(pv_mma, cudaFuncAttributeMaxDynamicSharedMemorySize, SMEM_PV);

    // 1. split inputs / weights to bf16 hi-lo (Wq|Wk|Wv concatenated transposed)
    split_plain<<<(S_ * HID_ + 255) / 256, 256>>>(hidden, xhat, S_, HID_);
    transpose_split<<<dim3(HID_ / 32, HID_ / 32, 1), dim3(32, 8)>>>(Wq, HID_, HID_, HID_, wqkvt);
    transpose_split<<<dim3((NKV_ * D_) / 32, HID_ / 32, 1), dim3(32, 8)>>>(
        Wk, NKV_ * D_, HID_, NKV_ * D_, wqkvt + (size_t)HID_ * 3 * HID_);
    transpose_split<<<dim3((NKV_ * D_) / 32, HID_ / 32, 1), dim3(32, 8)>>>(
        Wv, NKV_ * D_, HID_, NKV_ * D_, wqkvt + (size_t)(HID_ + NKV_ * D_) * 3 * HID_);
    transpose_split<<<dim3(HID_ / 32, HID_ / 32, 1), dim3(32, 8)>>>(Wo, HID_, HID_, HID_, wot);

    // 2. fused QKV projection (one GEMM, N=3072)
    mma_gemm<<<dim3(QKVN_ / 128, S_ / 128, 1), 256, SMEM_GEMM>>>(
        xhat, 0, wqkvt, 0, 0, qkv, 0, QKVN_, 3 * HID_, 0);

    // 3. RoPE (in place inside g_qkv)
    rope_kernel<<<(S_ * NH_ * 64 + 255) / 256, 256>>>(qkv, NH_, QKVN_);
    rope_kernel<<<(S_ * NKV_ * 64 + 255) / 256, 256>>>(qkv + HID_, NKV_, QKVN_);

    // 4. split roped Q/K, transpose-split V
    split_heads<<<(S_ * NH_ * D_ + 255) / 256, 256>>>(qkv, QKVN_, qhat, NH_, 0);
    split_heads<<<(S_ * NKV_ * D_ + 255) / 256, 256>>>(qkv + HID_, QKVN_, khat, NKV_, 1);
    transpose_split<<<dim3(D_ / 32, S_ / 32, NKV_), dim3(32, 8)>>>(
        qkv + HID_ + NKV_ * D_, QKVN_, S_, D_, vthat);

    // 5. e = exp(scale * QK^T) directly (lower triangle; zeros above diag)
    mma_gemm<<<dim3(S_ / 128, S_ / 128, NH_), 256, SMEM_GEMM>>>(
        qhat, (size_t)S_ * 3 * D_, khat, (size_t)S_ * 3 * D_, 2,
        e, (size_t)S_ * S_, S_, 3 * D_, 2);

    // 6. H2O: invl1, colsum (coalesced), topk (emits heavy bitmask)
    rowsum1_kernel<<<dim3(S_ / 8, NH_), 256>>>();
    colsum_kernel<<<dim3(S_ / 256, NH_), 256>>>();
    topk_kernel<<<NH_, 256>>>();

    // 7. invl2 (sum-only; e untouched)
    rowsum2_kernel<<<dim3(S_ / 8, NH_), 256>>>();

    // 8. fused masked PV -> aohat (split, pattern A)
    pv_mma<<<dim3(S_ / 128, NH_), 256, SMEM_PV>>>(vthat, e, il2, hbits, aohat);

    // 9. output projection
    mma_gemm<<<dim3(HID_ / 128, S_ / 128, 1), 256, SMEM_GEMM>>>(
        aohat, 0, wot, 0, 0, out, 0, HID_, 3 * HID_, 0);
}

// round 9
// speedup vs baseline: 2.8864x; 1.1248x over previous
#include <cuda_runtime.h>
#include <cuda_bf16.h>
#include <math.h>
#include <stdint.h>

#define S_    2048
#define HID_  2048
#define NH_   16
#define NKV_  4
#define D_    128
#define HB_   204
#define RB_   204
#define SCALE_ 0.08838834764831845f
#define L2E_  1.4426950408889634f
#define QKVN_ 3072

// ----------------------------- scratch ---------------------------------
__device__ float g_qkv[S_ * QKVN_];                 // [s][ q(2048) | k(512) | v(512) ]
__device__ float g_e[(size_t)NH_ * S_ * S_];        // exp(score); zero above diagonal
__device__ float g_rowsum[NH_ * S_];
__device__ float g_invl1[NH_ * S_], g_invl2[NH_ * S_];
__device__ float g_colsum[NH_ * S_];
__device__ int   g_heavylist[NH_ * HB_];
__device__ uint32_t g_heavybits[NH_ * 64];

__device__ __nv_bfloat16 g_xhat[(size_t)S_ * 3 * HID_];          // A-pattern [hi|lo|hi]
__device__ __nv_bfloat16 g_wqkvt[(size_t)QKVN_ * 3 * HID_];      // B-pattern [hi|hi|lo] (Wq|Wk|Wv)^T
__device__ __nv_bfloat16 g_wot[(size_t)HID_ * 3 * HID_];
__device__ __nv_bfloat16 g_qhat[(size_t)NH_ * S_ * 3 * D_];      // A-pattern
__device__ __nv_bfloat16 g_khat[(size_t)NKV_ * S_ * 3 * D_];     // B-pattern
__device__ __nv_bfloat16 g_vthat[(size_t)NKV_ * D_ * 3 * S_];    // B-pattern (V^T)
__device__ __nv_bfloat16 g_aohat[(size_t)S_ * 3 * HID_];         // A-pattern

// ----------------------------- PTX helpers ------------------------------
__device__ __forceinline__ uint32_t smem_u32(const void* p) {
    uint32_t a;
    asm("{ .reg .u64 t; cvta.to.shared.u64 t, %1; cvt.u32.u64 %0, t; }" : "=r"(a) : "l"(p));
    return a;
}
__device__ __forceinline__ void cp16(uint32_t saddr, const void* gptr) {
    asm volatile("cp.async.cg.shared.global [%0], [%1], 16;" :: "r"(saddr), "l"(gptr));
}
__device__ __forceinline__ void cp_commit() { asm volatile("cp.async.commit_group;"); }
__device__ __forceinline__ void cp_wait0() { asm volatile("cp.async.wait_group 0;" ::: "memory"); }
__device__ __forceinline__ void cp_wait1() { asm volatile("cp.async.wait_group 1;" ::: "memory"); }

__device__ __forceinline__ void ldsm4(uint32_t& r0, uint32_t& r1, uint32_t& r2, uint32_t& r3,
                                      uint32_t addr) {
    asm volatile("ldmatrix.sync.aligned.m8n8.x4.shared.b16 {%0,%1,%2,%3}, [%4];"
                 : "=r"(r0), "=r"(r1), "=r"(r2), "=r"(r3) : "r"(addr));
}
__device__ __forceinline__ void mma16816(float* d, const uint32_t* a, const uint32_t* b) {
    asm volatile(
        "mma.sync.aligned.m16n8k16.row.col.f32.bf16.bf16.f32 "
        "{%0,%1,%2,%3}, {%4,%5,%6,%7}, {%8,%9}, {%0,%1,%2,%3};"
        : "+f"(d[0]), "+f"(d[1]), "+f"(d[2]), "+f"(d[3])
        : "r"(a[0]), "r"(a[1]), "r"(a[2]), "r"(a[3]), "r"(b[0]), "r"(b[1]));
}
__device__ __forceinline__ float fexp(float x) {   // e^x via MUFU
    float y;
    asm("ex2.approx.ftz.f32 %0, %1;" : "=f"(y) : "f"(x * L2E_));
    return y;
}
__device__ __forceinline__ float fexp2p(float x) { // 2^x via FMA pipe
    float n = rintf(x);
    float f = x - n;
    float p = 1.3333558e-3f;
    p = fmaf(p, f, 9.6181291e-3f);
    p = fmaf(p, f, 5.5504110e-2f);
    p = fmaf(p, f, 2.4022651e-1f);
    p = fmaf(p, f, 6.9314718e-1f);
    p = fmaf(p, f, 1.0f);
    return p * __int_as_float(((int)n + 127) << 23);
}
__device__ __forceinline__ uint32_t split_pack(float p0, float p1, uint32_t& lo) {
    __nv_bfloat16 h0 = __float2bfloat16(p0), h1 = __float2bfloat16(p1);
    float f0 = __bfloat162float(h0), f1 = __bfloat162float(h1);
    __nv_bfloat16 l0 = __float2bfloat16(p0 - f0), l1 = __float2bfloat16(p1 - f1);
    lo = (uint32_t)__bfloat16_as_ushort(l0) | ((uint32_t)__bfloat16_as_ushort(l1) << 16);
    return (uint32_t)__bfloat16_as_ushort(h0) | ((uint32_t)__bfloat16_as_ushort(h1) << 16);
}

// ------------------------- HMMA GEMM -------------------------
__device__ __forceinline__ void load_tile_async(uint32_t sbase, const __nv_bfloat16* src,
                                                int ld, int row0, int kbase, int tid) {
#pragma unroll
    for (int t = 0; t < 4; t++) {
        int u = tid + t * 256;
        int row = u >> 3, seg = u & 7;
        uint32_t bo = (uint32_t)(row * 128 + seg * 16);
        bo ^= (bo >> 3) & 0x70;
        cp16(sbase + bo, src + (size_t)(row0 + row) * ld + kbase + seg * 8);
    }
}

// mode 0: plain fp32 store.
// mode 2: store e = exp(scale*s) for j<=i (0 above), hybrid MUFU/poly exp,
//         and accumulate per-row sums into rowsum[z*S + i] via atomics.
__global__ __launch_bounds__(256, 2) void mma_gemm(
    const __nv_bfloat16* __restrict__ A, size_t aStrideZ,
    const __nv_bfloat16* __restrict__ Bt, size_t bStrideZ, int bShift,
    float* __restrict__ C, size_t cStrideZ, int ldc,
    int Kp, int mode, float* __restrict__ rowsum) {
    int z = blockIdx.z;
    int i0 = blockIdx.y * 128, j0 = blockIdx.x * 128;
    if (mode == 2 && j0 > i0 + 127) return;   // fully above diagonal: skip

    const __nv_bfloat16* Az = A + (size_t)z * aStrideZ;
    const __nv_bfloat16* Bz = Bt + (size_t)(z >> bShift) * bStrideZ;
    float* Cz = C + (size_t)z * cStrideZ;
    int tid = threadIdx.x, wid = tid >> 5;
    uint32_t lane = tid & 31;

    extern __shared__ char dsm[];
    char* tile = (char*)(((uintptr_t)dsm + 1023) & ~(uintptr_t)1023);
    uint32_t sA[2] = { smem_u32(tile), smem_u32(tile) + 16384 };
    uint32_t sB[2] = { smem_u32(tile) + 32768, smem_u32(tile) + 49152 };

    int warp_m = wid >> 2;
    int warp_n = wid & 3;

    float acc[4][4][4];
#pragma unroll
    for (int i = 0; i < 4; i++)
#pragma unroll
        for (int j = 0; j < 4; j++)
#pragma unroll
            for (int r = 0; r < 4; r++) acc[i][j][r] = 0.f;

    load_tile_async(sA[0], Az, Kp, i0, 0, tid);
    load_tile_async(sB[0], Bz, Kp, j0, 0, tid);
    cp_commit();

    const int NC = Kp >> 6;
    for (int c = 0; c < NC; c++) {
        if (c + 1 < NC) {
            load_tile_async(sA[(c + 1) & 1], Az, Kp, i0, (c + 1) * 64, tid);
            load_tile_async(sB[(c + 1) & 1], Bz, Kp, j0, (c + 1) * 64, tid);
            cp_commit();
            cp_wait1();
        } else {
            cp_wait0();
        }
        __syncthreads();

        uint32_t a_base = sA[c & 1], b_base = sB[c & 1];
#pragma unroll
        for (int ks = 0; ks < 4; ks++) {
            uint32_t a[4][4], b[2][4];
#pragma unroll
            for (int mf = 0; mf < 4; mf++) {
                int row = 64 * warp_m + 16 * mf + (lane & 7) + (((lane >> 3) & 1) << 3);
                int colb = (16 * ks + (((lane >> 4) & 1) << 3)) * 2;
                uint32_t off = (uint32_t)(row * 128 + colb);
                off ^= (off >> 3) & 0x70;
                ldsm4(a[mf][0], a[mf][1], a[mf][2], a[mf][3], a_base + off);
            }
#pragma unroll
            for (int nf2 = 0; nf2 < 2; nf2++) {
                int row = 32 * warp_n + 16 * nf2 + (lane & 7) + (((lane >> 4) & 1) << 3);
                int colb = (16 * ks + (((lane >> 3) & 1) << 3)) * 2;
                uint32_t off = (uint32_t)(row * 128 + colb);
                off ^= (off >> 3) & 0x70;
                ldsm4(b[nf2][0], b[nf2][1], b[nf2][2], b[nf2][3], b_base + off);
            }
#pragma unroll
            for (int mf = 0; mf < 4; mf++)
#pragma unroll
                for (int nf = 0; nf < 4; nf++)
                    mma16816(acc[mf][nf], a[mf], &b[nf >> 1][(nf & 1) * 2]);
        }
        __syncthreads();
    }

    float rs0[4], rs1[4];
#pragma unroll
    for (int mf = 0; mf < 4; mf++) {
        int r0 = i0 + 64 * warp_m + 16 * mf + (int)(lane >> 2);
        float s0 = 0.f, s1 = 0.f;
#pragma unroll
        for (int nf = 0; nf < 4; nf++) {
            int c0 = j0 + 32 * warp_n + 8 * nf + (int)(lane & 3) * 2;
            float d0 = acc[mf][nf][0], d1 = acc[mf][nf][1];
            float d2 = acc[mf][nf][2], d3 = acc[mf][nf][3];
            if (mode == 2) {
                if (nf < 2) {   // MUFU half
                    d0 = (c0     <= r0)     ? fexp(d0 * SCALE_) : 0.f;
                    d1 = (c0 + 1 <= r0)     ? fexp(d1 * SCALE_) : 0.f;
                    d2 = (c0     <= r0 + 8) ? fexp(d2 * SCALE_) : 0.f;
                    d3 = (c0 + 1 <= r0 + 8) ? fexp(d3 * SCALE_) : 0.f;
                } else {        // FMA-pipe poly half
                    const float cl = SCALE_ * L2E_;
                    d0 = (c0     <= r0)     ? fexp2p(d0 * cl) : 0.f;
                    d1 = (c0 + 1 <= r0)     ? fexp2p(d1 * cl) : 0.f;
                    d2 = (c0     <= r0 + 8) ? fexp2p(d2 * cl) : 0.f;
                    d3 = (c0 + 1 <= r0 + 8) ? fexp2p(d3 * cl) : 0.f;
                }
                s0 += d0 + d1;
                s1 += d2 + d3;
            }
            *(float2*)(Cz + (size_t)r0 * ldc + c0) = make_float2(d0, d1);
            *(float2*)(Cz + (size_t)(r0 + 8) * ldc + c0) = make_float2(d2, d3);
        }
        rs0[mf] = s0; rs1[mf] = s1;
    }
    if (mode == 2) {
        float* rz = rowsum + (size_t)z * S_;
#pragma unroll
        for (int mf = 0; mf < 4; mf++) {
            float v0 = rs0[mf], v1 = rs1[mf];
            v0 += __shfl_xor_sync(0xFFFFFFFF, v0, 1);
            v0 += __shfl_xor_sync(0xFFFFFFFF, v0, 2);
            v1 += __shfl_xor_sync(0xFFFFFFFF, v1, 1);
            v1 += __shfl_xor_sync(0xFFFFFFFF, v1, 2);
            if ((lane & 3) == 0) {
                int r0 = i0 + 64 * warp_m + 16 * mf + (int)(lane >> 2);
                atomicAdd(rz + r0, v0);
                atomicAdd(rz + r0 + 8, v1);
            }
        }
    }
}

// ------------------------ fused PV (masked P on the fly) ------------------------
__global__ __launch_bounds__(256) void pv_mma(
    const __nv_bfloat16* __restrict__ vthat,
    const float* __restrict__ e, const float* __restrict__ invl2,
    const uint32_t* __restrict__ heavybits,
    __nv_bfloat16* __restrict__ aohat) {
    int i0 = blockIdx.x * 128, h = blockIdx.y, kh = h >> 2;
    int tid = threadIdx.x, wid = tid >> 5;
    uint32_t lane = tid & 31;
    int warp_m = wid >> 2, warp_n = wid & 3;

    extern __shared__ char dsm[];
    char* tile = (char*)(((uintptr_t)dsm + 1023) & ~(uintptr_t)1023);
    char* pPhi = tile;
    char* pPlo = tile + 16384;
    uint32_t sPhi = smem_u32(pPhi), sPlo = smem_u32(pPlo);
    uint32_t sVh[2] = { smem_u32(tile) + 32768, smem_u32(tile) + 49152 };
    uint32_t sVl[2] = { smem_u32(tile) + 65536, smem_u32(tile) + 81920 };

    __shared__ uint32_t sbits[64];
    if (tid < 64) sbits[tid] = heavybits[h * 64 + tid];

    int r = tid >> 1, half = tid & 1;
    int gi = i0 + r;
    float il = invl2[h * S_ + gi];
    const float* erow = e + ((size_t)h * S_ + gi) * S_ + half * 32;
    const __nv_bfloat16* Vz = vthat + (size_t)kh * D_ * 3 * S_;

    float acc[4][4][4];
#pragma unroll
    for (int i = 0; i < 4; i++)
#pragma unroll
        for (int j = 0; j < 4; j++)
#pragma unroll
            for (int q = 0; q < 4; q++) acc[i][j][q] = 0.f;

    const int NCH = (i0 >> 6) + 2;
    load_tile_async(sVh[0], Vz, 3 * S_, 0, 0, tid);
    load_tile_async(sVl[0], Vz, 3 * S_, 0, 2 * S_ + 0, tid);
    cp_commit();
    __syncthreads();   // sbits visible

    for (int c = 0; c < NCH; c++) {
        int j0 = c * 64;
        bool pre = (c + 1 < NCH);
        if (pre) {
            load_tile_async(sVh[(c + 1) & 1], Vz, 3 * S_, 0, (c + 1) * 64, tid);
            load_tile_async(sVl[(c + 1) & 1], Vz, 3 * S_, 0, 2 * S_ + (c + 1) * 64, tid);
            cp_commit();
        }
        uint32_t hib[16], lob[16];
        const float* ep = erow + j0;
        int gjb = j0 + half * 32;
#pragma unroll
        for (int q = 0; q < 8; q++) {
            float4 e4 = *(const float4*)(ep + q * 4);
            float pv[4] = { e4.x, e4.y, e4.z, e4.w };
#pragma unroll
            for (int u = 0; u < 4; u++) {
                int gj = gjb + q * 4 + u;
                bool keep = (gj <= gi) &&
                            ((gi - gj <= RB_) || ((sbits[gj >> 5] >> (gj & 31)) & 1u));
                pv[u] = keep ? pv[u] * il : 0.f;
            }
            hib[q * 2]     = split_pack(pv[0], pv[1], lob[q * 2]);
            hib[q * 2 + 1] = split_pack(pv[2], pv[3], lob[q * 2 + 1]);
        }
#pragma unroll
        for (int sg = 0; sg < 4; sg++) {
            uint32_t bo = (uint32_t)(r * 128 + half * 64 + sg * 16);
            bo ^= (bo >> 3) & 0x70;
            *(uint4*)(pPhi + bo) = make_uint4(hib[sg * 4], hib[sg * 4 + 1], hib[sg * 4 + 2], hib[sg * 4 + 3]);
            *(uint4*)(pPlo + bo) = make_uint4(lob[sg * 4], lob[sg * 4 + 1], lob[sg * 4 + 2], lob[sg * 4 + 3]);
        }
        if (pre) cp_wait1(); else cp_wait0();
        __syncthreads();

        uint32_t abases[3] = { sPhi, sPlo, sPhi };
        uint32_t bbases[3] = { sVh[c & 1], sVh[c & 1], sVl[c & 1] };
#pragma unroll
        for (int t = 0; t < 3; t++) {
            uint32_t a_base = abases[t], b_base = bbases[t];
#pragma unroll
            for (int ks = 0; ks < 4; ks++) {
                uint32_t a[4][4], b[2][4];
#pragma unroll
                for (int mf = 0; mf < 4; mf++) {
                    int row = 64 * warp_m + 16 * mf + (lane & 7) + (((lane >> 3) & 1) << 3);
                    int colb = (16 * ks + (((lane >> 4) & 1) << 3)) * 2;
                    uint32_t off = (uint32_t)(row * 128 + colb);
                    off ^= (off >> 3) & 0x70;
                    ldsm4(a[mf][0], a[mf][1], a[mf][2], a[mf][3], a_base + off);
                }
#pragma unroll
                for (int nf2 = 0; nf2 < 2; nf2++) {
                    int row = 32 * warp_n + 16 * nf2 + (lane & 7) + (((lane >> 4) & 1) << 3);
                    int colb = (16 * ks + (((lane >> 3) & 1) << 3)) * 2;
                    uint32_t off = (uint32_t)(row * 128 + colb);
                    off ^= (off >> 3) & 0x70;
                    ldsm4(b[nf2][0], b[nf2][1], b[nf2][2], b[nf2][3], b_base + off);
                }
#pragma unroll
                for (int mf = 0; mf < 4; mf++)
#pragma unroll
                    for (int nf = 0; nf < 4; nf++)
                        mma16816(acc[mf][nf], a[mf], &b[nf >> 1][(nf & 1) * 2]);
            }
        }
        __syncthreads();
    }

#pragma unroll
    for (int mf = 0; mf < 4; mf++) {
        int r0 = i0 + 64 * warp_m + 16 * mf + (int)(lane >> 2);
#pragma unroll
        for (int nf = 0; nf < 4; nf++) {
            int c0 = 32 * warp_n + 8 * nf + (int)(lane & 3) * 2;
#pragma unroll
            for (int rr = 0; rr < 2; rr++) {
                float d0 = acc[mf][nf][rr * 2], d1 = acc[mf][nf][rr * 2 + 1];
                uint32_t lo, hi = split_pack(d0, d1, lo);
                size_t b0 = (size_t)(r0 + rr * 8) * (3 * HID_) + h * D_ + c0;
                *(uint32_t*)(aohat + b0) = hi;
                *(uint32_t*)(aohat + b0 + HID_) = lo;
                *(uint32_t*)(aohat + b0 + 2 * HID_) = hi;
            }
        }
    }
}

// ----------------------- split-bf16 conversion kernels -------------------
__global__ void split_plain(const float* __restrict__ A, __nv_bfloat16* __restrict__ out,
                            int M, int K) {  // pattern A
    int idx = blockIdx.x * blockDim.x + threadIdx.x;
    if (idx >= M * K) return;
    int m = idx / K, k = idx - m * K;
    float x = A[idx];
    __nv_bfloat16 hi = __float2bfloat16(x);
    __nv_bfloat16 lo = __float2bfloat16(x - __bfloat162float(hi));
    size_t base = (size_t)m * 3 * K;
    out[base + k] = hi; out[base + K + k] = lo; out[base + 2 * K + k] = hi;
}

__global__ void split_heads(const float* __restrict__ src, int ld,
                            __nv_bfloat16* __restrict__ out, int nh, int patternB) {
    int idx = blockIdx.x * blockDim.x + threadIdx.x;
    if (idx >= S_ * nh * D_) return;
    int d = idx & 127;
    int h = (idx >> 7) % nh;
    int s = idx / (nh * D_);
    float x = src[(size_t)s * ld + h * D_ + d];
    __nv_bfloat16 hi = __float2bfloat16(x);
    __nv_bfloat16 lo = __float2bfloat16(x - __bfloat162float(hi));
    size_t base = ((size_t)h * S_ + s) * (3 * D_);
    if (patternB) { out[base + d] = hi; out[base + D_ + d] = hi; out[base + 2 * D_ + d] = lo; }
    else          { out[base + d] = hi; out[base + D_ + d] = lo; out[base + 2 * D_ + d] = hi; }
}

__global__ void transpose_split(const float* __restrict__ src, int ldsrc, int K, int Nper,
                                __nv_bfloat16* __restrict__ out) {  // pattern B
    int z = blockIdx.z;
    const float* s = src + (size_t)z * Nper;
    __nv_bfloat16* o = out + (size_t)z * Nper * 3 * K;
    __shared__ float t[32][33];
    int k0 = blockIdx.y * 32, n0 = blockIdx.x * 32;
    int tx = threadIdx.x, ty = threadIdx.y;
#pragma unroll
    for (int r = 0; r < 4; r++) {
        int k = k0 + ty + 8 * r;
        t[ty + 8 * r][tx] = s[(size_t)k * ldsrc + n0 + tx];
    }
    __syncthreads();
#pragma unroll
    for (int r = 0; r < 4; r++) {
        int n = n0 + ty + 8 * r, k = k0 + tx;
        float x = t[tx][ty + 8 * r];
        __nv_bfloat16 hi = __float2bfloat16(x);
        __nv_bfloat16 lo = __float2bfloat16(x - __bfloat162float(hi));
        size_t base = (size_t)n * 3 * K;
        o[base + k] = hi; o[base + K + k] = hi; o[base + 2 * K + k] = lo;
    }
}

// --------------------------------- RoPE ---------------------------------
__global__ void rope_kernel(float* x, int nh, int ld) {
    int idx = blockIdx.x * blockDim.x + threadIdx.x;
    if (idx >= S_ * nh * 64) return;
    int d = idx & 63;
    int rest = idx >> 6;
    int h = rest % nh;
    int s = rest / nh;
    float* base = x + (size_t)s * ld + h * 128;
    float x1 = base[d], x2 = base[d + 64];
    float inv = powf(10000.f, -(float)d * (1.f / 64.f));
    float ang = (float)s * inv;
    float c, sn;
    sincosf(ang, &sn, &c);
    base[d] = x1 * c - x2 * sn;
    base[d + 64] = x2 * c + x1 * sn;
}

// ------------------ invl1 = 1 / rowsum -----------------------------------
__global__ void invl_kernel(const float* __restrict__ rs, float* __restrict__ il) {
    int i = blockIdx.x * 256 + threadIdx.x;
    il[i] = 1.f / rs[i];
}

// coalesced column sums (rows above diagonal are exactly zero in g_e)
__global__ __launch_bounds__(256) void colsum_kernel() {
    int h = blockIdx.y;
    int j0 = blockIdx.x * 256;
    int j = j0 + threadIdx.x;
    const float* base = g_e + (size_t)h * S_ * S_;
    __shared__ float il[S_];
    for (int i = j0 + threadIdx.x; i < S_; i += 256)
        il[i] = g_invl1[h * S_ + i];
    __syncthreads();
    float a0 = 0.f, a1 = 0.f, a2 = 0.f, a3 = 0.f;
    for (int i = j0; i < S_; i += 4) {
        a0 += base[(size_t)(i    ) * S_ + j] * il[i];
        a1 += base[(size_t)(i + 1) * S_ + j] * il[i + 1];
        a2 += base[(size_t)(i + 2) * S_ + j] * il[i + 2];
        a3 += base[(size_t)(i + 3) * S_ + j] * il[i + 3];
    }
    g_colsum[h * S_ + j] = (a0 + a1) + (a2 + a3);
}

__global__ __launch_bounds__(256) void topk_kernel() {
    int h = blockIdx.x;
    int tid = threadIdx.x;
    int lane = tid & 31, w = tid >> 5;
    __shared__ float vals[S_];
    __shared__ float wbv[8];
    __shared__ int wbi[8];
    __shared__ uint32_t bits[64];
    for (int j = tid; j < S_; j += 256) vals[j] = g_colsum[h * S_ + j];
    if (tid < 64) bits[tid] = 0;
    __syncthreads();
    for (int it = 0; it < HB_; it++) {
        float best = -INFINITY; int besti = 1 << 30;
        for (int j = tid; j < S_; j += 256) {
            float v = vals[j];
            if (v > best || (v == best && j < besti)) { best = v; besti = j; }
        }
#pragma unroll
        for (int off = 16; off > 0; off >>= 1) {
            float ov = __shfl_xor_sync(0xFFFFFFFF, best, off);
            int oi = __shfl_xor_sync(0xFFFFFFFF, besti, off);
            if (ov > best || (ov == best && oi < besti)) { best = ov; besti = oi; }
        }
        if (lane == 0) { wbv[w] = best; wbi[w] = besti; }
        __syncthreads();
        if (tid == 0) {
            float b = wbv[0]; int bi2 = wbi[0];
#pragma unroll
            for (int q = 1; q < 8; q++)
                if (wbv[q] > b || (wbv[q] == b && wbi[q] < bi2)) { b = wbv[q]; bi2 = wbi[q]; }
            g_heavylist[h * HB_ + it] = bi2;
            bits[bi2 >> 5] |= (1u << (bi2 & 31));
            vals[bi2] = -INFINITY;
        }
        __syncthreads();
    }
    if (tid < 64) g_heavybits[h * 64 + tid] = bits[tid];
}

// ------ pass-2: invl2 = 1/sum(e over band + heavy) ------
__global__ __launch_bounds__(256) void rowsum2_kernel() {
    int h = blockIdx.y;
    int tid = threadIdx.x;
    __shared__ int hl[HB_];
    for (int t = tid; t < HB_; t += 256) hl[t] = g_heavylist[h * HB_ + t];
    __syncthreads();

    int w = tid >> 5, lane = tid & 31;
    int i = blockIdx.x * 8 + w;
    const float* erow = g_e + (size_t)(h * S_ + i) * S_;
    int lo = i - RB_; if (lo < 0) lo = 0;

    float l = 0.f;
    for (int j = lo + lane; j <= i; j += 32) l += erow[j];
    for (int t = lane; t < HB_; t += 32) {
        int j = hl[t];
        if (j < lo) l += erow[j];
    }
#pragma unroll
    for (int off = 16; off > 0; off >>= 1)
        l += __shfl_xor_sync(0xFFFFFFFF, l, off);
    if (lane == 0) g_invl2[h * S_ + i] = 1.f / l;
}

// ------------------------------ launcher ---------------------------------
extern "C" void kernel_launch(void* const* d_in, const int* in_sizes, int n_in,
                              void* d_out, int out_size) {
    const float* hidden = (const float*)d_in[0];
    const float* Wq = (const float*)d_in[1];
    const float* Wk = (const float*)d_in[2];
    const float* Wv = (const float*)d_in[3];
    const float* Wo = (const float*)d_in[4];
    float* out = (float*)d_out;

    float *qkv, *e, *rsum, *il1, *il2;
    uint32_t* hbits;
    __nv_bfloat16 *xhat, *wqkvt, *wot, *qhat, *khat, *vthat, *aohat;
    cudaGetSymbolAddress((void**)&qkv, g_qkv);
    cudaGetSymbolAddress((void**)&e, g_e);
    cudaGetSymbolAddress((void**)&rsum, g_rowsum);
    cudaGetSymbolAddress((void**)&il1, g_invl1);
    cudaGetSymbolAddress((void**)&il2, g_invl2);
    cudaGetSymbolAddress((void**)&hbits, g_heavybits);
    cudaGetSymbolAddress((void**)&xhat, g_xhat);
    cudaGetSymbolAddress((void**)&wqkvt, g_wqkvt);
    cudaGetSymbolAddress((void**)&wot, g_wot);
    cudaGetSymbolAddress((void**)&qhat, g_qhat);
    cudaGetSymbolAddress((void**)&khat, g_khat);
    cudaGetSymbolAddress((void**)&vthat, g_vthat);
    cudaGetSymbolAddress((void**)&aohat, g_aohat);

    const int SMEM_GEMM = 66560;
    const int SMEM_PV = 99328;
    cudaFuncSetAttribute(mma_gemm, cudaFuncAttributeMaxDynamicSharedMemorySize, SMEM_GEMM);
    cudaFuncSetAttribute(pv_mma, cudaFuncAttributeMaxDynamicSharedMemorySize, SMEM_PV);

    // 1-4: splits needed for QKV; QKV mma is the 5th launch (ncu capture slot)
    split_plain<<<(S_ * HID_ + 255) / 256, 256>>>(hidden, xhat, S_, HID_);
    transpose_split<<<dim3(HID_ / 32, HID_ / 32, 1), dim3(32, 8)>>>(Wq, HID_, HID_, HID_, wqkvt);
    transpose_split<<<dim3((NKV_ * D_) / 32, HID_ / 32, 1), dim3(32, 8)>>>(
        Wk, NKV_ * D_, HID_, NKV_ * D_, wqkvt + (size_t)HID_ * 3 * HID_);
    transpose_split<<<dim3((NKV_ * D_) / 32, HID_ / 32, 1), dim3(32, 8)>>>(
        Wv, NKV_ * D_, HID_, NKV_ * D_, wqkvt + (size_t)(HID_ + NKV_ * D_) * 3 * HID_);

    // 5. fused QKV projection (one GEMM, N=3072)
    mma_gemm<<<dim3(QKVN_ / 128, S_ / 128, 1), 256, SMEM_GEMM>>>(
        xhat, 0, wqkvt, 0, 0, qkv, 0, QKVN_, 3 * HID_, 0, nullptr);

    transpose_split<<<dim3(HID_ / 32, HID_ / 32, 1), dim3(32, 8)>>>(Wo, HID_, HID_, HID_, wot);

    // RoPE (in place inside g_qkv)
    rope_kernel<<<(S_ * NH_ * 64 + 255) / 256, 256>>>(qkv, NH_, QKVN_);
    rope_kernel<<<(S_ * NKV_ * 64 + 255) / 256, 256>>>(qkv + HID_, NKV_, QKVN_);

    // split roped Q/K, transpose-split V
    split_heads<<<(S_ * NH_ * D_ + 255) / 256, 256>>>(qkv, QKVN_, qhat, NH_, 0);
    split_heads<<<(S_ * NKV_ * D_ + 255) / 256, 256>>>(qkv + HID_, QKVN_, khat, NKV_, 1);
    transpose_split<<<dim3(D_ / 32, S_ / 32, NKV_), dim3(32, 8)>>>(
        qkv + HID_ + NKV_ * D_, QKVN_, S_, D_, vthat);

    // zero rowsum accumulator (captured node, re-zeroed every replay)
    cudaMemsetAsync(rsum, 0, NH_ * S_ * sizeof(float));

    // e = exp(scale * QK^T) + fused row sums
    mma_gemm<<<dim3(S_ / 128, S_ / 128, NH_), 256, SMEM_GEMM>>>(
        qhat, (size_t)S_ * 3 * D_, khat, (size_t)S_ * 3 * D_, 2,
        e, (size_t)S_ * S_, S_, 3 * D_, 2, rsum);

    // H2O: invl1, colsum, topk (emits heavy bitmask)
    invl_kernel<<<NH_ * S_ / 256, 256>>>(rsum, il1);
    colsum_kernel<<<dim3(S_ / 256, NH_), 256>>>();
    topk_kernel<<<NH_, 256>>>();

    // invl2 (sum-only; e untouched)
    rowsum2_kernel<<<dim3(S_ / 8, NH_), 256>>>();

    // fused masked PV -> aohat (split, pattern A)
    pv_mma<<<dim3(S_ / 128, NH_), 256, SMEM_PV>>>(vthat, e, il2, hbits, aohat);

    // output projection
    mma_gemm<<<dim3(HID_ / 128, S_ / 128, 1), 256, SMEM_GEMM>>>(
        aohat, 0, wot, 0, 0, out, 0, HID_, 3 * HID_, 0, nullptr);
}

// round 10
// speedup vs baseline: 3.5131x; 1.2171x over previous
#include <cuda_runtime.h>
#include <cuda_fp16.h>
#include <math.h>
#include <stdint.h>

#define S_    2048
#define HID_  2048
#define NH_   16
#define NKV_  4
#define D_    128
#define HB_   204
#define RB_   204
#define SCALE_ 0.08838834764831845f
#define L2E_  1.4426950408889634f
#define QKVN_ 3072

// ----------------------------- scratch ---------------------------------
__device__ float g_qkv[S_ * QKVN_];                 // [s][ q(2048) | k(512) | v(512) ]
__device__ float g_e[(size_t)NH_ * S_ * S_];        // exp(score); zero above diagonal
__device__ float g_rowsum[NH_ * S_];
__device__ float g_invl1[NH_ * S_], g_invl2[NH_ * S_];
__device__ float g_colsum[NH_ * S_];
__device__ int   g_heavylist[NH_ * HB_];
__device__ uint32_t g_heavybits[NH_ * 64];

__device__ __half g_xhat[(size_t)S_ * 2 * HID_];          // A-pattern [hi|lo]
__device__ __half g_wqkvt[(size_t)QKVN_ * 2 * HID_];      // B-pattern [b|b] (Wq|Wk|Wv)^T
__device__ __half g_wot[(size_t)HID_ * 2 * HID_];
__device__ __half g_qhat[(size_t)NH_ * S_ * 2 * D_];      // A-pattern [hi|lo]
__device__ __half g_khat[(size_t)NKV_ * S_ * 2 * D_];     // B-pattern [k|k]
__device__ __half g_vthat[(size_t)NKV_ * D_ * S_];        // single fp16 (V^T)
__device__ __half g_aohat[(size_t)S_ * 2 * HID_];         // A-pattern [hi|lo]

// ----------------------------- PTX helpers ------------------------------
__device__ __forceinline__ uint32_t smem_u32(const void* p) {
    uint32_t a;
    asm("{ .reg .u64 t; cvta.to.shared.u64 t, %1; cvt.u32.u64 %0, t; }" : "=r"(a) : "l"(p));
    return a;
}
__device__ __forceinline__ void cp16(uint32_t saddr, const void* gptr) {
    asm volatile("cp.async.cg.shared.global [%0], [%1], 16;" :: "r"(saddr), "l"(gptr));
}
__device__ __forceinline__ void cp_commit() { asm volatile("cp.async.commit_group;"); }
__device__ __forceinline__ void cp_wait0() { asm volatile("cp.async.wait_group 0;" ::: "memory"); }
__device__ __forceinline__ void cp_wait1() { asm volatile("cp.async.wait_group 1;" ::: "memory"); }

__device__ __forceinline__ void ldsm4(uint32_t& r0, uint32_t& r1, uint32_t& r2, uint32_t& r3,
                                      uint32_t addr) {
    asm volatile("ldmatrix.sync.aligned.m8n8.x4.shared.b16 {%0,%1,%2,%3}, [%4];"
                 : "=r"(r0), "=r"(r1), "=r"(r2), "=r"(r3) : "r"(addr));
}
__device__ __forceinline__ void mma16816(float* d, const uint32_t* a, const uint32_t* b) {
    asm volatile(
        "mma.sync.aligned.m16n8k16.row.col.f32.f16.f16.f32 "
        "{%0,%1,%2,%3}, {%4,%5,%6,%7}, {%8,%9}, {%0,%1,%2,%3};"
        : "+f"(d[0]), "+f"(d[1]), "+f"(d[2]), "+f"(d[3])
        : "r"(a[0]), "r"(a[1]), "r"(a[2]), "r"(a[3]), "r"(b[0]), "r"(b[1]));
}
__device__ __forceinline__ float fexp(float x) {   // e^x via MUFU
    float y;
    asm("ex2.approx.ftz.f32 %0, %1;" : "=f"(y) : "f"(x * L2E_));
    return y;
}
__device__ __forceinline__ float fexp2p(float x) { // 2^x via FMA pipe
    float n = rintf(x);
    float f = x - n;
    float p = 1.3333558e-3f;
    p = fmaf(p, f, 9.6181291e-3f);
    p = fmaf(p, f, 5.5504110e-2f);
    p = fmaf(p, f, 2.4022651e-1f);
    p = fmaf(p, f, 6.9314718e-1f);
    p = fmaf(p, f, 1.0f);
    return p * __int_as_float(((int)n + 127) << 23);
}
__device__ __forceinline__ uint32_t split_packh(float p0, float p1, uint32_t& lo) {
    __half h0 = __float2half_rn(p0), h1 = __float2half_rn(p1);
    float f0 = __half2float(h0), f1 = __half2float(h1);
    __half l0 = __float2half_rn(p0 - f0), l1 = __float2half_rn(p1 - f1);
    lo = (uint32_t)__half_as_ushort(l0) | ((uint32_t)__half_as_ushort(l1) << 16);
    return (uint32_t)__half_as_ushort(h0) | ((uint32_t)__half_as_ushort(h1) << 16);
}

// ------------------------- HMMA GEMM -------------------------
__device__ __forceinline__ void load_tile_async(uint32_t sbase, const __half* src,
                                                int ld, int row0, int kbase, int tid) {
#pragma unroll
    for (int t = 0; t < 4; t++) {
        int u = tid + t * 256;
        int row = u >> 3, seg = u & 7;
        uint32_t bo = (uint32_t)(row * 128 + seg * 16);
        bo ^= (bo >> 3) & 0x70;
        cp16(sbase + bo, src + (size_t)(row0 + row) * ld + kbase + seg * 8);
    }
}

// mode 0: plain fp32 store.
// mode 2: e = exp(scale*s) for j<=i (0 above), hybrid MUFU/poly exp, fused row sums.
__global__ __launch_bounds__(256, 2) void mma_gemm(
    const __half* __restrict__ A, size_t aStrideZ,
    const __half* __restrict__ Bt, size_t bStrideZ, int bShift,
    float* __restrict__ C, size_t cStrideZ, int ldc,
    int Kp, int mode, float* __restrict__ rowsum) {
    int z = blockIdx.z;
    int i0 = blockIdx.y * 128, j0 = blockIdx.x * 128;
    if (mode == 2 && j0 > i0 + 127) return;   // fully above diagonal: skip

    const __half* Az = A + (size_t)z * aStrideZ;
    const __half* Bz = Bt + (size_t)(z >> bShift) * bStrideZ;
    float* Cz = C + (size_t)z * cStrideZ;
    int tid = threadIdx.x, wid = tid >> 5;
    uint32_t lane = tid & 31;

    extern __shared__ char dsm[];
    char* tile = (char*)(((uintptr_t)dsm + 1023) & ~(uintptr_t)1023);
    uint32_t sA[2] = { smem_u32(tile), smem_u32(tile) + 16384 };
    uint32_t sB[2] = { smem_u32(tile) + 32768, smem_u32(tile) + 49152 };

    int warp_m = wid >> 2;
    int warp_n = wid & 3;

    float acc[4][4][4];
#pragma unroll
    for (int i = 0; i < 4; i++)
#pragma unroll
        for (int j = 0; j < 4; j++)
#pragma unroll
            for (int r = 0; r < 4; r++) acc[i][j][r] = 0.f;

    load_tile_async(sA[0], Az, Kp, i0, 0, tid);
    load_tile_async(sB[0], Bz, Kp, j0, 0, tid);
    cp_commit();

    const int NC = Kp >> 6;
    for (int c = 0; c < NC; c++) {
        if (c + 1 < NC) {
            load_tile_async(sA[(c + 1) & 1], Az, Kp, i0, (c + 1) * 64, tid);
            load_tile_async(sB[(c + 1) & 1], Bz, Kp, j0, (c + 1) * 64, tid);
            cp_commit();
            cp_wait1();
        } else {
            cp_wait0();
        }
        __syncthreads();

        uint32_t a_base = sA[c & 1], b_base = sB[c & 1];
#pragma unroll
        for (int ks = 0; ks < 4; ks++) {
            uint32_t a[4][4], b[2][4];
#pragma unroll
            for (int mf = 0; mf < 4; mf++) {
                int row = 64 * warp_m + 16 * mf + (lane & 7) + (((lane >> 3) & 1) << 3);
                int colb = (16 * ks + (((lane >> 4) & 1) << 3)) * 2;
                uint32_t off = (uint32_t)(row * 128 + colb);
                off ^= (off >> 3) & 0x70;
                ldsm4(a[mf][0], a[mf][1], a[mf][2], a[mf][3], a_base + off);
            }
#pragma unroll
            for (int nf2 = 0; nf2 < 2; nf2++) {
                int row = 32 * warp_n + 16 * nf2 + (lane & 7) + (((lane >> 4) & 1) << 3);
                int colb = (16 * ks + (((lane >> 3) & 1) << 3)) * 2;
                uint32_t off = (uint32_t)(row * 128 + colb);
                off ^= (off >> 3) & 0x70;
                ldsm4(b[nf2][0], b[nf2][1], b[nf2][2], b[nf2][3], b_base + off);
            }
#pragma unroll
            for (int mf = 0; mf < 4; mf++)
#pragma unroll
                for (int nf = 0; nf < 4; nf++)
                    mma16816(acc[mf][nf], a[mf], &b[nf >> 1][(nf & 1) * 2]);
        }
        __syncthreads();
    }

    float rs0[4], rs1[4];
#pragma unroll
    for (int mf = 0; mf < 4; mf++) {
        int r0 = i0 + 64 * warp_m + 16 * mf + (int)(lane >> 2);
        float s0 = 0.f, s1 = 0.f;
#pragma unroll
        for (int nf = 0; nf < 4; nf++) {
            int c0 = j0 + 32 * warp_n + 8 * nf + (int)(lane & 3) * 2;
            float d0 = acc[mf][nf][0], d1 = acc[mf][nf][1];
            float d2 = acc[mf][nf][2], d3 = acc[mf][nf][3];
            if (mode == 2) {
                if (nf < 2) {   // MUFU half
                    d0 = (c0     <= r0)     ? fexp(d0 * SCALE_) : 0.f;
                    d1 = (c0 + 1 <= r0)     ? fexp(d1 * SCALE_) : 0.f;
                    d2 = (c0     <= r0 + 8) ? fexp(d2 * SCALE_) : 0.f;
                    d3 = (c0 + 1 <= r0 + 8) ? fexp(d3 * SCALE_) : 0.f;
                } else {        // FMA-pipe poly half
                    const float cl = SCALE_ * L2E_;
                    d0 = (c0     <= r0)     ? fexp2p(d0 * cl) : 0.f;
                    d1 = (c0 + 1 <= r0)     ? fexp2p(d1 * cl) : 0.f;
                    d2 = (c0     <= r0 + 8) ? fexp2p(d2 * cl) : 0.f;
                    d3 = (c0 + 1 <= r0 + 8) ? fexp2p(d3 * cl) : 0.f;
                }
                s0 += d0 + d1;
                s1 += d2 + d3;
            }
            *(float2*)(Cz + (size_t)r0 * ldc + c0) = make_float2(d0, d1);
            *(float2*)(Cz + (size_t)(r0 + 8) * ldc + c0) = make_float2(d2, d3);
        }
        rs0[mf] = s0; rs1[mf] = s1;
    }
    if (mode == 2) {
        float* rz = rowsum + (size_t)z * S_;
#pragma unroll
        for (int mf = 0; mf < 4; mf++) {
            float v0 = rs0[mf], v1 = rs1[mf];
            v0 += __shfl_xor_sync(0xFFFFFFFF, v0, 1);
            v0 += __shfl_xor_sync(0xFFFFFFFF, v0, 2);
            v1 += __shfl_xor_sync(0xFFFFFFFF, v1, 1);
            v1 += __shfl_xor_sync(0xFFFFFFFF, v1, 2);
            if ((lane & 3) == 0) {
                int r0 = i0 + 64 * warp_m + 16 * mf + (int)(lane >> 2);
                atomicAdd(rz + r0, v0);
                atomicAdd(rz + r0 + 8, v1);
            }
        }
    }
}

// ------------------------ fused PV (masked P on the fly, 2-pass fp16) --------------
__global__ __launch_bounds__(256) void pv_mma(
    const __half* __restrict__ vthat,
    const float* __restrict__ e, const float* __restrict__ invl2,
    const uint32_t* __restrict__ heavybits,
    __half* __restrict__ aohat) {
    int i0 = blockIdx.x * 128, h = blockIdx.y, kh = h >> 2;
    int tid = threadIdx.x, wid = tid >> 5;
    uint32_t lane = tid & 31;
    int warp_m = wid >> 2, warp_n = wid & 3;

    extern __shared__ char dsm[];
    char* tile = (char*)(((uintptr_t)dsm + 1023) & ~(uintptr_t)1023);
    char* pPhi = tile;
    char* pPlo = tile + 16384;
    uint32_t sPhi = smem_u32(pPhi), sPlo = smem_u32(pPlo);
    uint32_t sVh[2] = { smem_u32(tile) + 32768, smem_u32(tile) + 49152 };

    __shared__ uint32_t sbits[64];
    if (tid < 64) sbits[tid] = heavybits[h * 64 + tid];

    int r = tid >> 1, half = tid & 1;
    int gi = i0 + r;
    float il = invl2[h * S_ + gi];
    const float* erow = e + ((size_t)h * S_ + gi) * S_ + half * 32;
    const __half* Vz = vthat + (size_t)kh * D_ * S_;

    float acc[4][4][4];
#pragma unroll
    for (int i = 0; i < 4; i++)
#pragma unroll
        for (int j = 0; j < 4; j++)
#pragma unroll
            for (int q = 0; q < 4; q++) acc[i][j][q] = 0.f;

    const int NCH = (i0 >> 6) + 2;
    load_tile_async(sVh[0], Vz, S_, 0, 0, tid);
    cp_commit();
    __syncthreads();   // sbits visible

    for (int c = 0; c < NCH; c++) {
        int j0 = c * 64;
        bool pre = (c + 1 < NCH);
        if (pre) {
            load_tile_async(sVh[(c + 1) & 1], Vz, S_, 0, (c + 1) * 64, tid);
            cp_commit();
        }
        uint32_t hib[16], lob[16];
        const float* ep = erow + j0;
        int gjb = j0 + half * 32;
#pragma unroll
        for (int q = 0; q < 8; q++) {
            float4 e4 = *(const float4*)(ep + q * 4);
            float pv[4] = { e4.x, e4.y, e4.z, e4.w };
#pragma unroll
            for (int u = 0; u < 4; u++) {
                int gj = gjb + q * 4 + u;
                bool keep = (gj <= gi) &&
                            ((gi - gj <= RB_) || ((sbits[gj >> 5] >> (gj & 31)) & 1u));
                pv[u] = keep ? pv[u] * il : 0.f;
            }
            hib[q * 2]     = split_packh(pv[0], pv[1], lob[q * 2]);
            hib[q * 2 + 1] = split_packh(pv[2], pv[3], lob[q * 2 + 1]);
        }
#pragma unroll
        for (int sg = 0; sg < 4; sg++) {
            uint32_t bo = (uint32_t)(r * 128 + half * 64 + sg * 16);
            bo ^= (bo >> 3) & 0x70;
            *(uint4*)(pPhi + bo) = make_uint4(hib[sg * 4], hib[sg * 4 + 1], hib[sg * 4 + 2], hib[sg * 4 + 3]);
            *(uint4*)(pPlo + bo) = make_uint4(lob[sg * 4], lob[sg * 4 + 1], lob[sg * 4 + 2], lob[sg * 4 + 3]);
        }
        if (pre) cp_wait1(); else cp_wait0();
        __syncthreads();

        uint32_t abases[2] = { sPhi, sPlo };
#pragma unroll
        for (int t = 0; t < 2; t++) {
            uint32_t a_base = abases[t], b_base = sVh[c & 1];
#pragma unroll
            for (int ks = 0; ks < 4; ks++) {
                uint32_t a[4][4], b[2][4];
#pragma unroll
                for (int mf = 0; mf < 4; mf++) {
                    int row = 64 * warp_m + 16 * mf + (lane & 7) + (((lane >> 3) & 1) << 3);
                    int colb = (16 * ks + (((lane >> 4) & 1) << 3)) * 2;
                    uint32_t off = (uint32_t)(row * 128 + colb);
                    off ^= (off >> 3) & 0x70;
                    ldsm4(a[mf][0], a[mf][1], a[mf][2], a[mf][3], a_base + off);
                }
#pragma unroll
                for (int nf2 = 0; nf2 < 2; nf2++) {
                    int row = 32 * warp_n + 16 * nf2 + (lane & 7) + (((lane >> 4) & 1) << 3);
                    int colb = (16 * ks + (((lane >> 3) & 1) << 3)) * 2;
                    uint32_t off = (uint32_t)(row * 128 + colb);
                    off ^= (off >> 3) & 0x70;
                    ldsm4(b[nf2][0], b[nf2][1], b[nf2][2], b[nf2][3], b_base + off);
                }
#pragma unroll
                for (int mf = 0; mf < 4; mf++)
#pragma unroll
                    for (int nf = 0; nf < 4; nf++)
                        mma16816(acc[mf][nf], a[mf], &b[nf >> 1][(nf & 1) * 2]);
            }
        }
        __syncthreads();
    }

    // epilogue: write split aohat (pattern A: [hi|lo], row width 2*HID)
#pragma unroll
    for (int mf = 0; mf < 4; mf++) {
        int r0 = i0 + 64 * warp_m + 16 * mf + (int)(lane >> 2);
#pragma unroll
        for (int nf = 0; nf < 4; nf++) {
            int c0 = 32 * warp_n + 8 * nf + (int)(lane & 3) * 2;
#pragma unroll
            for (int rr = 0; rr < 2; rr++) {
                float d0 = acc[mf][nf][rr * 2], d1 = acc[mf][nf][rr * 2 + 1];
                uint32_t lo, hi = split_packh(d0, d1, lo);
                size_t b0 = (size_t)(r0 + rr * 8) * (2 * HID_) + h * D_ + c0;
                *(uint32_t*)(aohat + b0) = hi;
                *(uint32_t*)(aohat + b0 + HID_) = lo;
            }
        }
    }
}

// ----------------------- split-fp16 conversion kernels -------------------
__global__ void split_plain(const float* __restrict__ A, __half* __restrict__ out,
                            int M, int K) {  // pattern A: [hi|lo]
    int idx = blockIdx.x * blockDim.x + threadIdx.x;
    if (idx >= M * K) return;
    int m = idx / K, k = idx - m * K;
    float x = A[idx];
    __half hi = __float2half_rn(x);
    __half lo = __float2half_rn(x - __half2float(hi));
    size_t base = (size_t)m * 2 * K;
    out[base + k] = hi; out[base + K + k] = lo;
}

__global__ void split_heads(const float* __restrict__ src, int ld,
                            __half* __restrict__ out, int nh, int patternB) {
    int idx = blockIdx.x * blockDim.x + threadIdx.x;
    if (idx >= S_ * nh * D_) return;
    int d = idx & 127;
    int h = (idx >> 7) % nh;
    int s = idx / (nh * D_);
    float x = src[(size_t)s * ld + h * D_ + d];
    __half hi = __float2half_rn(x);
    size_t base = ((size_t)h * S_ + s) * (2 * D_);
    if (patternB) {  // [k|k] duplicated
        out[base + d] = hi; out[base + D_ + d] = hi;
    } else {         // [hi|lo]
        __half lo = __float2half_rn(x - __half2float(hi));
        out[base + d] = hi; out[base + D_ + d] = lo;
    }
}

// transpose + fp16: dup=1 -> [b|b] (width 2K); dup=0 -> single (width K)
__global__ void transpose_split(const float* __restrict__ src, int ldsrc, int K, int Nper,
                                __half* __restrict__ out, int dup) {
    int z = blockIdx.z;
    const float* s = src + (size_t)z * Nper;
    int width = dup ? 2 * K : K;
    __half* o = out + (size_t)z * Nper * width;
    __shared__ float t[32][33];
    int k0 = blockIdx.y * 32, n0 = blockIdx.x * 32;
    int tx = threadIdx.x, ty = threadIdx.y;
#pragma unroll
    for (int r = 0; r < 4; r++) {
        int k = k0 + ty + 8 * r;
        t[ty + 8 * r][tx] = s[(size_t)k * ldsrc + n0 + tx];
    }
    __syncthreads();
#pragma unroll
    for (int r = 0; r < 4; r++) {
        int n = n0 + ty + 8 * r, k = k0 + tx;
        __half hh = __float2half_rn(t[tx][ty + 8 * r]);
        size_t base = (size_t)n * width;
        o[base + k] = hh;
        if (dup) o[base + K + k] = hh;
    }
}

// --------------------------------- RoPE ---------------------------------
__global__ void rope_kernel(float* x, int nh, int ld) {
    int idx = blockIdx.x * blockDim.x + threadIdx.x;
    if (idx >= S_ * nh * 64) return;
    int d = idx & 63;
    int rest = idx >> 6;
    int h = rest % nh;
    int s = rest / nh;
    float* base = x + (size_t)s * ld + h * 128;
    float x1 = base[d], x2 = base[d + 64];
    float inv = powf(10000.f, -(float)d * (1.f / 64.f));
    float ang = (float)s * inv;
    float c, sn;
    sincosf(ang, &sn, &c);
    base[d] = x1 * c - x2 * sn;
    base[d + 64] = x2 * c + x1 * sn;
}

// ------------------ invl1 = 1 / rowsum -----------------------------------
__global__ void invl_kernel(const float* __restrict__ rs, float* __restrict__ il) {
    int i = blockIdx.x * 256 + threadIdx.x;
    il[i] = 1.f / rs[i];
}

// coalesced column sums (rows above diagonal are exactly zero in g_e)
__global__ __launch_bounds__(256) void colsum_kernel() {
    int h = blockIdx.y;
    int j0 = blockIdx.x * 256;
    int j = j0 + threadIdx.x;
    const float* base = g_e + (size_t)h * S_ * S_;
    __shared__ float il[S_];
    for (int i = j0 + threadIdx.x; i < S_; i += 256)
        il[i] = g_invl1[h * S_ + i];
    __syncthreads();
    float a0 = 0.f, a1 = 0.f, a2 = 0.f, a3 = 0.f;
    for (int i = j0; i < S_; i += 4) {
        a0 += base[(size_t)(i    ) * S_ + j] * il[i];
        a1 += base[(size_t)(i + 1) * S_ + j] * il[i + 1];
        a2 += base[(size_t)(i + 2) * S_ + j] * il[i + 2];
        a3 += base[(size_t)(i + 3) * S_ + j] * il[i + 3];
    }
    g_colsum[h * S_ + j] = (a0 + a1) + (a2 + a3);
}

__global__ __launch_bounds__(256) void topk_kernel() {
    int h = blockIdx.x;
    int tid = threadIdx.x;
    int lane = tid & 31, w = tid >> 5;
    __shared__ float vals[S_];
    __shared__ float wbv[8];
    __shared__ int wbi[8];
    __shared__ uint32_t bits[64];
    for (int j = tid; j < S_; j += 256) vals[j] = g_colsum[h * S_ + j];
    if (tid < 64) bits[tid] = 0;
    __syncthreads();
    for (int it = 0; it < HB_; it++) {
        float best = -INFINITY; int besti = 1 << 30;
        for (int j = tid; j < S_; j += 256) {
            float v = vals[j];
            if (v > best || (v == best && j < besti)) { best = v; besti = j; }
        }
#pragma unroll
        for (int off = 16; off > 0; off >>= 1) {
            float ov = __shfl_xor_sync(0xFFFFFFFF, best, off);
            int oi = __shfl_xor_sync(0xFFFFFFFF, besti, off);
            if (ov > best || (ov == best && oi < besti)) { best = ov; besti = oi; }
        }
        if (lane == 0) { wbv[w] = best; wbi[w] = besti; }
        __syncthreads();
        if (tid == 0) {
            float b = wbv[0]; int bi2 = wbi[0];
#pragma unroll
            for (int q = 1; q < 8; q++)
                if (wbv[q] > b || (wbv[q] == b && wbi[q] < bi2)) { b = wbv[q]; bi2 = wbi[q]; }
            g_heavylist[h * HB_ + it] = bi2;
            bits[bi2 >> 5] |= (1u << (bi2 & 31));
            vals[bi2] = -INFINITY;
        }
        __syncthreads();
    }
    if (tid < 64) g_heavybits[h * 64 + tid] = bits[tid];
}

// ------ pass-2: invl2 = 1/sum(e over band + heavy) ------
__global__ __launch_bounds__(256) void rowsum2_kernel() {
    int h = blockIdx.y;
    int tid = threadIdx.x;
    __shared__ int hl[HB_];
    for (int t = tid; t < HB_; t += 256) hl[t] = g_heavylist[h * HB_ + t];
    __syncthreads();

    int w = tid >> 5, lane = tid & 31;
    int i = blockIdx.x * 8 + w;
    const float* erow = g_e + (size_t)(h * S_ + i) * S_;
    int lo = i - RB_; if (lo < 0) lo = 0;

    float l = 0.f;
    for (int j = lo + lane; j <= i; j += 32) l += erow[j];
    for (int t = lane; t < HB_; t += 32) {
        int j = hl[t];
        if (j < lo) l += erow[j];
    }
#pragma unroll
    for (int off = 16; off > 0; off >>= 1)
        l += __shfl_xor_sync(0xFFFFFFFF, l, off);
    if (lane == 0) g_invl2[h * S_ + i] = 1.f / l;
}

// ------------------------------ launcher ---------------------------------
extern "C" void kernel_launch(void* const* d_in, const int* in_sizes, int n_in,
                              void* d_out, int out_size) {
    const float* hidden = (const float*)d_in[0];
    const float* Wq = (const float*)d_in[1];
    const float* Wk = (const float*)d_in[2];
    const float* Wv = (const float*)d_in[3];
    const float* Wo = (const float*)d_in[4];
    float* out = (float*)d_out;

    float *qkv, *e, *rsum, *il1, *il2;
    uint32_t* hbits;
    __half *xhat, *wqkvt, *wot, *qhat, *khat, *vthat, *aohat;
    cudaGetSymbolAddress((void**)&qkv, g_qkv);
    cudaGetSymbolAddress((void**)&e, g_e);
    cudaGetSymbolAddress((void**)&rsum, g_rowsum);
    cudaGetSymbolAddress((void**)&il1, g_invl1);
    cudaGetSymbolAddress((void**)&il2, g_invl2);
    cudaGetSymbolAddress((void**)&hbits, g_heavybits);
    cudaGetSymbolAddress((void**)&xhat, g_xhat);
    cudaGetSymbolAddress((void**)&wqkvt, g_wqkvt);
    cudaGetSymbolAddress((void**)&wot, g_wot);
    cudaGetSymbolAddress((void**)&qhat, g_qhat);
    cudaGetSymbolAddress((void**)&khat, g_khat);
    cudaGetSymbolAddress((void**)&vthat, g_vthat);
    cudaGetSymbolAddress((void**)&aohat, g_aohat);

    const int SMEM_GEMM = 66560;
    const int SMEM_PV = 66560;
    cudaFuncSetAttribute(mma_gemm, cudaFuncAttributeMaxDynamicSharedMemorySize, SMEM_GEMM);
    cudaFuncSetAttribute(pv_mma, cudaFuncAttributeMaxDynamicSharedMemorySize, SMEM_PV);

    // 1-4: splits needed for QKV; QKV mma is the 5th launch (ncu capture slot)
    split_plain<<<(S_ * HID_ + 255) / 256, 256>>>(hidden, xhat, S_, HID_);
    transpose_split<<<dim3(HID_ / 32, HID_ / 32, 1), dim3(32, 8)>>>(Wq, HID_, HID_, HID_, wqkvt, 1);
    transpose_split<<<dim3((NKV_ * D_) / 32, HID_ / 32, 1), dim3(32, 8)>>>(
        Wk, NKV_ * D_, HID_, NKV_ * D_, wqkvt + (size_t)HID_ * 2 * HID_, 1);
    transpose_split<<<dim3((NKV_ * D_) / 32, HID_ / 32, 1), dim3(32, 8)>>>(
        Wv, NKV_ * D_, HID_, NKV_ * D_, wqkvt + (size_t)(HID_ + NKV_ * D_) * 2 * HID_, 1);

    // 5. fused QKV projection (one GEMM, N=3072, Kp = 2*HID)
    mma_gemm<<<dim3(QKVN_ / 128, S_ / 128, 1), 256, SMEM_GEMM>>>(
        xhat, 0, wqkvt, 0, 0, qkv, 0, QKVN_, 2 * HID_, 0, nullptr);

    transpose_split<<<dim3(HID_ / 32, HID_ / 32, 1), dim3(32, 8)>>>(Wo, HID_, HID_, HID_, wot, 1);

    // RoPE (in place inside g_qkv)
    rope_kernel<<<(S_ * NH_ * 64 + 255) / 256, 256>>>(qkv, NH_, QKVN_);
    rope_kernel<<<(S_ * NKV_ * 64 + 255) / 256, 256>>>(qkv + HID_, NKV_, QKVN_);

    // split roped Q ([hi|lo]) / K ([k|k]); transpose V -> single fp16 V^T
    split_heads<<<(S_ * NH_ * D_ + 255) / 256, 256>>>(qkv, QKVN_, qhat, NH_, 0);
    split_heads<<<(S_ * NKV_ * D_ + 255) / 256, 256>>>(qkv + HID_, QKVN_, khat, NKV_, 1);
    transpose_split<<<dim3(D_ / 32, S_ / 32, NKV_), dim3(32, 8)>>>(
        qkv + HID_ + NKV_ * D_, QKVN_, S_, D_, vthat, 0);

    // zero rowsum accumulator (captured node, re-zeroed every replay)
    cudaMemsetAsync(rsum, 0, NH_ * S_ * sizeof(float));

    // e = exp(scale * QK^T) + fused row sums (Kp = 2*D)
    mma_gemm<<<dim3(S_ / 128, S_ / 128, NH_), 256, SMEM_GEMM>>>(
        qhat, (size_t)S_ * 2 * D_, khat, (size_t)S_ * 2 * D_, 2,
        e, (size_t)S_ * S_, S_, 2 * D_, 2, rsum);

    // H2O: invl1, colsum, topk (emits heavy bitmask)
    invl_kernel<<<NH_ * S_ / 256, 256>>>(rsum, il1);
    colsum_kernel<<<dim3(S_ / 256, NH_), 256>>>();
    topk_kernel<<<NH_, 256>>>();

    // invl2 (sum-only; e untouched)
    rowsum2_kernel<<<dim3(S_ / 8, NH_), 256>>>();

    // fused masked PV -> aohat ([hi|lo] fp16)
    pv_mma<<<dim3(S_ / 128, NH_), 256, SMEM_PV>>>(vthat, e, il2, hbits, aohat);

    // output projection (Kp = 2*HID)
    mma_gemm<<<dim3(HID_ / 128, S_ / 128, 1), 256, SMEM_GEMM>>>(
        aohat, 0, wot, 0, 0, out, 0, HID_, 2 * HID_, 0, nullptr);
}

// round 11
// speedup vs baseline: 4.1956x; 1.1943x over previous
#include <cuda_runtime.h>
#include <cuda_fp16.h>
#include <math.h>
#include <stdint.h>

#define S_    2048
#define HID_  2048
#define NH_   16
#define NKV_  4
#define D_    128
#define HB_   204
#define RB_   204
#define SCALE_ 0.08838834764831845f
#define L2E_  1.4426950408889634f
#define QKVN_ 3072

// ----------------------------- scratch ---------------------------------
__device__ float g_qkv[S_ * QKVN_];                 // [s][ q(2048) | k(512) | v(512) ]
__device__ __half g_e[(size_t)NH_ * S_ * S_];       // exp(score) fp16; zero above diagonal
__device__ float g_rowsum[NH_ * S_];
__device__ float g_invl1[NH_ * S_], g_invl2[NH_ * S_];
__device__ float g_colsum[NH_ * S_];
__device__ int   g_heavylist[NH_ * HB_];
__device__ uint32_t g_heavybits[NH_ * 64];

__device__ __half g_xhat[(size_t)S_ * 2 * HID_];          // A-pattern [hi|lo]
__device__ __half g_wqkvt[(size_t)QKVN_ * 2 * HID_];      // B-pattern [b|b] (Wq|Wk|Wv)^T
__device__ __half g_wot[(size_t)HID_ * 2 * HID_];
__device__ __half g_qhat[(size_t)NH_ * S_ * 2 * D_];      // A-pattern [hi|lo]
__device__ __half g_khat[(size_t)NKV_ * S_ * 2 * D_];     // B-pattern [k|k]
__device__ __half g_vthat[(size_t)NKV_ * D_ * S_];        // single fp16 (V^T)
__device__ __half g_aohat[(size_t)S_ * 2 * HID_];         // A-pattern [hi|lo]

// ----------------------------- PTX helpers ------------------------------
__device__ __forceinline__ uint32_t smem_u32(const void* p) {
    uint32_t a;
    asm("{ .reg .u64 t; cvta.to.shared.u64 t, %1; cvt.u32.u64 %0, t; }" : "=r"(a) : "l"(p));
    return a;
}
__device__ __forceinline__ void cp16(uint32_t saddr, const void* gptr) {
    asm volatile("cp.async.cg.shared.global [%0], [%1], 16;" :: "r"(saddr), "l"(gptr));
}
__device__ __forceinline__ void cp_commit() { asm volatile("cp.async.commit_group;"); }
__device__ __forceinline__ void cp_wait0() { asm volatile("cp.async.wait_group 0;" ::: "memory"); }
__device__ __forceinline__ void cp_wait1() { asm volatile("cp.async.wait_group 1;" ::: "memory"); }

__device__ __forceinline__ void ldsm4(uint32_t& r0, uint32_t& r1, uint32_t& r2, uint32_t& r3,
                                      uint32_t addr) {
    asm volatile("ldmatrix.sync.aligned.m8n8.x4.shared.b16 {%0,%1,%2,%3}, [%4];"
                 : "=r"(r0), "=r"(r1), "=r"(r2), "=r"(r3) : "r"(addr));
}
__device__ __forceinline__ void mma16816(float* d, const uint32_t* a, const uint32_t* b) {
    asm volatile(
        "mma.sync.aligned.m16n8k16.row.col.f32.f16.f16.f32 "
        "{%0,%1,%2,%3}, {%4,%5,%6,%7}, {%8,%9}, {%0,%1,%2,%3};"
        : "+f"(d[0]), "+f"(d[1]), "+f"(d[2]), "+f"(d[3])
        : "r"(a[0]), "r"(a[1]), "r"(a[2]), "r"(a[3]), "r"(b[0]), "r"(b[1]));
}
__device__ __forceinline__ float fexp(float x) {   // e^x via MUFU
    float y;
    asm("ex2.approx.ftz.f32 %0, %1;" : "=f"(y) : "f"(x * L2E_));
    return y;
}
__device__ __forceinline__ float fexp2p(float x) { // 2^x via FMA pipe
    float n = rintf(x);
    float f = x - n;
    float p = 1.3333558e-3f;
    p = fmaf(p, f, 9.6181291e-3f);
    p = fmaf(p, f, 5.5504110e-2f);
    p = fmaf(p, f, 2.4022651e-1f);
    p = fmaf(p, f, 6.9314718e-1f);
    p = fmaf(p, f, 1.0f);
    return p * __int_as_float(((int)n + 127) << 23);
}
__device__ __forceinline__ uint32_t split_packh(float p0, float p1, uint32_t& lo) {
    __half h0 = __float2half_rn(p0), h1 = __float2half_rn(p1);
    float f0 = __half2float(h0), f1 = __half2float(h1);
    __half l0 = __float2half_rn(p0 - f0), l1 = __float2half_rn(p1 - f1);
    lo = (uint32_t)__half_as_ushort(l0) | ((uint32_t)__half_as_ushort(l1) << 16);
    return (uint32_t)__half_as_ushort(h0) | ((uint32_t)__half_as_ushort(h1) << 16);
}
__device__ __forceinline__ uint32_t packh(float p0, float p1) {
    __half2 h = __floats2half2_rn(p0, p1);
    return *(uint32_t*)&h;
}

// ------------------------- HMMA GEMM -------------------------
__device__ __forceinline__ void load_tile_async(uint32_t sbase, const __half* src,
                                                int ld, int row0, int kbase, int tid) {
#pragma unroll
    for (int t = 0; t < 4; t++) {
        int u = tid + t * 256;
        int row = u >> 3, seg = u & 7;
        uint32_t bo = (uint32_t)(row * 128 + seg * 16);
        bo ^= (bo >> 3) & 0x70;
        cp16(sbase + bo, src + (size_t)(row0 + row) * ld + kbase + seg * 8);
    }
}

// mode 0: plain fp32 store to C.
// mode 2: Eh = fp16(exp(scale*s)) for j<=i (0 above), hybrid exp, fused row sums of rounded e.
__global__ __launch_bounds__(256, 2) void mma_gemm(
    const __half* __restrict__ A, size_t aStrideZ,
    const __half* __restrict__ Bt, size_t bStrideZ, int bShift,
    float* __restrict__ C, __half* __restrict__ Eh, size_t cStrideZ, int ldc,
    int Kp, int mode, float* __restrict__ rowsum) {
    int z = blockIdx.z;
    int i0 = blockIdx.y * 128, j0 = blockIdx.x * 128;
    if (mode == 2 && j0 > i0 + 127) return;   // fully above diagonal: skip

    const __half* Az = A + (size_t)z * aStrideZ;
    const __half* Bz = Bt + (size_t)(z >> bShift) * bStrideZ;
    int tid = threadIdx.x, wid = tid >> 5;
    uint32_t lane = tid & 31;

    extern __shared__ char dsm[];
    char* tile = (char*)(((uintptr_t)dsm + 1023) & ~(uintptr_t)1023);
    uint32_t sA[2] = { smem_u32(tile), smem_u32(tile) + 16384 };
    uint32_t sB[2] = { smem_u32(tile) + 32768, smem_u32(tile) + 49152 };

    int warp_m = wid >> 2;
    int warp_n = wid & 3;

    float acc[4][4][4];
#pragma unroll
    for (int i = 0; i < 4; i++)
#pragma unroll
        for (int j = 0; j < 4; j++)
#pragma unroll
            for (int r = 0; r < 4; r++) acc[i][j][r] = 0.f;

    load_tile_async(sA[0], Az, Kp, i0, 0, tid);
    load_tile_async(sB[0], Bz, Kp, j0, 0, tid);
    cp_commit();

    const int NC = Kp >> 6;
    for (int c = 0; c < NC; c++) {
        if (c + 1 < NC) {
            load_tile_async(sA[(c + 1) & 1], Az, Kp, i0, (c + 1) * 64, tid);
            load_tile_async(sB[(c + 1) & 1], Bz, Kp, j0, (c + 1) * 64, tid);
            cp_commit();
            cp_wait1();
        } else {
            cp_wait0();
        }
        __syncthreads();

        uint32_t a_base = sA[c & 1], b_base = sB[c & 1];
#pragma unroll
        for (int ks = 0; ks < 4; ks++) {
            uint32_t a[4][4], b[2][4];
#pragma unroll
            for (int mf = 0; mf < 4; mf++) {
                int row = 64 * warp_m + 16 * mf + (lane & 7) + (((lane >> 3) & 1) << 3);
                int colb = (16 * ks + (((lane >> 4) & 1) << 3)) * 2;
                uint32_t off = (uint32_t)(row * 128 + colb);
                off ^= (off >> 3) & 0x70;
                ldsm4(a[mf][0], a[mf][1], a[mf][2], a[mf][3], a_base + off);
            }
#pragma unroll
            for (int nf2 = 0; nf2 < 2; nf2++) {
                int row = 32 * warp_n + 16 * nf2 + (lane & 7) + (((lane >> 4) & 1) << 3);
                int colb = (16 * ks + (((lane >> 3) & 1) << 3)) * 2;
                uint32_t off = (uint32_t)(row * 128 + colb);
                off ^= (off >> 3) & 0x70;
                ldsm4(b[nf2][0], b[nf2][1], b[nf2][2], b[nf2][3], b_base + off);
            }
#pragma unroll
            for (int mf = 0; mf < 4; mf++)
#pragma unroll
                for (int nf = 0; nf < 4; nf++)
                    mma16816(acc[mf][nf], a[mf], &b[nf >> 1][(nf & 1) * 2]);
        }
        __syncthreads();
    }

    if (mode == 0) {
        float* Cz = C + (size_t)z * cStrideZ;
#pragma unroll
        for (int mf = 0; mf < 4; mf++) {
            int r0 = i0 + 64 * warp_m + 16 * mf + (int)(lane >> 2);
#pragma unroll
            for (int nf = 0; nf < 4; nf++) {
                int c0 = j0 + 32 * warp_n + 8 * nf + (int)(lane & 3) * 2;
                *(float2*)(Cz + (size_t)r0 * ldc + c0) = make_float2(acc[mf][nf][0], acc[mf][nf][1]);
                *(float2*)(Cz + (size_t)(r0 + 8) * ldc + c0) = make_float2(acc[mf][nf][2], acc[mf][nf][3]);
            }
        }
        return;
    }

    // mode 2: exp epilogue, fp16 store, fused row sums (of rounded values)
    __half* Ez = Eh + (size_t)z * cStrideZ;
    float rs0[4], rs1[4];
#pragma unroll
    for (int mf = 0; mf < 4; mf++) {
        int r0 = i0 + 64 * warp_m + 16 * mf + (int)(lane >> 2);
        float s0 = 0.f, s1 = 0.f;
#pragma unroll
        for (int nf = 0; nf < 4; nf++) {
            int c0 = j0 + 32 * warp_n + 8 * nf + (int)(lane & 3) * 2;
            float d0 = acc[mf][nf][0], d1 = acc[mf][nf][1];
            float d2 = acc[mf][nf][2], d3 = acc[mf][nf][3];
            if (nf < 2) {   // MUFU half
                d0 = (c0     <= r0)     ? fexp(d0 * SCALE_) : 0.f;
                d1 = (c0 + 1 <= r0)     ? fexp(d1 * SCALE_) : 0.f;
                d2 = (c0     <= r0 + 8) ? fexp(d2 * SCALE_) : 0.f;
                d3 = (c0 + 1 <= r0 + 8) ? fexp(d3 * SCALE_) : 0.f;
            } else {        // FMA-pipe poly half
                const float cl = SCALE_ * L2E_;
                d0 = (c0     <= r0)     ? fexp2p(d0 * cl) : 0.f;
                d1 = (c0 + 1 <= r0)     ? fexp2p(d1 * cl) : 0.f;
                d2 = (c0     <= r0 + 8) ? fexp2p(d2 * cl) : 0.f;
                d3 = (c0 + 1 <= r0 + 8) ? fexp2p(d3 * cl) : 0.f;
            }
            __half2 h01 = __floats2half2_rn(d0, d1);
            __half2 h23 = __floats2half2_rn(d2, d3);
            *(uint32_t*)(Ez + (size_t)r0 * ldc + c0) = *(uint32_t*)&h01;
            *(uint32_t*)(Ez + (size_t)(r0 + 8) * ldc + c0) = *(uint32_t*)&h23;
            float2 f01 = __half22float2(h01);
            float2 f23 = __half22float2(h23);
            s0 += f01.x + f01.y;
            s1 += f23.x + f23.y;
        }
        rs0[mf] = s0; rs1[mf] = s1;
    }
    {
        float* rz = rowsum + (size_t)z * S_;
#pragma unroll
        for (int mf = 0; mf < 4; mf++) {
            float v0 = rs0[mf], v1 = rs1[mf];
            v0 += __shfl_xor_sync(0xFFFFFFFF, v0, 1);
            v0 += __shfl_xor_sync(0xFFFFFFFF, v0, 2);
            v1 += __shfl_xor_sync(0xFFFFFFFF, v1, 1);
            v1 += __shfl_xor_sync(0xFFFFFFFF, v1, 2);
            if ((lane & 3) == 0) {
                int r0 = i0 + 64 * warp_m + 16 * mf + (int)(lane >> 2);
                atomicAdd(rz + r0, v0);
                atomicAdd(rz + r0 + 8, v1);
            }
        }
    }
}

// ------------------ fused PV (masked P on the fly, single-pass fp16) --------------
__global__ __launch_bounds__(256, 2) void pv_mma(
    const __half* __restrict__ vthat,
    const __half* __restrict__ e, const float* __restrict__ invl2,
    const uint32_t* __restrict__ heavybits,
    __half* __restrict__ aohat) {
    int i0 = (int)(gridDim.x - 1 - blockIdx.x) * 128;   // heavy blocks first
    int h = blockIdx.y, kh = h >> 2;
    int tid = threadIdx.x, wid = tid >> 5;
    uint32_t lane = tid & 31;
    int warp_m = wid >> 2, warp_n = wid & 3;

    extern __shared__ char dsm[];
    char* tile = (char*)(((uintptr_t)dsm + 1023) & ~(uintptr_t)1023);
    char* pP = tile;                                   // 16 KB P tile (fp16)
    uint32_t sP = smem_u32(pP);
    uint32_t sV[2] = { smem_u32(tile) + 16384, smem_u32(tile) + 32768 };

    __shared__ uint32_t sbits[64];
    if (tid < 64) sbits[tid] = heavybits[h * 64 + tid];

    int r = tid >> 1, half = tid & 1;
    int gi = i0 + r;
    float il = invl2[h * S_ + gi];
    const __half* erow = e + ((size_t)h * S_ + gi) * S_ + half * 32;
    const __half* Vz = vthat + (size_t)kh * D_ * S_;

    float acc[4][4][4];
#pragma unroll
    for (int i = 0; i < 4; i++)
#pragma unroll
        for (int j = 0; j < 4; j++)
#pragma unroll
            for (int q = 0; q < 4; q++) acc[i][j][q] = 0.f;

    const int NCH = (i0 >> 6) + 2;
    load_tile_async(sV[0], Vz, S_, 0, 0, tid);
    cp_commit();
    __syncthreads();   // sbits visible

    for (int c = 0; c < NCH; c++) {
        int j0 = c * 64;
        bool pre = (c + 1 < NCH);
        if (pre) {
            load_tile_async(sV[(c + 1) & 1], Vz, S_, 0, (c + 1) * 64, tid);
            cp_commit();
        }
        // build masked fp16 P tile (row r, 32 cols starting at j0 + half*32)
        uint32_t hib[16];
        const __half* ep = erow + j0;
        int gjb = j0 + half * 32;
#pragma unroll
        for (int w = 0; w < 4; w++) {
            uint4 ev = *(const uint4*)(ep + w * 8);
            float2 f0 = __half22float2(*(__half2*)&ev.x);
            float2 f1 = __half22float2(*(__half2*)&ev.y);
            float2 f2 = __half22float2(*(__half2*)&ev.z);
            float2 f3 = __half22float2(*(__half2*)&ev.w);
            float pv[8] = { f0.x, f0.y, f1.x, f1.y, f2.x, f2.y, f3.x, f3.y };
#pragma unroll
            for (int u = 0; u < 8; u++) {
                int gj = gjb + w * 8 + u;
                bool keep = (gj <= gi) &&
                            ((gi - gj <= RB_) || ((sbits[gj >> 5] >> (gj & 31)) & 1u));
                pv[u] = keep ? pv[u] * il : 0.f;
            }
            hib[w * 4 + 0] = packh(pv[0], pv[1]);
            hib[w * 4 + 1] = packh(pv[2], pv[3]);
            hib[w * 4 + 2] = packh(pv[4], pv[5]);
            hib[w * 4 + 3] = packh(pv[6], pv[7]);
        }
#pragma unroll
        for (int sg = 0; sg < 4; sg++) {
            uint32_t bo = (uint32_t)(r * 128 + half * 64 + sg * 16);
            bo ^= (bo >> 3) & 0x70;
            *(uint4*)(pP + bo) = make_uint4(hib[sg * 4], hib[sg * 4 + 1], hib[sg * 4 + 2], hib[sg * 4 + 3]);
        }
        if (pre) cp_wait1(); else cp_wait0();
        __syncthreads();

        uint32_t b_base = sV[c & 1];
#pragma unroll
        for (int ks = 0; ks < 4; ks++) {
            uint32_t a[4][4], b[2][4];
#pragma unroll
            for (int mf = 0; mf < 4; mf++) {
                int row = 64 * warp_m + 16 * mf + (lane & 7) + (((lane >> 3) & 1) << 3);
                int colb = (16 * ks + (((lane >> 4) & 1) << 3)) * 2;
                uint32_t off = (uint32_t)(row * 128 + colb);
                off ^= (off >> 3) & 0x70;
                ldsm4(a[mf][0], a[mf][1], a[mf][2], a[mf][3], sP + off);
            }
#pragma unroll
            for (int nf2 = 0; nf2 < 2; nf2++) {
                int row = 32 * warp_n + 16 * nf2 + (lane & 7) + (((lane >> 4) & 1) << 3);
                int colb = (16 * ks + (((lane >> 3) & 1) << 3)) * 2;
                uint32_t off = (uint32_t)(row * 128 + colb);
                off ^= (off >> 3) & 0x70;
                ldsm4(b[nf2][0], b[nf2][1], b[nf2][2], b[nf2][3], b_base + off);
            }
#pragma unroll
            for (int mf = 0; mf < 4; mf++)
#pragma unroll
                for (int nf = 0; nf < 4; nf++)
                    mma16816(acc[mf][nf], a[mf], &b[nf >> 1][(nf & 1) * 2]);
        }
        __syncthreads();
    }

    // epilogue: write split aohat (pattern A: [hi|lo], row width 2*HID)
#pragma unroll
    for (int mf = 0; mf < 4; mf++) {
        int r0 = i0 + 64 * warp_m + 16 * mf + (int)(lane >> 2);
#pragma unroll
        for (int nf = 0; nf < 4; nf++) {
            int c0 = 32 * warp_n + 8 * nf + (int)(lane & 3) * 2;
#pragma unroll
            for (int rr = 0; rr < 2; rr++) {
                float d0 = acc[mf][nf][rr * 2], d1 = acc[mf][nf][rr * 2 + 1];
                uint32_t lo, hi = split_packh(d0, d1, lo);
                size_t b0 = (size_t)(r0 + rr * 8) * (2 * HID_) + h * D_ + c0;
                *(uint32_t*)(aohat + b0) = hi;
                *(uint32_t*)(aohat + b0 + HID_) = lo;
            }
        }
    }
}

// ----------------------- split-fp16 conversion kernels -------------------
__global__ void split_plain(const float* __restrict__ A, __half* __restrict__ out,
                            int M, int K) {  // pattern A: [hi|lo]
    int idx = blockIdx.x * blockDim.x + threadIdx.x;
    if (idx >= M * K) return;
    int m = idx / K, k = idx - m * K;
    float x = A[idx];
    __half hi = __float2half_rn(x);
    __half lo = __float2half_rn(x - __half2float(hi));
    size_t base = (size_t)m * 2 * K;
    out[base + k] = hi; out[base + K + k] = lo;
}

__global__ void split_heads(const float* __restrict__ src, int ld,
                            __half* __restrict__ out, int nh, int patternB) {
    int idx = blockIdx.x * blockDim.x + threadIdx.x;
    if (idx >= S_ * nh * D_) return;
    int d = idx & 127;
    int h = (idx >> 7) % nh;
    int s = idx / (nh * D_);
    float x = src[(size_t)s * ld + h * D_ + d];
    __half hi = __float2half_rn(x);
    size_t base = ((size_t)h * S_ + s) * (2 * D_);
    if (patternB) {  // [k|k] duplicated
        out[base + d] = hi; out[base + D_ + d] = hi;
    } else {         // [hi|lo]
        __half lo = __float2half_rn(x - __half2float(hi));
        out[base + d] = hi; out[base + D_ + d] = lo;
    }
}

// transpose + fp16: dup=1 -> [b|b] (width 2K); dup=0 -> single (width K)
__global__ void transpose_split(const float* __restrict__ src, int ldsrc, int K, int Nper,
                                __half* __restrict__ out, int dup) {
    int z = blockIdx.z;
    const float* s = src + (size_t)z * Nper;
    int width = dup ? 2 * K : K;
    __half* o = out + (size_t)z * Nper * width;
    __shared__ float t[32][33];
    int k0 = blockIdx.y * 32, n0 = blockIdx.x * 32;
    int tx = threadIdx.x, ty = threadIdx.y;
#pragma unroll
    for (int r = 0; r < 4; r++) {
        int k = k0 + ty + 8 * r;
        t[ty + 8 * r][tx] = s[(size_t)k * ldsrc + n0 + tx];
    }
    __syncthreads();
#pragma unroll
    for (int r = 0; r < 4; r++) {
        int n = n0 + ty + 8 * r, k = k0 + tx;
        __half hh = __float2half_rn(t[tx][ty + 8 * r]);
        size_t base = (size_t)n * width;
        o[base + k] = hh;
        if (dup) o[base + K + k] = hh;
    }
}

// --------------------------------- RoPE ---------------------------------
__global__ void rope_kernel(float* x, int nh, int ld) {
    int idx = blockIdx.x * blockDim.x + threadIdx.x;
    if (idx >= S_ * nh * 64) return;
    int d = idx & 63;
    int rest = idx >> 6;
    int h = rest % nh;
    int s = rest / nh;
    float* base = x + (size_t)s * ld + h * 128;
    float x1 = base[d], x2 = base[d + 64];
    float inv = powf(10000.f, -(float)d * (1.f / 64.f));
    float ang = (float)s * inv;
    float c, sn;
    sincosf(ang, &sn, &c);
    base[d] = x1 * c - x2 * sn;
    base[d + 64] = x2 * c + x1 * sn;
}

// ------------------ invl1 = 1 / rowsum -----------------------------------
__global__ void invl_kernel(const float* __restrict__ rs, float* __restrict__ il) {
    int i = blockIdx.x * 256 + threadIdx.x;
    il[i] = 1.f / rs[i];
}

// coalesced column sums over fp16 e (rows above diagonal are exactly zero)
__global__ __launch_bounds__(256) void colsum_kernel() {
    int h = blockIdx.y;
    int j0 = blockIdx.x * 256;
    int j = j0 + threadIdx.x;
    const __half* base = g_e + (size_t)h * S_ * S_;
    __shared__ float il[S_];
    for (int i = j0 + threadIdx.x; i < S_; i += 256)
        il[i] = g_invl1[h * S_ + i];
    __syncthreads();
    float a0 = 0.f, a1 = 0.f, a2 = 0.f, a3 = 0.f;
    for (int i = j0; i < S_; i += 4) {
        a0 += __half2float(base[(size_t)(i    ) * S_ + j]) * il[i];
        a1 += __half2float(base[(size_t)(i + 1) * S_ + j]) * il[i + 1];
        a2 += __half2float(base[(size_t)(i + 2) * S_ + j]) * il[i + 2];
        a3 += __half2float(base[(size_t)(i + 3) * S_ + j]) * il[i + 3];
    }
    g_colsum[h * S_ + j] = (a0 + a1) + (a2 + a3);
}

__global__ __launch_bounds__(256) void topk_kernel() {
    int h = blockIdx.x;
    int tid = threadIdx.x;
    int lane = tid & 31, w = tid >> 5;
    __shared__ float vals[S_];
    __shared__ float wbv[8];
    __shared__ int wbi[8];
    __shared__ uint32_t bits[64];
    for (int j = tid; j < S_; j += 256) vals[j] = g_colsum[h * S_ + j];
    if (tid < 64) bits[tid] = 0;
    __syncthreads();
    for (int it = 0; it < HB_; it++) {
        float best = -INFINITY; int besti = 1 << 30;
        for (int j = tid; j < S_; j += 256) {
            float v = vals[j];
            if (v > best || (v == best && j < besti)) { best = v; besti = j; }
        }
#pragma unroll
        for (int off = 16; off > 0; off >>= 1) {
            float ov = __shfl_xor_sync(0xFFFFFFFF, best, off);
            int oi = __shfl_xor_sync(0xFFFFFFFF, besti, off);
            if (ov > best || (ov == best && oi < besti)) { best = ov; besti = oi; }
        }
        if (lane == 0) { wbv[w] = best; wbi[w] = besti; }
        __syncthreads();
        if (tid == 0) {
            float b = wbv[0]; int bi2 = wbi[0];
#pragma unroll
            for (int q = 1; q < 8; q++)
                if (wbv[q] > b || (wbv[q] == b && wbi[q] < bi2)) { b = wbv[q]; bi2 = wbi[q]; }
            g_heavylist[h * HB_ + it] = bi2;
            bits[bi2 >> 5] |= (1u << (bi2 & 31));
            vals[bi2] = -INFINITY;
        }
        __syncthreads();
    }
    if (tid < 64) g_heavybits[h * 64 + tid] = bits[tid];
}

// ------ pass-2: invl2 = 1/sum(e over band + heavy) ------
__global__ __launch_bounds__(256) void rowsum2_kernel() {
    int h = blockIdx.y;
    int tid = threadIdx.x;
    __shared__ int hl[HB_];
    for (int t = tid; t < HB_; t += 256) hl[t] = g_heavylist[h * HB_ + t];
    __syncthreads();

    int w = tid >> 5, lane = tid & 31;
    int i = blockIdx.x * 8 + w;
    const __half* erow = g_e + (size_t)(h * S_ + i) * S_;
    int lo = i - RB_; if (lo < 0) lo = 0;

    float l = 0.f;
    for (int j = lo + lane; j <= i; j += 32) l += __half2float(erow[j]);
    for (int t = lane; t < HB_; t += 32) {
        int j = hl[t];
        if (j < lo) l += __half2float(erow[j]);
    }
#pragma unroll
    for (int off = 16; off > 0; off >>= 1)
        l += __shfl_xor_sync(0xFFFFFFFF, l, off);
    if (lane == 0) g_invl2[h * S_ + i] = 1.f / l;
}

// ------------------------------ launcher ---------------------------------
extern "C" void kernel_launch(void* const* d_in, const int* in_sizes, int n_in,
                              void* d_out, int out_size) {
    const float* hidden = (const float*)d_in[0];
    const float* Wq = (const float*)d_in[1];
    const float* Wk = (const float*)d_in[2];
    const float* Wv = (const float*)d_in[3];
    const float* Wo = (const float*)d_in[4];
    float* out = (float*)d_out;

    float *qkv, *rsum, *il1, *il2;
    __half* e;
    uint32_t* hbits;
    __half *xhat, *wqkvt, *wot, *qhat, *khat, *vthat, *aohat;
    cudaGetSymbolAddress((void**)&qkv, g_qkv);
    cudaGetSymbolAddress((void**)&e, g_e);
    cudaGetSymbolAddress((void**)&rsum, g_rowsum);
    cudaGetSymbolAddress((void**)&il1, g_invl1);
    cudaGetSymbolAddress((void**)&il2, g_invl2);
    cudaGetSymbolAddress((void**)&hbits, g_heavybits);
    cudaGetSymbolAddress((void**)&xhat, g_xhat);
    cudaGetSymbolAddress((void**)&wqkvt, g_wqkvt);
    cudaGetSymbolAddress((void**)&wot, g_wot);
    cudaGetSymbolAddress((void**)&qhat, g_qhat);
    cudaGetSymbolAddress((void**)&khat, g_khat);
    cudaGetSymbolAddress((void**)&vthat, g_vthat);
    cudaGetSymbolAddress((void**)&aohat, g_aohat);

    const int SMEM_GEMM = 66560;
    const int SMEM_PV = 50176;
    cudaFuncSetAttribute(mma_gemm, cudaFuncAttributeMaxDynamicSharedMemorySize, SMEM_GEMM);
    cudaFuncSetAttribute(pv_mma, cudaFuncAttributeMaxDynamicSharedMemorySize, SMEM_PV);

    // 1-4: splits needed for QKV; QKV mma is the 5th launch (ncu capture slot)
    split_plain<<<(S_ * HID_ + 255) / 256, 256>>>(hidden, xhat, S_, HID_);
    transpose_split<<<dim3(HID_ / 32, HID_ / 32, 1), dim3(32, 8)>>>(Wq, HID_, HID_, HID_, wqkvt, 1);
    transpose_split<<<dim3((NKV_ * D_) / 32, HID_ / 32, 1), dim3(32, 8)>>>(
        Wk, NKV_ * D_, HID_, NKV_ * D_, wqkvt + (size_t)HID_ * 2 * HID_, 1);
    transpose_split<<<dim3((NKV_ * D_) / 32, HID_ / 32, 1), dim3(32, 8)>>>(
        Wv, NKV_ * D_, HID_, NKV_ * D_, wqkvt + (size_t)(HID_ + NKV_ * D_) * 2 * HID_, 1);

    // 5. fused QKV projection (one GEMM, N=3072, Kp = 2*HID)
    mma_gemm<<<dim3(QKVN_ / 128, S_ / 128, 1), 256, SMEM_GEMM>>>(
        xhat, 0, wqkvt, 0, 0, qkv, nullptr, 0, QKVN_, 2 * HID_, 0, nullptr);

    transpose_split<<<dim3(HID_ / 32, HID_ / 32, 1), dim3(32, 8)>>>(Wo, HID_, HID_, HID_, wot, 1);

    // RoPE (in place inside g_qkv)
    rope_kernel<<<(S_ * NH_ * 64 + 255) / 256, 256>>>(qkv, NH_, QKVN_);
    rope_kernel<<<(S_ * NKV_ * 64 + 255) / 256, 256>>>(qkv + HID_, NKV_, QKVN_);

    // split roped Q ([hi|lo]) / K ([k|k]); transpose V -> single fp16 V^T
    split_heads<<<(S_ * NH_ * D_ + 255) / 256, 256>>>(qkv, QKVN_, qhat, NH_, 0);
    split_heads<<<(S_ * NKV_ * D_ + 255) / 256, 256>>>(qkv + HID_, QKVN_, khat, NKV_, 1);
    transpose_split<<<dim3(D_ / 32, S_ / 32, NKV_), dim3(32, 8)>>>(
        qkv + HID_ + NKV_ * D_, QKVN_, S_, D_, vthat, 0);

    // zero rowsum accumulator (captured node, re-zeroed every replay)
    cudaMemsetAsync(rsum, 0, NH_ * S_ * sizeof(float));

    // e = fp16(exp(scale * QK^T)) + fused row sums (Kp = 2*D)
    mma_gemm<<<dim3(S_ / 128, S_ / 128, NH_), 256, SMEM_GEMM>>>(
        qhat, (size_t)S_ * 2 * D_, khat, (size_t)S_ * 2 * D_, 2,
        nullptr, e, (size_t)S_ * S_, S_, 2 * D_, 2, rsum);

    // H2O: invl1, colsum, topk (emits heavy bitmask)
    invl_kernel<<<NH_ * S_ / 256, 256>>>(rsum, il1);
    colsum_kernel<<<dim3(S_ / 256, NH_), 256>>>();
    topk_kernel<<<NH_, 256>>>();

    // invl2 (sum-only; e untouched)
    rowsum2_kernel<<<dim3(S_ / 8, NH_), 256>>>();

    // fused masked PV -> aohat ([hi|lo] fp16), single-pass P, heavy blocks first
    pv_mma<<<dim3(S_ / 128, NH_), 256, SMEM_PV>>>(vthat, e, il2, hbits, aohat);

    // output projection (Kp = 2*HID)
    mma_gemm<<<dim3(HID_ / 128, S_ / 128, 1), 256, SMEM_GEMM>>>(
        aohat, 0, wot, 0, 0, out, nullptr, 0, HID_, 2 * HID_, 0, nullptr);
}

// round 12
// speedup vs baseline: 4.2077x; 1.0029x over previous
#include <cuda_runtime.h>
#include <cuda_fp16.h>
#include <math.h>
#include <stdint.h>

#define S_    2048
#define HID_  2048
#define NH_   16
#define NKV_  4
#define D_    128
#define HB_   204
#define RB_   204
#define SCALE_ 0.08838834764831845f
#define L2E_  1.4426950408889634f
#define QKVN_ 3072

// ----------------------------- scratch ---------------------------------
__device__ float g_qkv[S_ * QKVN_];                 // [s][ q(2048) | k(512) | v(512) ]
__device__ __half g_e[(size_t)NH_ * S_ * S_];       // exp(score) fp16; zero above diagonal
__device__ float g_rowsum[NH_ * S_];
__device__ float g_invl1[NH_ * S_], g_invl2[NH_ * S_];
__device__ float g_colsum[NH_ * S_];
__device__ int   g_heavylist[NH_ * HB_];
__device__ uint32_t g_heavybits[NH_ * 64];

__device__ __half g_xhat[(size_t)S_ * 2 * HID_];          // A-pattern [hi|lo]
__device__ __half g_wqkvt[(size_t)QKVN_ * 2 * HID_];      // B-pattern [b|b] (Wq|Wk|Wv)^T
__device__ __half g_wot[(size_t)HID_ * 2 * HID_];
__device__ __half g_qhat[(size_t)NH_ * S_ * 2 * D_];      // A-pattern [hi|lo]
__device__ __half g_khat[(size_t)NKV_ * S_ * 2 * D_];     // B-pattern [k|k]
__device__ __half g_vthat[(size_t)NKV_ * D_ * S_];        // single fp16 (V^T)
__device__ __half g_aohat[(size_t)S_ * 2 * HID_];         // A-pattern [hi|lo]

// ----------------------------- PTX helpers ------------------------------
__device__ __forceinline__ uint32_t smem_u32(const void* p) {
    uint32_t a;
    asm("{ .reg .u64 t; cvta.to.shared.u64 t, %1; cvt.u32.u64 %0, t; }" : "=r"(a) : "l"(p));
    return a;
}
__device__ __forceinline__ void cp16(uint32_t saddr, const void* gptr) {
    asm volatile("cp.async.cg.shared.global [%0], [%1], 16;" :: "r"(saddr), "l"(gptr));
}
__device__ __forceinline__ void cp_commit() { asm volatile("cp.async.commit_group;"); }
__device__ __forceinline__ void cp_wait0() { asm volatile("cp.async.wait_group 0;" ::: "memory"); }
__device__ __forceinline__ void cp_wait1() { asm volatile("cp.async.wait_group 1;" ::: "memory"); }

__device__ __forceinline__ void ldsm4(uint32_t& r0, uint32_t& r1, uint32_t& r2, uint32_t& r3,
                                      uint32_t addr) {
    asm volatile("ldmatrix.sync.aligned.m8n8.x4.shared.b16 {%0,%1,%2,%3}, [%4];"
                 : "=r"(r0), "=r"(r1), "=r"(r2), "=r"(r3) : "r"(addr));
}
__device__ __forceinline__ void mma16816(float* d, const uint32_t* a, const uint32_t* b) {
    asm volatile(
        "mma.sync.aligned.m16n8k16.row.col.f32.f16.f16.f32 "
        "{%0,%1,%2,%3}, {%4,%5,%6,%7}, {%8,%9}, {%0,%1,%2,%3};"
        : "+f"(d[0]), "+f"(d[1]), "+f"(d[2]), "+f"(d[3])
        : "r"(a[0]), "r"(a[1]), "r"(a[2]), "r"(a[3]), "r"(b[0]), "r"(b[1]));
}
__device__ __forceinline__ float fexp(float x) {   // e^x via MUFU
    float y;
    asm("ex2.approx.ftz.f32 %0, %1;" : "=f"(y) : "f"(x * L2E_));
    return y;
}
__device__ __forceinline__ float fexp2p3(float x) { // 2^x via FMA pipe, deg-3 (err ~6e-5)
    float n = rintf(x);
    float f = x - n;
    float p = 5.5490603e-2f;
    p = fmaf(p, f, 2.4022651e-1f);
    p = fmaf(p, f, 6.9315308e-1f);
    p = fmaf(p, f, 9.9999989e-1f);
    return p * __int_as_float(((int)n + 127) << 23);
}
__device__ __forceinline__ uint32_t split_packh(float p0, float p1, uint32_t& lo) {
    __half h0 = __float2half_rn(p0), h1 = __float2half_rn(p1);
    float f0 = __half2float(h0), f1 = __half2float(h1);
    __half l0 = __float2half_rn(p0 - f0), l1 = __float2half_rn(p1 - f1);
    lo = (uint32_t)__half_as_ushort(l0) | ((uint32_t)__half_as_ushort(l1) << 16);
    return (uint32_t)__half_as_ushort(h0) | ((uint32_t)__half_as_ushort(h1) << 16);
}
__device__ __forceinline__ uint32_t packh(float p0, float p1) {
    __half2 h = __floats2half2_rn(p0, p1);
    return *(uint32_t*)&h;
}

// ------------------------- HMMA GEMM -------------------------
__device__ __forceinline__ void load_tile_async(uint32_t sbase, const __half* src,
                                                int ld, int row0, int kbase, int tid) {
#pragma unroll
    for (int t = 0; t < 4; t++) {
        int u = tid + t * 256;
        int row = u >> 3, seg = u & 7;
        uint32_t bo = (uint32_t)(row * 128 + seg * 16);
        bo ^= (bo >> 3) & 0x70;
        cp16(sbase + bo, src + (size_t)(row0 + row) * ld + kbase + seg * 8);
    }
}

// mode 0: plain fp32 store to C.
// mode 2: Eh = fp16(exp(scale*s)) for j<=i (0 above), hybrid exp, fused row sums of rounded e.
// 3-stage cp.async pipeline, ONE __syncthreads per K-chunk.
__global__ __launch_bounds__(256, 2) void mma_gemm(
    const __half* __restrict__ A, size_t aStrideZ,
    const __half* __restrict__ Bt, size_t bStrideZ, int bShift,
    float* __restrict__ C, __half* __restrict__ Eh, size_t cStrideZ, int ldc,
    int Kp, int mode, float* __restrict__ rowsum) {
    int z = blockIdx.z;
    int i0 = blockIdx.y * 128, j0 = blockIdx.x * 128;
    if (mode == 2 && j0 > i0 + 127) return;   // fully above diagonal: skip

    const __half* Az = A + (size_t)z * aStrideZ;
    const __half* Bz = Bt + (size_t)(z >> bShift) * bStrideZ;
    int tid = threadIdx.x, wid = tid >> 5;
    uint32_t lane = tid & 31;

    extern __shared__ char dsm[];
    char* tile = (char*)(((uintptr_t)dsm + 1023) & ~(uintptr_t)1023);
    uint32_t sA[3] = { smem_u32(tile), smem_u32(tile) + 16384, smem_u32(tile) + 32768 };
    uint32_t sB[3] = { smem_u32(tile) + 49152, smem_u32(tile) + 65536, smem_u32(tile) + 81920 };

    int warp_m = wid >> 2;
    int warp_n = wid & 3;

    float acc[4][4][4];
#pragma unroll
    for (int i = 0; i < 4; i++)
#pragma unroll
        for (int j = 0; j < 4; j++)
#pragma unroll
            for (int r = 0; r < 4; r++) acc[i][j][r] = 0.f;

    const int NC = Kp >> 6;
    load_tile_async(sA[0], Az, Kp, i0, 0, tid);
    load_tile_async(sB[0], Bz, Kp, j0, 0, tid);
    cp_commit();
    if (NC > 1) {
        load_tile_async(sA[1], Az, Kp, i0, 64, tid);
        load_tile_async(sB[1], Bz, Kp, j0, 64, tid);
        cp_commit();
    }

    int cur = 0, nxt2 = 2;   // buffer indices mod 3
    for (int c = 0; c < NC; c++) {
        if (c + 1 < NC) cp_wait1(); else cp_wait0();
        __syncthreads();
        if (c + 2 < NC) {
            load_tile_async(sA[nxt2], Az, Kp, i0, (c + 2) * 64, tid);
            load_tile_async(sB[nxt2], Bz, Kp, j0, (c + 2) * 64, tid);
            cp_commit();
        }

        uint32_t a_base = sA[cur], b_base = sB[cur];
#pragma unroll
        for (int ks = 0; ks < 4; ks++) {
            uint32_t a[4][4], b[2][4];
#pragma unroll
            for (int mf = 0; mf < 4; mf++) {
                int row = 64 * warp_m + 16 * mf + (lane & 7) + (((lane >> 3) & 1) << 3);
                int colb = (16 * ks + (((lane >> 4) & 1) << 3)) * 2;
                uint32_t off = (uint32_t)(row * 128 + colb);
                off ^= (off >> 3) & 0x70;
                ldsm4(a[mf][0], a[mf][1], a[mf][2], a[mf][3], a_base + off);
            }
#pragma unroll
            for (int nf2 = 0; nf2 < 2; nf2++) {
                int row = 32 * warp_n + 16 * nf2 + (lane & 7) + (((lane >> 4) & 1) << 3);
                int colb = (16 * ks + (((lane >> 3) & 1) << 3)) * 2;
                uint32_t off = (uint32_t)(row * 128 + colb);
                off ^= (off >> 3) & 0x70;
                ldsm4(b[nf2][0], b[nf2][1], b[nf2][2], b[nf2][3], b_base + off);
            }
#pragma unroll
            for (int mf = 0; mf < 4; mf++)
#pragma unroll
                for (int nf = 0; nf < 4; nf++)
                    mma16816(acc[mf][nf], a[mf], &b[nf >> 1][(nf & 1) * 2]);
        }
        cur = (cur == 2) ? 0 : cur + 1;
        nxt2 = (nxt2 == 2) ? 0 : nxt2 + 1;
    }

    if (mode == 0) {
        float* Cz = C + (size_t)z * cStrideZ;
#pragma unroll
        for (int mf = 0; mf < 4; mf++) {
            int r0 = i0 + 64 * warp_m + 16 * mf + (int)(lane >> 2);
#pragma unroll
            for (int nf = 0; nf < 4; nf++) {
                int c0 = j0 + 32 * warp_n + 8 * nf + (int)(lane & 3) * 2;
                *(float2*)(Cz + (size_t)r0 * ldc + c0) = make_float2(acc[mf][nf][0], acc[mf][nf][1]);
                *(float2*)(Cz + (size_t)(r0 + 8) * ldc + c0) = make_float2(acc[mf][nf][2], acc[mf][nf][3]);
            }
        }
        return;
    }

    // mode 2: exp epilogue (10/16 MUFU + 6/16 deg-3 poly), fp16 store, fused row sums
    __half* Ez = Eh + (size_t)z * cStrideZ;
    const float cl = SCALE_ * L2E_;
    float rs0[4], rs1[4];
#pragma unroll
    for (int mf = 0; mf < 4; mf++) {
        int r0 = i0 + 64 * warp_m + 16 * mf + (int)(lane >> 2);
        float s0 = 0.f, s1 = 0.f;
#pragma unroll
        for (int nf = 0; nf < 4; nf++) {
            int c0 = j0 + 32 * warp_n + 8 * nf + (int)(lane & 3) * 2;
            float d0 = acc[mf][nf][0], d1 = acc[mf][nf][1];
            float d2 = acc[mf][nf][2], d3 = acc[mf][nf][3];
            if (nf < 2) {          // full MUFU
                d0 = (c0     <= r0)     ? fexp(d0 * SCALE_) : 0.f;
                d1 = (c0 + 1 <= r0)     ? fexp(d1 * SCALE_) : 0.f;
                d2 = (c0     <= r0 + 8) ? fexp(d2 * SCALE_) : 0.f;
                d3 = (c0 + 1 <= r0 + 8) ? fexp(d3 * SCALE_) : 0.f;
            } else if (nf == 2) {  // half MUFU, half poly
                d0 = (c0     <= r0)     ? fexp(d0 * SCALE_) : 0.f;
                d1 = (c0 + 1 <= r0)     ? fexp(d1 * SCALE_) : 0.f;
                d2 = (c0     <= r0 + 8) ? fexp2p3(d2 * cl) : 0.f;
                d3 = (c0 + 1 <= r0 + 8) ? fexp2p3(d3 * cl) : 0.f;
            } else {               // full poly
                d0 = (c0     <= r0)     ? fexp2p3(d0 * cl) : 0.f;
                d1 = (c0 + 1 <= r0)     ? fexp2p3(d1 * cl) : 0.f;
                d2 = (c0     <= r0 + 8) ? fexp2p3(d2 * cl) : 0.f;
                d3 = (c0 + 1 <= r0 + 8) ? fexp2p3(d3 * cl) : 0.f;
            }
            __half2 h01 = __floats2half2_rn(d0, d1);
            __half2 h23 = __floats2half2_rn(d2, d3);
            *(uint32_t*)(Ez + (size_t)r0 * ldc + c0) = *(uint32_t*)&h01;
            *(uint32_t*)(Ez + (size_t)(r0 + 8) * ldc + c0) = *(uint32_t*)&h23;
            float2 f01 = __half22float2(h01);
            float2 f23 = __half22float2(h23);
            s0 += f01.x + f01.y;
            s1 += f23.x + f23.y;
        }
        rs0[mf] = s0; rs1[mf] = s1;
    }
    {
        float* rz = rowsum + (size_t)z * S_;
#pragma unroll
        for (int mf = 0; mf < 4; mf++) {
            float v0 = rs0[mf], v1 = rs1[mf];
            v0 += __shfl_xor_sync(0xFFFFFFFF, v0, 1);
            v0 += __shfl_xor_sync(0xFFFFFFFF, v0, 2);
            v1 += __shfl_xor_sync(0xFFFFFFFF, v1, 1);
            v1 += __shfl_xor_sync(0xFFFFFFFF, v1, 2);
            if ((lane & 3) == 0) {
                int r0 = i0 + 64 * warp_m + 16 * mf + (int)(lane >> 2);
                atomicAdd(rz + r0, v0);
                atomicAdd(rz + r0 + 8, v1);
            }
        }
    }
}

// ------------------ fused PV (masked P on the fly, single-pass fp16) --------------
__global__ __launch_bounds__(256, 2) void pv_mma(
    const __half* __restrict__ vthat,
    const __half* __restrict__ e, const float* __restrict__ invl2,
    const uint32_t* __restrict__ heavybits,
    __half* __restrict__ aohat) {
    int i0 = (int)(gridDim.x - 1 - blockIdx.x) * 128;   // heavy blocks first
    int h = blockIdx.y, kh = h >> 2;
    int tid = threadIdx.x, wid = tid >> 5;
    uint32_t lane = tid & 31;
    int warp_m = wid >> 2, warp_n = wid & 3;

    extern __shared__ char dsm[];
    char* tile = (char*)(((uintptr_t)dsm + 1023) & ~(uintptr_t)1023);
    char* pP = tile;                                   // 16 KB P tile (fp16)
    uint32_t sP = smem_u32(pP);
    uint32_t sV[2] = { smem_u32(tile) + 16384, smem_u32(tile) + 32768 };

    __shared__ uint32_t sbits[64];
    if (tid < 64) sbits[tid] = heavybits[h * 64 + tid];

    int r = tid >> 1, half = tid & 1;
    int gi = i0 + r;
    float il = invl2[h * S_ + gi];
    const __half* erow = e + ((size_t)h * S_ + gi) * S_ + half * 32;
    const __half* Vz = vthat + (size_t)kh * D_ * S_;

    float acc[4][4][4];
#pragma unroll
    for (int i = 0; i < 4; i++)
#pragma unroll
        for (int j = 0; j < 4; j++)
#pragma unroll
            for (int q = 0; q < 4; q++) acc[i][j][q] = 0.f;

    const int NCH = (i0 >> 6) + 2;
    load_tile_async(sV[0], Vz, S_, 0, 0, tid);
    cp_commit();
    __syncthreads();   // sbits visible

    for (int c = 0; c < NCH; c++) {
        int j0 = c * 64;
        bool pre = (c + 1 < NCH);
        if (pre) {
            load_tile_async(sV[(c + 1) & 1], Vz, S_, 0, (c + 1) * 64, tid);
            cp_commit();
        }
        // build masked fp16 P tile (row r, 32 cols starting at j0 + half*32)
        uint32_t hib[16];
        const __half* ep = erow + j0;
        int gjb = j0 + half * 32;
#pragma unroll
        for (int w = 0; w < 4; w++) {
            uint4 ev = *(const uint4*)(ep + w * 8);
            float2 f0 = __half22float2(*(__half2*)&ev.x);
            float2 f1 = __half22float2(*(__half2*)&ev.y);
            float2 f2 = __half22float2(*(__half2*)&ev.z);
            float2 f3 = __half22float2(*(__half2*)&ev.w);
            float pv[8] = { f0.x, f0.y, f1.x, f1.y, f2.x, f2.y, f3.x, f3.y };
#pragma unroll
            for (int u = 0; u < 8; u++) {
                int gj = gjb + w * 8 + u;
                bool keep = (gj <= gi) &&
                            ((gi - gj <= RB_) || ((sbits[gj >> 5] >> (gj & 31)) & 1u));
                pv[u] = keep ? pv[u] * il : 0.f;
            }
            hib[w * 4 + 0] = packh(pv[0], pv[1]);
            hib[w * 4 + 1] = packh(pv[2], pv[3]);
            hib[w * 4 + 2] = packh(pv[4], pv[5]);
            hib[w * 4 + 3] = packh(pv[6], pv[7]);
        }
#pragma unroll
        for (int sg = 0; sg < 4; sg++) {
            uint32_t bo = (uint32_t)(r * 128 + half * 64 + sg * 16);
            bo ^= (bo >> 3) & 0x70;
            *(uint4*)(pP + bo) = make_uint4(hib[sg * 4], hib[sg * 4 + 1], hib[sg * 4 + 2], hib[sg * 4 + 3]);
        }
        if (pre) cp_wait1(); else cp_wait0();
        __syncthreads();

        uint32_t b_base = sV[c & 1];
#pragma unroll
        for (int ks = 0; ks < 4; ks++) {
            uint32_t a[4][4], b[2][4];
#pragma unroll
            for (int mf = 0; mf < 4; mf++) {
                int row = 64 * warp_m + 16 * mf + (lane & 7) + (((lane >> 3) & 1) << 3);
                int colb = (16 * ks + (((lane >> 4) & 1) << 3)) * 2;
                uint32_t off = (uint32_t)(row * 128 + colb);
                off ^= (off >> 3) & 0x70;
                ldsm4(a[mf][0], a[mf][1], a[mf][2], a[mf][3], sP + off);
            }
#pragma unroll
            for (int nf2 = 0; nf2 < 2; nf2++) {
                int row = 32 * warp_n + 16 * nf2 + (lane & 7) + (((lane >> 4) & 1) << 3);
                int colb = (16 * ks + (((lane >> 3) & 1) << 3)) * 2;
                uint32_t off = (uint32_t)(row * 128 + colb);
                off ^= (off >> 3) & 0x70;
                ldsm4(b[nf2][0], b[nf2][1], b[nf2][2], b[nf2][3], b_base + off);
            }
#pragma unroll
            for (int mf = 0; mf < 4; mf++)
#pragma unroll
                for (int nf = 0; nf < 4; nf++)
                    mma16816(acc[mf][nf], a[mf], &b[nf >> 1][(nf & 1) * 2]);
        }
        __syncthreads();
    }

    // epilogue: write split aohat (pattern A: [hi|lo], row width 2*HID)
#pragma unroll
    for (int mf = 0; mf < 4; mf++) {
        int r0 = i0 + 64 * warp_m + 16 * mf + (int)(lane >> 2);
#pragma unroll
        for (int nf = 0; nf < 4; nf++) {
            int c0 = 32 * warp_n + 8 * nf + (int)(lane & 3) * 2;
#pragma unroll
            for (int rr = 0; rr < 2; rr++) {
                float d0 = acc[mf][nf][rr * 2], d1 = acc[mf][nf][rr * 2 + 1];
                uint32_t lo, hi = split_packh(d0, d1, lo);
                size_t b0 = (size_t)(r0 + rr * 8) * (2 * HID_) + h * D_ + c0;
                *(uint32_t*)(aohat + b0) = hi;
                *(uint32_t*)(aohat + b0 + HID_) = lo;
            }
        }
    }
}

// ----------------------- split-fp16 conversion kernels -------------------
__global__ void split_plain(const float* __restrict__ A, __half* __restrict__ out,
                            int M, int K) {  // pattern A: [hi|lo]
    int idx = blockIdx.x * blockDim.x + threadIdx.x;
    if (idx >= M * K) return;
    int m = idx / K, k = idx - m * K;
    float x = A[idx];
    __half hi = __float2half_rn(x);
    __half lo = __float2half_rn(x - __half2float(hi));
    size_t base = (size_t)m * 2 * K;
    out[base + k] = hi; out[base + K + k] = lo;
}

__global__ void split_heads(const float* __restrict__ src, int ld,
                            __half* __restrict__ out, int nh, int patternB) {
    int idx = blockIdx.x * blockDim.x + threadIdx.x;
    if (idx >= S_ * nh * D_) return;
    int d = idx & 127;
    int h = (idx >> 7) % nh;
    int s = idx / (nh * D_);
    float x = src[(size_t)s * ld + h * D_ + d];
    __half hi = __float2half_rn(x);
    size_t base = ((size_t)h * S_ + s) * (2 * D_);
    if (patternB) {  // [k|k] duplicated
        out[base + d] = hi; out[base + D_ + d] = hi;
    } else {         // [hi|lo]
        __half lo = __float2half_rn(x - __half2float(hi));
        out[base + d] = hi; out[base + D_ + d] = lo;
    }
}

// transpose + fp16: dup=1 -> [b|b] (width 2K); dup=0 -> single (width K)
__global__ void transpose_split(const float* __restrict__ src, int ldsrc, int K, int Nper,
                                __half* __restrict__ out, int dup) {
    int z = blockIdx.z;
    const float* s = src + (size_t)z * Nper;
    int width = dup ? 2 * K : K;
    __half* o = out + (size_t)z * Nper * width;
    __shared__ float t[32][33];
    int k0 = blockIdx.y * 32, n0 = blockIdx.x * 32;
    int tx = threadIdx.x, ty = threadIdx.y;
#pragma unroll
    for (int r = 0; r < 4; r++) {
        int k = k0 + ty + 8 * r;
        t[ty + 8 * r][tx] = s[(size_t)k * ldsrc + n0 + tx];
    }
    __syncthreads();
#pragma unroll
    for (int r = 0; r < 4; r++) {
        int n = n0 + ty + 8 * r, k = k0 + tx;
        __half hh = __float2half_rn(t[tx][ty + 8 * r]);
        size_t base = (size_t)n * width;
        o[base + k] = hh;
        if (dup) o[base + K + k] = hh;
    }
}

// --------------------------------- RoPE ---------------------------------
__global__ void rope_kernel(float* x, int nh, int ld) {
    int idx = blockIdx.x * blockDim.x + threadIdx.x;
    if (idx >= S_ * nh * 64) return;
    int d = idx & 63;
    int rest = idx >> 6;
    int h = rest % nh;
    int s = rest / nh;
    float* base = x + (size_t)s * ld + h * 128;
    float x1 = base[d], x2 = base[d + 64];
    float inv = powf(10000.f, -(float)d * (1.f / 64.f));
    float ang = (float)s * inv;
    float c, sn;
    sincosf(ang, &sn, &c);
    base[d] = x1 * c - x2 * sn;
    base[d + 64] = x2 * c + x1 * sn;
}

// ------------------ invl1 = 1 / rowsum -----------------------------------
__global__ void invl_kernel(const float* __restrict__ rs, float* __restrict__ il) {
    int i = blockIdx.x * 256 + threadIdx.x;
    il[i] = 1.f / rs[i];
}

// coalesced column sums over fp16 e (rows above diagonal are exactly zero)
__global__ __launch_bounds__(256) void colsum_kernel() {
    int h = blockIdx.y;
    int j0 = blockIdx.x * 256;
    int j = j0 + threadIdx.x;
    const __half* base = g_e + (size_t)h * S_ * S_;
    __shared__ float il[S_];
    for (int i = j0 + threadIdx.x; i < S_; i += 256)
        il[i] = g_invl1[h * S_ + i];
    __syncthreads();
    float a0 = 0.f, a1 = 0.f, a2 = 0.f, a3 = 0.f;
    for (int i = j0; i < S_; i += 4) {
        a0 += __half2float(base[(size_t)(i    ) * S_ + j]) * il[i];
        a1 += __half2float(base[(size_t)(i + 1) * S_ + j]) * il[i + 1];
        a2 += __half2float(base[(size_t)(i + 2) * S_ + j]) * il[i + 2];
        a3 += __half2float(base[(size_t)(i + 3) * S_ + j]) * il[i + 3];
    }
    g_colsum[h * S_ + j] = (a0 + a1) + (a2 + a3);
}

__global__ __launch_bounds__(256) void topk_kernel() {
    int h = blockIdx.x;
    int tid = threadIdx.x;
    int lane = tid & 31, w = tid >> 5;
    __shared__ float vals[S_];
    __shared__ float wbv[8];
    __shared__ int wbi[8];
    __shared__ uint32_t bits[64];
    for (int j = tid; j < S_; j += 256) vals[j] = g_colsum[h * S_ + j];
    if (tid < 64) bits[tid] = 0;
    __syncthreads();
    for (int it = 0; it < HB_; it++) {
        float best = -INFINITY; int besti = 1 << 30;
        for (int j = tid; j < S_; j += 256) {
            float v = vals[j];
            if (v > best || (v == best && j < besti)) { best = v; besti = j; }
        }
#pragma unroll
        for (int off = 16; off > 0; off >>= 1) {
            float ov = __shfl_xor_sync(0xFFFFFFFF, best, off);
            int oi = __shfl_xor_sync(0xFFFFFFFF, besti, off);
            if (ov > best || (ov == best && oi < besti)) { best = ov; besti = oi; }
        }
        if (lane == 0) { wbv[w] = best; wbi[w] = besti; }
        __syncthreads();
        if (tid == 0) {
            float b = wbv[0]; int bi2 = wbi[0];
#pragma unroll
            for (int q = 1; q < 8; q++)
                if (wbv[q] > b || (wbv[q] == b && wbi[q] < bi2)) { b = wbv[q]; bi2 = wbi[q]; }
            g_heavylist[h * HB_ + it] = bi2;
            bits[bi2 >> 5] |= (1u << (bi2 & 31));
            vals[bi2] = -INFINITY;
        }
        __syncthreads();
    }
    if (tid < 64) g_heavybits[h * 64 + tid] = bits[tid];
}

// ------ pass-2: invl2 = 1/sum(e over band + heavy) ------
__global__ __launch_bounds__(256) void rowsum2_kernel() {
    int h = blockIdx.y;
    int tid = threadIdx.x;
    __shared__ int hl[HB_];
    for (int t = tid; t < HB_; t += 256) hl[t] = g_heavylist[h * HB_ + t];
    __syncthreads();

    int w = tid >> 5, lane = tid & 31;
    int i = blockIdx.x * 8 + w;
    const __half* erow = g_e + (size_t)(h * S_ + i) * S_;
    int lo = i - RB_; if (lo < 0) lo = 0;

    float l = 0.f;
    for (int j = lo + lane; j <= i; j += 32) l += __half2float(erow[j]);
    for (int t = lane; t < HB_; t += 32) {
        int j = hl[t];
        if (j < lo) l += __half2float(erow[j]);
    }
#pragma unroll
    for (int off = 16; off > 0; off >>= 1)
        l += __shfl_xor_sync(0xFFFFFFFF, l, off);
    if (lane == 0) g_invl2[h * S_ + i] = 1.f / l;
}

// ------------------------------ launcher ---------------------------------
extern "C" void kernel_launch(void* const* d_in, const int* in_sizes, int n_in,
                              void* d_out, int out_size) {
    const float* hidden = (const float*)d_in[0];
    const float* Wq = (const float*)d_in[1];
    const float* Wk = (const float*)d_in[2];
    const float* Wv = (const float*)d_in[3];
    const float* Wo = (const float*)d_in[4];
    float* out = (float*)d_out;

    float *qkv, *rsum, *il1, *il2;
    __half* e;
    uint32_t* hbits;
    __half *xhat, *wqkvt, *wot, *qhat, *khat, *vthat, *aohat;
    cudaGetSymbolAddress((void**)&qkv, g_qkv);
    cudaGetSymbolAddress((void**)&e, g_e);
    cudaGetSymbolAddress((void**)&rsum, g_rowsum);
    cudaGetSymbolAddress((void**)&il1, g_invl1);
    cudaGetSymbolAddress((void**)&il2, g_invl2);
    cudaGetSymbolAddress((void**)&hbits, g_heavybits);
    cudaGetSymbolAddress((void**)&xhat, g_xhat);
    cudaGetSymbolAddress((void**)&wqkvt, g_wqkvt);
    cudaGetSymbolAddress((void**)&wot, g_wot);
    cudaGetSymbolAddress((void**)&qhat, g_qhat);
    cudaGetSymbolAddress((void**)&khat, g_khat);
    cudaGetSymbolAddress((void**)&vthat, g_vthat);
    cudaGetSymbolAddress((void**)&aohat, g_aohat);

    const int SMEM_GEMM = 99328;   // 3-stage: 3*(16K+16K) + 1K align
    const int SMEM_PV = 50176;
    cudaFuncSetAttribute(mma_gemm, cudaFuncAttributeMaxDynamicSharedMemorySize, SMEM_GEMM);
    cudaFuncSetAttribute(pv_mma, cudaFuncAttributeMaxDynamicSharedMemorySize, SMEM_PV);

    // 1-4: splits needed for QKV; QKV mma is the 5th launch (ncu capture slot)
    split_plain<<<(S_ * HID_ + 255) / 256, 256>>>(hidden, xhat, S_, HID_);
    transpose_split<<<dim3(HID_ / 32, HID_ / 32, 1), dim3(32, 8)>>>(Wq, HID_, HID_, HID_, wqkvt, 1);
    transpose_split<<<dim3((NKV_ * D_) / 32, HID_ / 32, 1), dim3(32, 8)>>>(
        Wk, NKV_ * D_, HID_, NKV_ * D_, wqkvt + (size_t)HID_ * 2 * HID_, 1);
    transpose_split<<<dim3((NKV_ * D_) / 32, HID_ / 32, 1), dim3(32, 8)>>>(
        Wv, NKV_ * D_, HID_, NKV_ * D_, wqkvt + (size_t)(HID_ + NKV_ * D_) * 2 * HID_, 1);

    // 5. fused QKV projection (one GEMM, N=3072, Kp = 2*HID)
    mma_gemm<<<dim3(QKVN_ / 128, S_ / 128, 1), 256, SMEM_GEMM>>>(
        xhat, 0, wqkvt, 0, 0, qkv, nullptr, 0, QKVN_, 2 * HID_, 0, nullptr);

    transpose_split<<<dim3(HID_ / 32, HID_ / 32, 1), dim3(32, 8)>>>(Wo, HID_, HID_, HID_, wot, 1);

    // RoPE (in place inside g_qkv)
    rope_kernel<<<(S_ * NH_ * 64 + 255) / 256, 256>>>(qkv, NH_, QKVN_);
    rope_kernel<<<(S_ * NKV_ * 64 + 255) / 256, 256>>>(qkv + HID_, NKV_, QKVN_);

    // split roped Q ([hi|lo]) / K ([k|k]); transpose V -> single fp16 V^T
    split_heads<<<(S_ * NH_ * D_ + 255) / 256, 256>>>(qkv, QKVN_, qhat, NH_, 0);
    split_heads<<<(S_ * NKV_ * D_ + 255) / 256, 256>>>(qkv + HID_, QKVN_, khat, NKV_, 1);
    transpose_split<<<dim3(D_ / 32, S_ / 32, NKV_), dim3(32, 8)>>>(
        qkv + HID_ + NKV_ * D_, QKVN_, S_, D_, vthat, 0);

    // zero rowsum accumulator (captured node, re-zeroed every replay)
    cudaMemsetAsync(rsum, 0, NH_ * S_ * sizeof(float));

    // e = fp16(exp(scale * QK^T)) + fused row sums (Kp = 2*D)
    mma_gemm<<<dim3(S_ / 128, S_ / 128, NH_), 256, SMEM_GEMM>>>(
        qhat, (size_t)S_ * 2 * D_, khat, (size_t)S_ * 2 * D_, 2,
        nullptr, e, (size_t)S_ * S_, S_, 2 * D_, 2, rsum);

    // H2O: invl1, colsum, topk (emits heavy bitmask)
    invl_kernel<<<NH_ * S_ / 256, 256>>>(rsum, il1);
    colsum_kernel<<<dim3(S_ / 256, NH_), 256>>>();
    topk_kernel<<<NH_, 256>>>();

    // invl2 (sum-only; e untouched)
    rowsum2_kernel<<<dim3(S_ / 8, NH_), 256>>>();

    // fused masked PV -> aohat ([hi|lo] fp16), single-pass P, heavy blocks first
    pv_mma<<<dim3(S_ / 128, NH_), 256, SMEM_PV>>>(vthat, e, il2, hbits, aohat);

    // output projection (Kp = 2*HID)
    mma_gemm<<<dim3(HID_ / 128, S_ / 128, 1), 256, SMEM_GEMM>>>(
        aohat, 0, wot, 0, 0, out, nullptr, 0, HID_, 2 * HID_, 0, nullptr);
}

// round 13
// speedup vs baseline: 4.5045x; 1.0705x over previous
#include <cuda_runtime.h>
#include <cuda_fp16.h>
#include <math.h>
#include <stdint.h>

#define S_    2048
#define HID_  2048
#define NH_   16
#define NKV_  4
#define D_    128
#define HB_   204
#define RB_   204
#define SCALE_ 0.08838834764831845f
#define L2E_  1.4426950408889634f
#define QKVN_ 3072

// ----------------------------- scratch ---------------------------------
__device__ float g_qkv[S_ * QKVN_];                 // [s][ q(2048) | k(512) | v(512) ]
__device__ __half g_e[(size_t)NH_ * S_ * S_];       // exp(score) fp16; zero above diagonal
__device__ float g_rowsum[NH_ * S_];
__device__ float g_invl1[NH_ * S_], g_invl2[NH_ * S_];
__device__ float g_colsum[NH_ * S_];
__device__ int   g_heavylist[NH_ * HB_];
__device__ uint32_t g_heavybits[NH_ * 64];

__device__ __half g_xhat[(size_t)S_ * 2 * HID_];          // A-pattern [hi|lo]
__device__ __half g_wqkvt[(size_t)QKVN_ * 2 * HID_];      // B-pattern [b|b] (Wq|Wk|Wv)^T
__device__ __half g_wot[(size_t)HID_ * HID_];             // single fp16 Wo^T
__device__ __half g_qhat[(size_t)NH_ * S_ * 2 * D_];      // A-pattern [hi|lo]
__device__ __half g_khat[(size_t)NKV_ * S_ * 2 * D_];     // B-pattern [k|k]
__device__ __half g_vthat[(size_t)NKV_ * D_ * S_];        // single fp16 (V^T)
__device__ __half g_aohat[(size_t)S_ * HID_];             // single fp16 attention out

// ----------------------------- PTX helpers ------------------------------
__device__ __forceinline__ uint32_t smem_u32(const void* p) {
    uint32_t a;
    asm("{ .reg .u64 t; cvta.to.shared.u64 t, %1; cvt.u32.u64 %0, t; }" : "=r"(a) : "l"(p));
    return a;
}
__device__ __forceinline__ void cp16(uint32_t saddr, const void* gptr) {
    asm volatile("cp.async.cg.shared.global [%0], [%1], 16;" :: "r"(saddr), "l"(gptr));
}
__device__ __forceinline__ void cp_commit() { asm volatile("cp.async.commit_group;"); }
__device__ __forceinline__ void cp_wait0() { asm volatile("cp.async.wait_group 0;" ::: "memory"); }
__device__ __forceinline__ void cp_wait1() { asm volatile("cp.async.wait_group 1;" ::: "memory"); }

__device__ __forceinline__ void ldsm4(uint32_t& r0, uint32_t& r1, uint32_t& r2, uint32_t& r3,
                                      uint32_t addr) {
    asm volatile("ldmatrix.sync.aligned.m8n8.x4.shared.b16 {%0,%1,%2,%3}, [%4];"
                 : "=r"(r0), "=r"(r1), "=r"(r2), "=r"(r3) : "r"(addr));
}
__device__ __forceinline__ void mma16816(float* d, const uint32_t* a, const uint32_t* b) {
    asm volatile(
        "mma.sync.aligned.m16n8k16.row.col.f32.f16.f16.f32 "
        "{%0,%1,%2,%3}, {%4,%5,%6,%7}, {%8,%9}, {%0,%1,%2,%3};"
        : "+f"(d[0]), "+f"(d[1]), "+f"(d[2]), "+f"(d[3])
        : "r"(a[0]), "r"(a[1]), "r"(a[2]), "r"(a[3]), "r"(b[0]), "r"(b[1]));
}
__device__ __forceinline__ float fexp(float x) {   // e^x via MUFU
    float y;
    asm("ex2.approx.ftz.f32 %0, %1;" : "=f"(y) : "f"(x * L2E_));
    return y;
}
__device__ __forceinline__ float fexp2p3(float x) { // 2^x via FMA pipe, deg-3 (err ~6e-5)
    float n = rintf(x);
    float f = x - n;
    float p = 5.5490603e-2f;
    p = fmaf(p, f, 2.4022651e-1f);
    p = fmaf(p, f, 6.9315308e-1f);
    p = fmaf(p, f, 9.9999989e-1f);
    return p * __int_as_float(((int)n + 127) << 23);
}
__device__ __forceinline__ uint32_t packh(float p0, float p1) {
    __half2 h = __floats2half2_rn(p0, p1);
    return *(uint32_t*)&h;
}

// ------------------------- HMMA GEMM -------------------------
__device__ __forceinline__ void load_tile_async(uint32_t sbase, const __half* src,
                                                int ld, int row0, int kbase, int tid) {
#pragma unroll
    for (int t = 0; t < 4; t++) {
        int u = tid + t * 256;
        int row = u >> 3, seg = u & 7;
        uint32_t bo = (uint32_t)(row * 128 + seg * 16);
        bo ^= (bo >> 3) & 0x70;
        cp16(sbase + bo, src + (size_t)(row0 + row) * ld + kbase + seg * 8);
    }
}

// mode 0: plain fp32 store to C.
// mode 2: Eh = fp16(exp(scale*s)) for j<=i (0 above), hybrid exp, fused row sums of rounded e.
__global__ __launch_bounds__(256, 2) void mma_gemm(
    const __half* __restrict__ A, size_t aStrideZ,
    const __half* __restrict__ Bt, size_t bStrideZ, int bShift,
    float* __restrict__ C, __half* __restrict__ Eh, size_t cStrideZ, int ldc,
    int Kp, int mode, float* __restrict__ rowsum) {
    int z = blockIdx.z;
    int i0 = blockIdx.y * 128, j0 = blockIdx.x * 128;
    if (mode == 2 && j0 > i0 + 127) return;   // fully above diagonal: skip

    const __half* Az = A + (size_t)z * aStrideZ;
    const __half* Bz = Bt + (size_t)(z >> bShift) * bStrideZ;
    int tid = threadIdx.x, wid = tid >> 5;
    uint32_t lane = tid & 31;

    extern __shared__ char dsm[];
    char* tile = (char*)(((uintptr_t)dsm + 1023) & ~(uintptr_t)1023);
    uint32_t sA[2] = { smem_u32(tile), smem_u32(tile) + 16384 };
    uint32_t sB[2] = { smem_u32(tile) + 32768, smem_u32(tile) + 49152 };

    int warp_m = wid >> 2;
    int warp_n = wid & 3;

    float acc[4][4][4];
#pragma unroll
    for (int i = 0; i < 4; i++)
#pragma unroll
        for (int j = 0; j < 4; j++)
#pragma unroll
            for (int r = 0; r < 4; r++) acc[i][j][r] = 0.f;

    load_tile_async(sA[0], Az, Kp, i0, 0, tid);
    load_tile_async(sB[0], Bz, Kp, j0, 0, tid);
    cp_commit();

    const int NC = Kp >> 6;
    for (int c = 0; c < NC; c++) {
        if (c + 1 < NC) {
            load_tile_async(sA[(c + 1) & 1], Az, Kp, i0, (c + 1) * 64, tid);
            load_tile_async(sB[(c + 1) & 1], Bz, Kp, j0, (c + 1) * 64, tid);
            cp_commit();
            cp_wait1();
        } else {
            cp_wait0();
        }
        __syncthreads();

        uint32_t a_base = sA[c & 1], b_base = sB[c & 1];
#pragma unroll
        for (int ks = 0; ks < 4; ks++) {
            uint32_t a[4][4], b[2][4];
#pragma unroll
            for (int mf = 0; mf < 4; mf++) {
                int row = 64 * warp_m + 16 * mf + (lane & 7) + (((lane >> 3) & 1) << 3);
                int colb = (16 * ks + (((lane >> 4) & 1) << 3)) * 2;
                uint32_t off = (uint32_t)(row * 128 + colb);
                off ^= (off >> 3) & 0x70;
                ldsm4(a[mf][0], a[mf][1], a[mf][2], a[mf][3], a_base + off);
            }
#pragma unroll
            for (int nf2 = 0; nf2 < 2; nf2++) {
                int row = 32 * warp_n + 16 * nf2 + (lane & 7) + (((lane >> 4) & 1) << 3);
                int colb = (16 * ks + (((lane >> 3) & 1) << 3)) * 2;
                uint32_t off = (uint32_t)(row * 128 + colb);
                off ^= (off >> 3) & 0x70;
                ldsm4(b[nf2][0], b[nf2][1], b[nf2][2], b[nf2][3], b_base + off);
            }
#pragma unroll
            for (int mf = 0; mf < 4; mf++)
#pragma unroll
                for (int nf = 0; nf < 4; nf++)
                    mma16816(acc[mf][nf], a[mf], &b[nf >> 1][(nf & 1) * 2]);
        }
        __syncthreads();
    }

    if (mode == 0) {
        float* Cz = C + (size_t)z * cStrideZ;
#pragma unroll
        for (int mf = 0; mf < 4; mf++) {
            int r0 = i0 + 64 * warp_m + 16 * mf + (int)(lane >> 2);
#pragma unroll
            for (int nf = 0; nf < 4; nf++) {
                int c0 = j0 + 32 * warp_n + 8 * nf + (int)(lane & 3) * 2;
                *(float2*)(Cz + (size_t)r0 * ldc + c0) = make_float2(acc[mf][nf][0], acc[mf][nf][1]);
                *(float2*)(Cz + (size_t)(r0 + 8) * ldc + c0) = make_float2(acc[mf][nf][2], acc[mf][nf][3]);
            }
        }
        return;
    }

    // mode 2: exp epilogue (10/16 MUFU + 6/16 deg-3 poly), fp16 store, fused row sums
    __half* Ez = Eh + (size_t)z * cStrideZ;
    const float cl = SCALE_ * L2E_;
    float rs0[4], rs1[4];
#pragma unroll
    for (int mf = 0; mf < 4; mf++) {
        int r0 = i0 + 64 * warp_m + 16 * mf + (int)(lane >> 2);
        float s0 = 0.f, s1 = 0.f;
#pragma unroll
        for (int nf = 0; nf < 4; nf++) {
            int c0 = j0 + 32 * warp_n + 8 * nf + (int)(lane & 3) * 2;
            float d0 = acc[mf][nf][0], d1 = acc[mf][nf][1];
            float d2 = acc[mf][nf][2], d3 = acc[mf][nf][3];
            if (nf < 2) {          // full MUFU
                d0 = (c0     <= r0)     ? fexp(d0 * SCALE_) : 0.f;
                d1 = (c0 + 1 <= r0)     ? fexp(d1 * SCALE_) : 0.f;
                d2 = (c0     <= r0 + 8) ? fexp(d2 * SCALE_) : 0.f;
                d3 = (c0 + 1 <= r0 + 8) ? fexp(d3 * SCALE_) : 0.f;
            } else if (nf == 2) {  // half MUFU, half poly
                d0 = (c0     <= r0)     ? fexp(d0 * SCALE_) : 0.f;
                d1 = (c0 + 1 <= r0)     ? fexp(d1 * SCALE_) : 0.f;
                d2 = (c0     <= r0 + 8) ? fexp2p3(d2 * cl) : 0.f;
                d3 = (c0 + 1 <= r0 + 8) ? fexp2p3(d3 * cl) : 0.f;
            } else {               // full poly
                d0 = (c0     <= r0)     ? fexp2p3(d0 * cl) : 0.f;
                d1 = (c0 + 1 <= r0)     ? fexp2p3(d1 * cl) : 0.f;
                d2 = (c0     <= r0 + 8) ? fexp2p3(d2 * cl) : 0.f;
                d3 = (c0 + 1 <= r0 + 8) ? fexp2p3(d3 * cl) : 0.f;
            }
            __half2 h01 = __floats2half2_rn(d0, d1);
            __half2 h23 = __floats2half2_rn(d2, d3);
            *(uint32_t*)(Ez + (size_t)r0 * ldc + c0) = *(uint32_t*)&h01;
            *(uint32_t*)(Ez + (size_t)(r0 + 8) * ldc + c0) = *(uint32_t*)&h23;
            float2 f01 = __half22float2(h01);
            float2 f23 = __half22float2(h23);
            s0 += f01.x + f01.y;
            s1 += f23.x + f23.y;
        }
        rs0[mf] = s0; rs1[mf] = s1;
    }
    {
        float* rz = rowsum + (size_t)z * S_;
#pragma unroll
        for (int mf = 0; mf < 4; mf++) {
            float v0 = rs0[mf], v1 = rs1[mf];
            v0 += __shfl_xor_sync(0xFFFFFFFF, v0, 1);
            v0 += __shfl_xor_sync(0xFFFFFFFF, v0, 2);
            v1 += __shfl_xor_sync(0xFFFFFFFF, v1, 1);
            v1 += __shfl_xor_sync(0xFFFFFFFF, v1, 2);
            if ((lane & 3) == 0) {
                int r0 = i0 + 64 * warp_m + 16 * mf + (int)(lane >> 2);
                atomicAdd(rz + r0, v0);
                atomicAdd(rz + r0 + 8, v1);
            }
        }
    }
}

// ------------------ fused PV (masked P on the fly, single-pass fp16) --------------
__global__ __launch_bounds__(256, 2) void pv_mma(
    const __half* __restrict__ vthat,
    const __half* __restrict__ e, const float* __restrict__ invl2,
    const uint32_t* __restrict__ heavybits,
    __half* __restrict__ aohat) {
    int i0 = (int)(gridDim.x - 1 - blockIdx.x) * 128;   // heavy blocks first
    int h = blockIdx.y, kh = h >> 2;
    int tid = threadIdx.x, wid = tid >> 5;
    uint32_t lane = tid & 31;
    int warp_m = wid >> 2, warp_n = wid & 3;

    extern __shared__ char dsm[];
    char* tile = (char*)(((uintptr_t)dsm + 1023) & ~(uintptr_t)1023);
    char* pP = tile;                                   // 16 KB P tile (fp16)
    uint32_t sP = smem_u32(pP);
    uint32_t sV[2] = { smem_u32(tile) + 16384, smem_u32(tile) + 32768 };

    __shared__ uint32_t sbits[64];
    if (tid < 64) sbits[tid] = heavybits[h * 64 + tid];

    int r = tid >> 1, half = tid & 1;
    int gi = i0 + r;
    float il = invl2[h * S_ + gi];
    const __half* erow = e + ((size_t)h * S_ + gi) * S_ + half * 32;
    const __half* Vz = vthat + (size_t)kh * D_ * S_;

    float acc[4][4][4];
#pragma unroll
    for (int i = 0; i < 4; i++)
#pragma unroll
        for (int j = 0; j < 4; j++)
#pragma unroll
            for (int q = 0; q < 4; q++) acc[i][j][q] = 0.f;

    const int NCH = (i0 >> 6) + 2;
    load_tile_async(sV[0], Vz, S_, 0, 0, tid);
    cp_commit();
    __syncthreads();   // sbits visible

    for (int c = 0; c < NCH; c++) {
        int j0 = c * 64;
        bool pre = (c + 1 < NCH);
        if (pre) {
            load_tile_async(sV[(c + 1) & 1], Vz, S_, 0, (c + 1) * 64, tid);
            cp_commit();
        }
        // build masked fp16 P tile (row r, 32 cols starting at j0 + half*32)
        uint32_t hib[16];
        const __half* ep = erow + j0;
        int gjb = j0 + half * 32;
#pragma unroll
        for (int w = 0; w < 4; w++) {
            uint4 ev = *(const uint4*)(ep + w * 8);
            float2 f0 = __half22float2(*(__half2*)&ev.x);
            float2 f1 = __half22float2(*(__half2*)&ev.y);
            float2 f2 = __half22float2(*(__half2*)&ev.z);
            float2 f3 = __half22float2(*(__half2*)&ev.w);
            float pv[8] = { f0.x, f0.y, f1.x, f1.y, f2.x, f2.y, f3.x, f3.y };
#pragma unroll
            for (int u = 0; u < 8; u++) {
                int gj = gjb + w * 8 + u;
                bool keep = (gj <= gi) &&
                            ((gi - gj <= RB_) || ((sbits[gj >> 5] >> (gj & 31)) & 1u));
                pv[u] = keep ? pv[u] * il : 0.f;
            }
            hib[w * 4 + 0] = packh(pv[0], pv[1]);
            hib[w * 4 + 1] = packh(pv[2], pv[3]);
            hib[w * 4 + 2] = packh(pv[4], pv[5]);
            hib[w * 4 + 3] = packh(pv[6], pv[7]);
        }
#pragma unroll
        for (int sg = 0; sg < 4; sg++) {
            uint32_t bo = (uint32_t)(r * 128 + half * 64 + sg * 16);
            bo ^= (bo >> 3) & 0x70;
            *(uint4*)(pP + bo) = make_uint4(hib[sg * 4], hib[sg * 4 + 1], hib[sg * 4 + 2], hib[sg * 4 + 3]);
        }
        if (pre) cp_wait1(); else cp_wait0();
        __syncthreads();

        uint32_t b_base = sV[c & 1];
#pragma unroll
        for (int ks = 0; ks < 4; ks++) {
            uint32_t a[4][4], b[2][4];
#pragma unroll
            for (int mf = 0; mf < 4; mf++) {
                int row = 64 * warp_m + 16 * mf + (lane & 7) + (((lane >> 3) & 1) << 3);
                int colb = (16 * ks + (((lane >> 4) & 1) << 3)) * 2;
                uint32_t off = (uint32_t)(row * 128 + colb);
                off ^= (off >> 3) & 0x70;
                ldsm4(a[mf][0], a[mf][1], a[mf][2], a[mf][3], sP + off);
            }
#pragma unroll
            for (int nf2 = 0; nf2 < 2; nf2++) {
                int row = 32 * warp_n + 16 * nf2 + (lane & 7) + (((lane >> 4) & 1) << 3);
                int colb = (16 * ks + (((lane >> 3) & 1) << 3)) * 2;
                uint32_t off = (uint32_t)(row * 128 + colb);
                off ^= (off >> 3) & 0x70;
                ldsm4(b[nf2][0], b[nf2][1], b[nf2][2], b[nf2][3], b_base + off);
            }
#pragma unroll
            for (int mf = 0; mf < 4; mf++)
#pragma unroll
                for (int nf = 0; nf < 4; nf++)
                    mma16816(acc[mf][nf], a[mf], &b[nf >> 1][(nf & 1) * 2]);
        }
        __syncthreads();
    }

    // epilogue: write single fp16 aohat (row width HID)
#pragma unroll
    for (int mf = 0; mf < 4; mf++) {
        int r0 = i0 + 64 * warp_m + 16 * mf + (int)(lane >> 2);
#pragma unroll
        for (int nf = 0; nf < 4; nf++) {
            int c0 = 32 * warp_n + 8 * nf + (int)(lane & 3) * 2;
#pragma unroll
            for (int rr = 0; rr < 2; rr++) {
                uint32_t hi = packh(acc[mf][nf][rr * 2], acc[mf][nf][rr * 2 + 1]);
                size_t b0 = (size_t)(r0 + rr * 8) * HID_ + h * D_ + c0;
                *(uint32_t*)(aohat + b0) = hi;
            }
        }
    }
}

// ----------------------- split-fp16 conversion kernels -------------------
__global__ void split_plain(const float* __restrict__ A, __half* __restrict__ out,
                            int M, int K) {  // pattern A: [hi|lo]
    int idx = blockIdx.x * blockDim.x + threadIdx.x;
    if (idx >= M * K) return;
    int m = idx / K, k = idx - m * K;
    float x = A[idx];
    __half hi = __float2half_rn(x);
    __half lo = __float2half_rn(x - __half2float(hi));
    size_t base = (size_t)m * 2 * K;
    out[base + k] = hi; out[base + K + k] = lo;
}

__global__ void split_heads(const float* __restrict__ src, int ld,
                            __half* __restrict__ out, int nh, int patternB) {
    int idx = blockIdx.x * blockDim.x + threadIdx.x;
    if (idx >= S_ * nh * D_) return;
    int d = idx & 127;
    int h = (idx >> 7) % nh;
    int s = idx / (nh * D_);
    float x = src[(size_t)s * ld + h * D_ + d];
    __half hi = __float2half_rn(x);
    size_t base = ((size_t)h * S_ + s) * (2 * D_);
    if (patternB) {  // [k|k] duplicated
        out[base + d] = hi; out[base + D_ + d] = hi;
    } else {         // [hi|lo]
        __half lo = __float2half_rn(x - __half2float(hi));
        out[base + d] = hi; out[base + D_ + d] = lo;
    }
}

// transpose + fp16: dup=1 -> [b|b] (width 2K); dup=0 -> single (width K)
__global__ void transpose_split(const float* __restrict__ src, int ldsrc, int K, int Nper,
                                __half* __restrict__ out, int dup) {
    int z = blockIdx.z;
    const float* s = src + (size_t)z * Nper;
    int width = dup ? 2 * K : K;
    __half* o = out + (size_t)z * Nper * width;
    __shared__ float t[32][33];
    int k0 = blockIdx.y * 32, n0 = blockIdx.x * 32;
    int tx = threadIdx.x, ty = threadIdx.y;
#pragma unroll
    for (int r = 0; r < 4; r++) {
        int k = k0 + ty + 8 * r;
        t[ty + 8 * r][tx] = s[(size_t)k * ldsrc + n0 + tx];
    }
    __syncthreads();
#pragma unroll
    for (int r = 0; r < 4; r++) {
        int n = n0 + ty + 8 * r, k = k0 + tx;
        __half hh = __float2half_rn(t[tx][ty + 8 * r]);
        size_t base = (size_t)n * width;
        o[base + k] = hh;
        if (dup) o[base + K + k] = hh;
    }
}

// --------------------------------- RoPE ---------------------------------
__global__ void rope_kernel(float* x, int nh, int ld) {
    int idx = blockIdx.x * blockDim.x + threadIdx.x;
    if (idx >= S_ * nh * 64) return;
    int d = idx & 63;
    int rest = idx >> 6;
    int h = rest % nh;
    int s = rest / nh;
    float* base = x + (size_t)s * ld + h * 128;
    float x1 = base[d], x2 = base[d + 64];
    float inv = powf(10000.f, -(float)d * (1.f / 64.f));
    float ang = (float)s * inv;
    float c, sn;
    sincosf(ang, &sn, &c);
    base[d] = x1 * c - x2 * sn;
    base[d + 64] = x2 * c + x1 * sn;
}

// ------------------ invl1 = 1 / rowsum -----------------------------------
__global__ void invl_kernel(const float* __restrict__ rs, float* __restrict__ il) {
    int i = blockIdx.x * 256 + threadIdx.x;
    il[i] = 1.f / rs[i];
}

// coalesced column sums over fp16 e (rows above diagonal are exactly zero)
__global__ __launch_bounds__(256) void colsum_kernel() {
    int h = blockIdx.y;
    int j0 = blockIdx.x * 256;
    int j = j0 + threadIdx.x;
    const __half* base = g_e + (size_t)h * S_ * S_;
    __shared__ float il[S_];
    for (int i = j0 + threadIdx.x; i < S_; i += 256)
        il[i] = g_invl1[h * S_ + i];
    __syncthreads();
    float a0 = 0.f, a1 = 0.f, a2 = 0.f, a3 = 0.f;
    for (int i = j0; i < S_; i += 4) {
        a0 += __half2float(base[(size_t)(i    ) * S_ + j]) * il[i];
        a1 += __half2float(base[(size_t)(i + 1) * S_ + j]) * il[i + 1];
        a2 += __half2float(base[(size_t)(i + 2) * S_ + j]) * il[i + 2];
        a3 += __half2float(base[(size_t)(i + 3) * S_ + j]) * il[i + 3];
    }
    g_colsum[h * S_ + j] = (a0 + a1) + (a2 + a3);
}

__global__ __launch_bounds__(256) void topk_kernel() {
    int h = blockIdx.x;
    int tid = threadIdx.x;
    int lane = tid & 31, w = tid >> 5;
    __shared__ float vals[S_];
    __shared__ float wbv[8];
    __shared__ int wbi[8];
    __shared__ uint32_t bits[64];
    for (int j = tid; j < S_; j += 256) vals[j] = g_colsum[h * S_ + j];
    if (tid < 64) bits[tid] = 0;
    __syncthreads();
    for (int it = 0; it < HB_; it++) {
        float best = -INFINITY; int besti = 1 << 30;
        for (int j = tid; j < S_; j += 256) {
            float v = vals[j];
            if (v > best || (v == best && j < besti)) { best = v; besti = j; }
        }
#pragma unroll
        for (int off = 16; off > 0; off >>= 1) {
            float ov = __shfl_xor_sync(0xFFFFFFFF, best, off);
            int oi = __shfl_xor_sync(0xFFFFFFFF, besti, off);
            if (ov > best || (ov == best && oi < besti)) { best = ov; besti = oi; }
        }
        if (lane == 0) { wbv[w] = best; wbi[w] = besti; }
        __syncthreads();
        if (tid == 0) {
            float b = wbv[0]; int bi2 = wbi[0];
#pragma unroll
            for (int q = 1; q < 8; q++)
                if (wbv[q] > b || (wbv[q] == b && wbi[q] < bi2)) { b = wbv[q]; bi2 = wbi[q]; }
            g_heavylist[h * HB_ + it] = bi2;
            bits[bi2 >> 5] |= (1u << (bi2 & 31));
            vals[bi2] = -INFINITY;
        }
        __syncthreads();
    }
    if (tid < 64) g_heavybits[h * 64 + tid] = bits[tid];
}

// ------ pass-2: invl2 = 1/sum(e over band + heavy) ------
__global__ __launch_bounds__(256) void rowsum2_kernel() {
    int h = blockIdx.y;
    int tid = threadIdx.x;
    __shared__ int hl[HB_];
    for (int t = tid; t < HB_; t += 256) hl[t] = g_heavylist[h * HB_ + t];
    __syncthreads();

    int w = tid >> 5, lane = tid & 31;
    int i = blockIdx.x * 8 + w;
    const __half* erow = g_e + (size_t)(h * S_ + i) * S_;
    int lo = i - RB_; if (lo < 0) lo = 0;

    float l = 0.f;
    for (int j = lo + lane; j <= i; j += 32) l += __half2float(erow[j]);
    for (int t = lane; t < HB_; t += 32) {
        int j = hl[t];
        if (j < lo) l += __half2float(erow[j]);
    }
#pragma unroll
    for (int off = 16; off > 0; off >>= 1)
        l += __shfl_xor_sync(0xFFFFFFFF, l, off);
    if (lane == 0) g_invl2[h * S_ + i] = 1.f / l;
}

// ------------------------------ launcher ---------------------------------
extern "C" void kernel_launch(void* const* d_in, const int* in_sizes, int n_in,
                              void* d_out, int out_size) {
    const float* hidden = (const float*)d_in[0];
    const float* Wq = (const float*)d_in[1];
    const float* Wk = (const float*)d_in[2];
    const float* Wv = (const float*)d_in[3];
    const float* Wo = (const float*)d_in[4];
    float* out = (float*)d_out;

    float *qkv, *rsum, *il1, *il2;
    __half* e;
    uint32_t* hbits;
    __half *xhat, *wqkvt, *wot, *qhat, *khat, *vthat, *aohat;
    cudaGetSymbolAddress((void**)&qkv, g_qkv);
    cudaGetSymbolAddress((void**)&e, g_e);
    cudaGetSymbolAddress((void**)&rsum, g_rowsum);
    cudaGetSymbolAddress((void**)&il1, g_invl1);
    cudaGetSymbolAddress((void**)&il2, g_invl2);
    cudaGetSymbolAddress((void**)&hbits, g_heavybits);
    cudaGetSymbolAddress((void**)&xhat, g_xhat);
    cudaGetSymbolAddress((void**)&wqkvt, g_wqkvt);
    cudaGetSymbolAddress((void**)&wot, g_wot);
    cudaGetSymbolAddress((void**)&qhat, g_qhat);
    cudaGetSymbolAddress((void**)&khat, g_khat);
    cudaGetSymbolAddress((void**)&vthat, g_vthat);
    cudaGetSymbolAddress((void**)&aohat, g_aohat);

    const int SMEM_GEMM = 66560;
    const int SMEM_PV = 50176;
    cudaFuncSetAttribute(mma_gemm, cudaFuncAttributeMaxDynamicSharedMemorySize, SMEM_GEMM);
    cudaFuncSetAttribute(pv_mma, cudaFuncAttributeMaxDynamicSharedMemorySize, SMEM_PV);

    // launches 1-5: conversions; QKV mma is launch #6 (ncu -s 5 capture slot)
    split_plain<<<(S_ * HID_ + 255) / 256, 256>>>(hidden, xhat, S_, HID_);
    transpose_split<<<dim3(HID_ / 32, HID_ / 32, 1), dim3(32, 8)>>>(Wq, HID_, HID_, HID_, wqkvt, 1);
    transpose_split<<<dim3((NKV_ * D_) / 32, HID_ / 32, 1), dim3(32, 8)>>>(
        Wk, NKV_ * D_, HID_, NKV_ * D_, wqkvt + (size_t)HID_ * 2 * HID_, 1);
    transpose_split<<<dim3((NKV_ * D_) / 32, HID_ / 32, 1), dim3(32, 8)>>>(
        Wv, NKV_ * D_, HID_, NKV_ * D_, wqkvt + (size_t)(HID_ + NKV_ * D_) * 2 * HID_, 1);
    transpose_split<<<dim3(HID_ / 32, HID_ / 32, 1), dim3(32, 8)>>>(Wo, HID_, HID_, HID_, wot, 0);

    // 6. fused QKV projection (one GEMM, N=3072, Kp = 2*HID)
    mma_gemm<<<dim3(QKVN_ / 128, S_ / 128, 1), 256, SMEM_GEMM>>>(
        xhat, 0, wqkvt, 0, 0, qkv, nullptr, 0, QKVN_, 2 * HID_, 0, nullptr);

    // RoPE (in place inside g_qkv)
    rope_kernel<<<(S_ * NH_ * 64 + 255) / 256, 256>>>(qkv, NH_, QKVN_);
    rope_kernel<<<(S_ * NKV_ * 64 + 255) / 256, 256>>>(qkv + HID_, NKV_, QKVN_);

    // split roped Q ([hi|lo]) / K ([k|k]); transpose V -> single fp16 V^T
    split_heads<<<(S_ * NH_ * D_ + 255) / 256, 256>>>(qkv, QKVN_, qhat, NH_, 0);
    split_heads<<<(S_ * NKV_ * D_ + 255) / 256, 256>>>(qkv + HID_, QKVN_, khat, NKV_, 1);
    transpose_split<<<dim3(D_ / 32, S_ / 32, NKV_), dim3(32, 8)>>>(
        qkv + HID_ + NKV_ * D_, QKVN_, S_, D_, vthat, 0);

    // zero rowsum accumulator (captured node, re-zeroed every replay)
    cudaMemsetAsync(rsum, 0, NH_ * S_ * sizeof(float));

    // e = fp16(exp(scale * QK^T)) + fused row sums (Kp = 2*D)
    mma_gemm<<<dim3(S_ / 128, S_ / 128, NH_), 256, SMEM_GEMM>>>(
        qhat, (size_t)S_ * 2 * D_, khat, (size_t)S_ * 2 * D_, 2,
        nullptr, e, (size_t)S_ * S_, S_, 2 * D_, 2, rsum);

    // H2O: invl1, colsum, topk (emits heavy bitmask)
    invl_kernel<<<NH_ * S_ / 256, 256>>>(rsum, il1);
    colsum_kernel<<<dim3(S_ / 256, NH_), 256>>>();
    topk_kernel<<<NH_, 256>>>();

    // invl2 (sum-only; e untouched)
    rowsum2_kernel<<<dim3(S_ / 8, NH_), 256>>>();

    // fused masked PV -> aohat (single fp16), heavy blocks first
    pv_mma<<<dim3(S_ / 128, NH_), 256, SMEM_PV>>>(vthat, e, il2, hbits, aohat);

    // output projection (single fp16 both sides, Kp = HID)
    mma_gemm<<<dim3(HID_ / 128, S_ / 128, 1), 256, SMEM_GEMM>>>(
        aohat, 0, wot, 0, 0, out, nullptr, 0, HID_, HID_, 0, nullptr);
}

// round 14
// speedup vs baseline: 4.8630x; 1.0796x over previous
#include <cuda_runtime.h>
#include <cuda_fp16.h>
#include <math.h>
#include <stdint.h>

#define S_    2048
#define HID_  2048
#define NH_   16
#define NKV_  4
#define D_    128
#define HB_   204
#define RB_   204
#define SCALE_ 0.08838834764831845f
#define L2E_  1.4426950408889634f
#define QKVN_ 3072

// ----------------------------- scratch ---------------------------------
__device__ float g_qkv[S_ * QKVN_];                 // [s][ q(2048) | k(512) | v(512) ]
__device__ __half g_e[(size_t)NH_ * S_ * S_];       // exp(score) fp16; zero above diagonal
__device__ float g_rowsum[NH_ * S_];
__device__ float g_invl1[NH_ * S_], g_invl2[NH_ * S_];
__device__ float g_colsum[NH_ * S_];
__device__ int   g_heavylist[NH_ * HB_];
__device__ uint32_t g_heavybits[NH_ * 64];

__device__ __half g_xhat[(size_t)S_ * 2 * HID_];          // [hi(2048) | lo(2048)] per row
__device__ __half g_wqt[(size_t)HID_ * 2 * HID_];         // Wq^T dup [b|b]
__device__ __half g_wkvt[(size_t)(2 * NKV_ * D_) * HID_]; // (Wk|Wv)^T single fp16
__device__ __half g_wot[(size_t)HID_ * HID_];             // Wo^T single fp16
__device__ __half g_qhat[(size_t)NH_ * S_ * D_];          // single fp16 roped Q
__device__ __half g_khat[(size_t)NKV_ * S_ * D_];         // single fp16 roped K
__device__ __half g_vthat[(size_t)NKV_ * D_ * S_];        // single fp16 V^T
__device__ __half g_aohat[(size_t)S_ * HID_];             // single fp16 attention out

// ----------------------------- PTX helpers ------------------------------
__device__ __forceinline__ uint32_t smem_u32(const void* p) {
    uint32_t a;
    asm("{ .reg .u64 t; cvta.to.shared.u64 t, %1; cvt.u32.u64 %0, t; }" : "=r"(a) : "l"(p));
    return a;
}
__device__ __forceinline__ void cp16(uint32_t saddr, const void* gptr) {
    asm volatile("cp.async.cg.shared.global [%0], [%1], 16;" :: "r"(saddr), "l"(gptr));
}
__device__ __forceinline__ void cp_commit() { asm volatile("cp.async.commit_group;"); }
__device__ __forceinline__ void cp_wait0() { asm volatile("cp.async.wait_group 0;" ::: "memory"); }
__device__ __forceinline__ void cp_wait1() { asm volatile("cp.async.wait_group 1;" ::: "memory"); }

__device__ __forceinline__ void ldsm4(uint32_t& r0, uint32_t& r1, uint32_t& r2, uint32_t& r3,
                                      uint32_t addr) {
    asm volatile("ldmatrix.sync.aligned.m8n8.x4.shared.b16 {%0,%1,%2,%3}, [%4];"
                 : "=r"(r0), "=r"(r1), "=r"(r2), "=r"(r3) : "r"(addr));
}
__device__ __forceinline__ void mma16816(float* d, const uint32_t* a, const uint32_t* b) {
    asm volatile(
        "mma.sync.aligned.m16n8k16.row.col.f32.f16.f16.f32 "
        "{%0,%1,%2,%3}, {%4,%5,%6,%7}, {%8,%9}, {%0,%1,%2,%3};"
        : "+f"(d[0]), "+f"(d[1]), "+f"(d[2]), "+f"(d[3])
        : "r"(a[0]), "r"(a[1]), "r"(a[2]), "r"(a[3]), "r"(b[0]), "r"(b[1]));
}
__device__ __forceinline__ float fexp(float x) {   // e^x via MUFU
    float y;
    asm("ex2.approx.ftz.f32 %0, %1;" : "=f"(y) : "f"(x * L2E_));
    return y;
}
__device__ __forceinline__ float fexp2p3(float x) { // 2^x via FMA pipe, deg-3
    float n = rintf(x);
    float f = x - n;
    float p = 5.5490603e-2f;
    p = fmaf(p, f, 2.4022651e-1f);
    p = fmaf(p, f, 6.9315308e-1f);
    p = fmaf(p, f, 9.9999989e-1f);
    return p * __int_as_float(((int)n + 127) << 23);
}
__device__ __forceinline__ uint32_t packh(float p0, float p1) {
    __half2 h = __floats2half2_rn(p0, p1);
    return *(uint32_t*)&h;
}

// ------------------------- HMMA GEMM -------------------------
__device__ __forceinline__ void load_tile_async(uint32_t sbase, const __half* src,
                                                int ld, int row0, int kbase, int tid) {
#pragma unroll
    for (int t = 0; t < 4; t++) {
        int u = tid + t * 256;
        int row = u >> 3, seg = u & 7;
        uint32_t bo = (uint32_t)(row * 128 + seg * 16);
        bo ^= (bo >> 3) & 0x70;
        cp16(sbase + bo, src + (size_t)(row0 + row) * ld + kbase + seg * 8);
    }
}

// mode 0: plain fp32 store to C.
// mode 2: Eh = fp16(exp(scale*s)) for j<=i (0 above), hybrid exp, fused row sums.
// aLd/bLd decoupled from Kp (lets a 1-term GEMM read the hi half of a [hi|lo] buffer).
__global__ __launch_bounds__(256, 2) void mma_gemm(
    const __half* __restrict__ A, size_t aStrideZ, int aLd,
    const __half* __restrict__ Bt, size_t bStrideZ, int bShift, int bLd,
    float* __restrict__ C, __half* __restrict__ Eh, size_t cStrideZ, int ldc,
    int Kp, int mode, float* __restrict__ rowsum) {
    int z = blockIdx.z;
    int i0 = blockIdx.y * 128, j0 = blockIdx.x * 128;
    if (mode == 2 && j0 > i0 + 127) return;   // fully above diagonal: skip

    const __half* Az = A + (size_t)z * aStrideZ;
    const __half* Bz = Bt + (size_t)(z >> bShift) * bStrideZ;
    int tid = threadIdx.x, wid = tid >> 5;
    uint32_t lane = tid & 31;

    extern __shared__ char dsm[];
    char* tile = (char*)(((uintptr_t)dsm + 1023) & ~(uintptr_t)1023);
    uint32_t sA[2] = { smem_u32(tile), smem_u32(tile) + 16384 };
    uint32_t sB[2] = { smem_u32(tile) + 32768, smem_u32(tile) + 49152 };

    int warp_m = wid >> 2;
    int warp_n = wid & 3;

    float acc[4][4][4];
#pragma unroll
    for (int i = 0; i < 4; i++)
#pragma unroll
        for (int j = 0; j < 4; j++)
#pragma unroll
            for (int r = 0; r < 4; r++) acc[i][j][r] = 0.f;

    load_tile_async(sA[0], Az, aLd, i0, 0, tid);
    load_tile_async(sB[0], Bz, bLd, j0, 0, tid);
    cp_commit();

    const int NC = Kp >> 6;
    for (int c = 0; c < NC; c++) {
        if (c + 1 < NC) {
            load_tile_async(sA[(c + 1) & 1], Az, aLd, i0, (c + 1) * 64, tid);
            load_tile_async(sB[(c + 1) & 1], Bz, bLd, j0, (c + 1) * 64, tid);
            cp_commit();
            cp_wait1();
        } else {
            cp_wait0();
        }
        __syncthreads();

        uint32_t a_base = sA[c & 1], b_base = sB[c & 1];
#pragma unroll
        for (int ks = 0; ks < 4; ks++) {
            uint32_t a[4][4], b[2][4];
#pragma unroll
            for (int mf = 0; mf < 4; mf++) {
                int row = 64 * warp_m + 16 * mf + (lane & 7) + (((lane >> 3) & 1) << 3);
                int colb = (16 * ks + (((lane >> 4) & 1) << 3)) * 2;
                uint32_t off = (uint32_t)(row * 128 + colb);
                off ^= (off >> 3) & 0x70;
                ldsm4(a[mf][0], a[mf][1], a[mf][2], a[mf][3], a_base + off);
            }
#pragma unroll
            for (int nf2 = 0; nf2 < 2; nf2++) {
                int row = 32 * warp_n + 16 * nf2 + (lane & 7) + (((lane >> 4) & 1) << 3);
                int colb = (16 * ks + (((lane >> 3) & 1) << 3)) * 2;
                uint32_t off = (uint32_t)(row * 128 + colb);
                off ^= (off >> 3) & 0x70;
                ldsm4(b[nf2][0], b[nf2][1], b[nf2][2], b[nf2][3], b_base + off);
            }
#pragma unroll
            for (int mf = 0; mf < 4; mf++)
#pragma unroll
                for (int nf = 0; nf < 4; nf++)
                    mma16816(acc[mf][nf], a[mf], &b[nf >> 1][(nf & 1) * 2]);
        }
        __syncthreads();
    }

    if (mode == 0) {
        float* Cz = C + (size_t)z * cStrideZ;
#pragma unroll
        for (int mf = 0; mf < 4; mf++) {
            int r0 = i0 + 64 * warp_m + 16 * mf + (int)(lane >> 2);
#pragma unroll
            for (int nf = 0; nf < 4; nf++) {
                int c0 = j0 + 32 * warp_n + 8 * nf + (int)(lane & 3) * 2;
                *(float2*)(Cz + (size_t)r0 * ldc + c0) = make_float2(acc[mf][nf][0], acc[mf][nf][1]);
                *(float2*)(Cz + (size_t)(r0 + 8) * ldc + c0) = make_float2(acc[mf][nf][2], acc[mf][nf][3]);
            }
        }
        return;
    }

    // mode 2: exp epilogue (10/16 MUFU + 6/16 deg-3 poly), fp16 store, fused row sums
    __half* Ez = Eh + (size_t)z * cStrideZ;
    const float cl = SCALE_ * L2E_;
    float rs0[4], rs1[4];
#pragma unroll
    for (int mf = 0; mf < 4; mf++) {
        int r0 = i0 + 64 * warp_m + 16 * mf + (int)(lane >> 2);
        float s0 = 0.f, s1 = 0.f;
#pragma unroll
        for (int nf = 0; nf < 4; nf++) {
            int c0 = j0 + 32 * warp_n + 8 * nf + (int)(lane & 3) * 2;
            float d0 = acc[mf][nf][0], d1 = acc[mf][nf][1];
            float d2 = acc[mf][nf][2], d3 = acc[mf][nf][3];
            if (nf < 2) {
                d0 = (c0     <= r0)     ? fexp(d0 * SCALE_) : 0.f;
                d1 = (c0 + 1 <= r0)     ? fexp(d1 * SCALE_) : 0.f;
                d2 = (c0     <= r0 + 8) ? fexp(d2 * SCALE_) : 0.f;
                d3 = (c0 + 1 <= r0 + 8) ? fexp(d3 * SCALE_) : 0.f;
            } else if (nf == 2) {
                d0 = (c0     <= r0)     ? fexp(d0 * SCALE_) : 0.f;
                d1 = (c0 + 1 <= r0)     ? fexp(d1 * SCALE_) : 0.f;
                d2 = (c0     <= r0 + 8) ? fexp2p3(d2 * cl) : 0.f;
                d3 = (c0 + 1 <= r0 + 8) ? fexp2p3(d3 * cl) : 0.f;
            } else {
                d0 = (c0     <= r0)     ? fexp2p3(d0 * cl) : 0.f;
                d1 = (c0 + 1 <= r0)     ? fexp2p3(d1 * cl) : 0.f;
                d2 = (c0     <= r0 + 8) ? fexp2p3(d2 * cl) : 0.f;
                d3 = (c0 + 1 <= r0 + 8) ? fexp2p3(d3 * cl) : 0.f;
            }
            __half2 h01 = __floats2half2_rn(d0, d1);
            __half2 h23 = __floats2half2_rn(d2, d3);
            *(uint32_t*)(Ez + (size_t)r0 * ldc + c0) = *(uint32_t*)&h01;
            *(uint32_t*)(Ez + (size_t)(r0 + 8) * ldc + c0) = *(uint32_t*)&h23;
            float2 f01 = __half22float2(h01);
            float2 f23 = __half22float2(h23);
            s0 += f01.x + f01.y;
            s1 += f23.x + f23.y;
        }
        rs0[mf] = s0; rs1[mf] = s1;
    }
    {
        float* rz = rowsum + (size_t)z * S_;
#pragma unroll
        for (int mf = 0; mf < 4; mf++) {
            float v0 = rs0[mf], v1 = rs1[mf];
            v0 += __shfl_xor_sync(0xFFFFFFFF, v0, 1);
            v0 += __shfl_xor_sync(0xFFFFFFFF, v0, 2);
            v1 += __shfl_xor_sync(0xFFFFFFFF, v1, 1);
            v1 += __shfl_xor_sync(0xFFFFFFFF, v1, 2);
            if ((lane & 3) == 0) {
                int r0 = i0 + 64 * warp_m + 16 * mf + (int)(lane >> 2);
                atomicAdd(rz + r0, v0);
                atomicAdd(rz + r0 + 8, v1);
            }
        }
    }
}

// ------------------ fused PV (masked P on the fly, single-pass fp16) --------------
__global__ __launch_bounds__(256, 2) void pv_mma(
    const __half* __restrict__ vthat,
    const __half* __restrict__ e, const float* __restrict__ invl2,
    const uint32_t* __restrict__ heavybits,
    __half* __restrict__ aohat) {
    int i0 = (int)(gridDim.x - 1 - blockIdx.x) * 128;   // heavy blocks first
    int h = blockIdx.y, kh = h >> 2;
    int tid = threadIdx.x, wid = tid >> 5;
    uint32_t lane = tid & 31;
    int warp_m = wid >> 2, warp_n = wid & 3;

    extern __shared__ char dsm[];
    char* tile = (char*)(((uintptr_t)dsm + 1023) & ~(uintptr_t)1023);
    char* pP = tile;
    uint32_t sP = smem_u32(pP);
    uint32_t sV[2] = { smem_u32(tile) + 16384, smem_u32(tile) + 32768 };

    __shared__ uint32_t sbits[64];
    if (tid < 64) sbits[tid] = heavybits[h * 64 + tid];

    int r = tid >> 1, half = tid & 1;
    int gi = i0 + r;
    float il = invl2[h * S_ + gi];
    const __half* erow = e + ((size_t)h * S_ + gi) * S_ + half * 32;
    const __half* Vz = vthat + (size_t)kh * D_ * S_;

    float acc[4][4][4];
#pragma unroll
    for (int i = 0; i < 4; i++)
#pragma unroll
        for (int j = 0; j < 4; j++)
#pragma unroll
            for (int q = 0; q < 4; q++) acc[i][j][q] = 0.f;

    const int NCH = (i0 >> 6) + 2;
    load_tile_async(sV[0], Vz, S_, 0, 0, tid);
    cp_commit();
    __syncthreads();

    for (int c = 0; c < NCH; c++) {
        int j0 = c * 64;
        bool pre = (c + 1 < NCH);
        if (pre) {
            load_tile_async(sV[(c + 1) & 1], Vz, S_, 0, (c + 1) * 64, tid);
            cp_commit();
        }
        uint32_t hib[16];
        const __half* ep = erow + j0;
        int gjb = j0 + half * 32;
#pragma unroll
        for (int w = 0; w < 4; w++) {
            uint4 ev = *(const uint4*)(ep + w * 8);
            float2 f0 = __half22float2(*(__half2*)&ev.x);
            float2 f1 = __half22float2(*(__half2*)&ev.y);
            float2 f2 = __half22float2(*(__half2*)&ev.z);
            float2 f3 = __half22float2(*(__half2*)&ev.w);
            float pv[8] = { f0.x, f0.y, f1.x, f1.y, f2.x, f2.y, f3.x, f3.y };
#pragma unroll
            for (int u = 0; u < 8; u++) {
                int gj = gjb + w * 8 + u;
                bool keep = (gj <= gi) &&
                            ((gi - gj <= RB_) || ((sbits[gj >> 5] >> (gj & 31)) & 1u));
                pv[u] = keep ? pv[u] * il : 0.f;
            }
            hib[w * 4 + 0] = packh(pv[0], pv[1]);
            hib[w * 4 + 1] = packh(pv[2], pv[3]);
            hib[w * 4 + 2] = packh(pv[4], pv[5]);
            hib[w * 4 + 3] = packh(pv[6], pv[7]);
        }
#pragma unroll
        for (int sg = 0; sg < 4; sg++) {
            uint32_t bo = (uint32_t)(r * 128 + half * 64 + sg * 16);
            bo ^= (bo >> 3) & 0x70;
            *(uint4*)(pP + bo) = make_uint4(hib[sg * 4], hib[sg * 4 + 1], hib[sg * 4 + 2], hib[sg * 4 + 3]);
        }
        if (pre) cp_wait1(); else cp_wait0();
        __syncthreads();

        uint32_t b_base = sV[c & 1];
#pragma unroll
        for (int ks = 0; ks < 4; ks++) {
            uint32_t a[4][4], b[2][4];
#pragma unroll
            for (int mf = 0; mf < 4; mf++) {
                int row = 64 * warp_m + 16 * mf + (lane & 7) + (((lane >> 3) & 1) << 3);
                int colb = (16 * ks + (((lane >> 4) & 1) << 3)) * 2;
                uint32_t off = (uint32_t)(row * 128 + colb);
                off ^= (off >> 3) & 0x70;
                ldsm4(a[mf][0], a[mf][1], a[mf][2], a[mf][3], sP + off);
            }
#pragma unroll
            for (int nf2 = 0; nf2 < 2; nf2++) {
                int row = 32 * warp_n + 16 * nf2 + (lane & 7) + (((lane >> 4) & 1) << 3);
                int colb = (16 * ks + (((lane >> 3) & 1) << 3)) * 2;
                uint32_t off = (uint32_t)(row * 128 + colb);
                off ^= (off >> 3) & 0x70;
                ldsm4(b[nf2][0], b[nf2][1], b[nf2][2], b[nf2][3], b_base + off);
            }
#pragma unroll
            for (int mf = 0; mf < 4; mf++)
#pragma unroll
                for (int nf = 0; nf < 4; nf++)
                    mma16816(acc[mf][nf], a[mf], &b[nf >> 1][(nf & 1) * 2]);
        }
        __syncthreads();
    }

#pragma unroll
    for (int mf = 0; mf < 4; mf++) {
        int r0 = i0 + 64 * warp_m + 16 * mf + (int)(lane >> 2);
#pragma unroll
        for (int nf = 0; nf < 4; nf++) {
            int c0 = 32 * warp_n + 8 * nf + (int)(lane & 3) * 2;
#pragma unroll
            for (int rr = 0; rr < 2; rr++) {
                uint32_t hi = packh(acc[mf][nf][rr * 2], acc[mf][nf][rr * 2 + 1]);
                size_t b0 = (size_t)(r0 + rr * 8) * HID_ + h * D_ + c0;
                *(uint32_t*)(aohat + b0) = hi;
            }
        }
    }
}

// ----------------------- conversion kernels -------------------
__global__ void split_plain(const float* __restrict__ A, __half* __restrict__ out,
                            int M, int K) {  // [hi|lo]
    int idx = blockIdx.x * blockDim.x + threadIdx.x;
    if (idx >= M * K) return;
    int m = idx / K, k = idx - m * K;
    float x = A[idx];
    __half hi = __float2half_rn(x);
    __half lo = __float2half_rn(x - __half2float(hi));
    size_t base = (size_t)m * 2 * K;
    out[base + k] = hi; out[base + K + k] = lo;
}

// single fp16 per-head layout: out[h][s][d]
__global__ void heads_single(const float* __restrict__ src, int ld,
                             __half* __restrict__ out, int nh) {
    int idx = blockIdx.x * blockDim.x + threadIdx.x;
    if (idx >= S_ * nh * D_) return;
    int d = idx & 127;
    int h = (idx >> 7) % nh;
    int s = idx / (nh * D_);
    float x = src[(size_t)s * ld + h * D_ + d];
    out[((size_t)h * S_ + s) * D_ + d] = __float2half_rn(x);
}

// transpose + fp16: dup=1 -> [b|b] (width 2K); dup=0 -> single (width K)
__global__ void transpose_split(const float* __restrict__ src, int ldsrc, int K, int Nper,
                                __half* __restrict__ out, int dup) {
    int z = blockIdx.z;
    const float* s = src + (size_t)z * Nper;
    int width = dup ? 2 * K : K;
    __half* o = out + (size_t)z * Nper * width;
    __shared__ float t[32][33];
    int k0 = blockIdx.y * 32, n0 = blockIdx.x * 32;
    int tx = threadIdx.x, ty = threadIdx.y;
#pragma unroll
    for (int r = 0; r < 4; r++) {
        int k = k0 + ty + 8 * r;
        t[ty + 8 * r][tx] = s[(size_t)k * ldsrc + n0 + tx];
    }
    __syncthreads();
#pragma unroll
    for (int r = 0; r < 4; r++) {
        int n = n0 + ty + 8 * r, k = k0 + tx;
        __half hh = __float2half_rn(t[tx][ty + 8 * r]);
        size_t base = (size_t)n * width;
        o[base + k] = hh;
        if (dup) o[base + K + k] = hh;
    }
}

// --------------------------------- RoPE ---------------------------------
__global__ void rope_kernel(float* x, int nh, int ld) {
    int idx = blockIdx.x * blockDim.x + threadIdx.x;
    if (idx >= S_ * nh * 64) return;
    int d = idx & 63;
    int rest = idx >> 6;
    int h = rest % nh;
    int s = rest / nh;
    float* base = x + (size_t)s * ld + h * 128;
    float x1 = base[d], x2 = base[d + 64];
    float inv = powf(10000.f, -(float)d * (1.f / 64.f));
    float ang = (float)s * inv;
    float c, sn;
    sincosf(ang, &sn, &c);
    base[d] = x1 * c - x2 * sn;
    base[d + 64] = x2 * c + x1 * sn;
}

// ------------------ invl1 = 1 / rowsum -----------------------------------
__global__ void invl_kernel(const float* __restrict__ rs, float* __restrict__ il) {
    int i = blockIdx.x * 256 + threadIdx.x;
    il[i] = 1.f / rs[i];
}

// coalesced column sums over fp16 e (rows above diagonal are exactly zero)
__global__ __launch_bounds__(256) void colsum_kernel() {
    int h = blockIdx.y;
    int j0 = blockIdx.x * 256;
    int j = j0 + threadIdx.x;
    const __half* base = g_e + (size_t)h * S_ * S_;
    __shared__ float il[S_];
    for (int i = j0 + threadIdx.x; i < S_; i += 256)
        il[i] = g_invl1[h * S_ + i];
    __syncthreads();
    float a0 = 0.f, a1 = 0.f, a2 = 0.f, a3 = 0.f;
    for (int i = j0; i < S_; i += 4) {
        a0 += __half2float(base[(size_t)(i    ) * S_ + j]) * il[i];
        a1 += __half2float(base[(size_t)(i + 1) * S_ + j]) * il[i + 1];
        a2 += __half2float(base[(size_t)(i + 2) * S_ + j]) * il[i + 2];
        a3 += __half2float(base[(size_t)(i + 3) * S_ + j]) * il[i + 3];
    }
    g_colsum[h * S_ + j] = (a0 + a1) + (a2 + a3);
}

__global__ __launch_bounds__(256) void topk_kernel() {
    int h = blockIdx.x;
    int tid = threadIdx.x;
    int lane = tid & 31, w = tid >> 5;
    __shared__ float vals[S_];
    __shared__ float wbv[8];
    __shared__ int wbi[8];
    __shared__ uint32_t bits[64];
    for (int j = tid; j < S_; j += 256) vals[j] = g_colsum[h * S_ + j];
    if (tid < 64) bits[tid] = 0;
    __syncthreads();
    for (int it = 0; it < HB_; it++) {
        float best = -INFINITY; int besti = 1 << 30;
        for (int j = tid; j < S_; j += 256) {
            float v = vals[j];
            if (v > best || (v == best && j < besti)) { best = v; besti = j; }
        }
#pragma unroll
        for (int off = 16; off > 0; off >>= 1) {
            float ov = __shfl_xor_sync(0xFFFFFFFF, best, off);
            int oi = __shfl_xor_sync(0xFFFFFFFF, besti, off);
            if (ov > best || (ov == best && oi < besti)) { best = ov; besti = oi; }
        }
        if (lane == 0) { wbv[w] = best; wbi[w] = besti; }
        __syncthreads();
        if (tid == 0) {
            float b = wbv[0]; int bi2 = wbi[0];
#pragma unroll
            for (int q = 1; q < 8; q++)
                if (wbv[q] > b || (wbv[q] == b && wbi[q] < bi2)) { b = wbv[q]; bi2 = wbi[q]; }
            g_heavylist[h * HB_ + it] = bi2;
            bits[bi2 >> 5] |= (1u << (bi2 & 31));
            vals[bi2] = -INFINITY;
        }
        __syncthreads();
    }
    if (tid < 64) g_heavybits[h * 64 + tid] = bits[tid];
}

// ------ pass-2: invl2 = 1/sum(e over band + heavy) ------
__global__ __launch_bounds__(256) void rowsum2_kernel() {
    int h = blockIdx.y;
    int tid = threadIdx.x;
    __shared__ int hl[HB_];
    for (int t = tid; t < HB_; t += 256) hl[t] = g_heavylist[h * HB_ + t];
    __syncthreads();

    int w = tid >> 5, lane = tid & 31;
    int i = blockIdx.x * 8 + w;
    const __half* erow = g_e + (size_t)(h * S_ + i) * S_;
    int lo = i - RB_; if (lo < 0) lo = 0;

    float l = 0.f;
    for (int j = lo + lane; j <= i; j += 32) l += __half2float(erow[j]);
    for (int t = lane; t < HB_; t += 32) {
        int j = hl[t];
        if (j < lo) l += __half2float(erow[j]);
    }
#pragma unroll
    for (int off = 16; off > 0; off >>= 1)
        l += __shfl_xor_sync(0xFFFFFFFF, l, off);
    if (lane == 0) g_invl2[h * S_ + i] = 1.f / l;
}

// ------------------------------ launcher ---------------------------------
extern "C" void kernel_launch(void* const* d_in, const int* in_sizes, int n_in,
                              void* d_out, int out_size) {
    const float* hidden = (const float*)d_in[0];
    const float* Wq = (const float*)d_in[1];
    const float* Wk = (const float*)d_in[2];
    const float* Wv = (const float*)d_in[3];
    const float* Wo = (const float*)d_in[4];
    float* out = (float*)d_out;

    float *qkv, *rsum, *il1, *il2;
    __half* e;
    uint32_t* hbits;
    __half *xhat, *wqt, *wkvt, *wot, *qhat, *khat, *vthat, *aohat;
    cudaGetSymbolAddress((void**)&qkv, g_qkv);
    cudaGetSymbolAddress((void**)&e, g_e);
    cudaGetSymbolAddress((void**)&rsum, g_rowsum);
    cudaGetSymbolAddress((void**)&il1, g_invl1);
    cudaGetSymbolAddress((void**)&il2, g_invl2);
    cudaGetSymbolAddress((void**)&hbits, g_heavybits);
    cudaGetSymbolAddress((void**)&xhat, g_xhat);
    cudaGetSymbolAddress((void**)&wqt, g_wqt);
    cudaGetSymbolAddress((void**)&wkvt, g_wkvt);
    cudaGetSymbolAddress((void**)&wot, g_wot);
    cudaGetSymbolAddress((void**)&qhat, g_qhat);
    cudaGetSymbolAddress((void**)&khat, g_khat);
    cudaGetSymbolAddress((void**)&vthat, g_vthat);
    cudaGetSymbolAddress((void**)&aohat, g_aohat);

    const int SMEM_GEMM = 66560;
    const int SMEM_PV = 50176;
    cudaFuncSetAttribute(mma_gemm, cudaFuncAttributeMaxDynamicSharedMemorySize, SMEM_GEMM);
    cudaFuncSetAttribute(pv_mma, cudaFuncAttributeMaxDynamicSharedMemorySize, SMEM_PV);

    // conversions (QKV Q-mma is launch #6 -> ncu -s 5 capture)
    split_plain<<<(S_ * HID_ + 255) / 256, 256>>>(hidden, xhat, S_, HID_);
    transpose_split<<<dim3(HID_ / 32, HID_ / 32, 1), dim3(32, 8)>>>(Wq, HID_, HID_, HID_, wqt, 1);
    transpose_split<<<dim3((NKV_ * D_) / 32, HID_ / 32, 1), dim3(32, 8)>>>(
        Wk, NKV_ * D_, HID_, NKV_ * D_, wkvt, 0);
    transpose_split<<<dim3((NKV_ * D_) / 32, HID_ / 32, 1), dim3(32, 8)>>>(
        Wv, NKV_ * D_, HID_, NKV_ * D_, wkvt + (size_t)(NKV_ * D_) * HID_, 0);
    transpose_split<<<dim3(HID_ / 32, HID_ / 32, 1), dim3(32, 8)>>>(Wo, HID_, HID_, HID_, wot, 0);

    // 6. Q projection (2-term: A=xhat Kp=2*HID)
    mma_gemm<<<dim3(HID_ / 128, S_ / 128, 1), 256, SMEM_GEMM>>>(
        xhat, 0, 2 * HID_, wqt, 0, 0, 2 * HID_,
        qkv, nullptr, 0, QKVN_, 2 * HID_, 0, nullptr);

    // 7. K|V projection (1-term: reads hi half of xhat, Kp=HID)
    mma_gemm<<<dim3((2 * NKV_ * D_) / 128, S_ / 128, 1), 256, SMEM_GEMM>>>(
        xhat, 0, 2 * HID_, wkvt, 0, 0, HID_,
        qkv + HID_, nullptr, 0, QKVN_, HID_, 0, nullptr);

    // RoPE (in place inside g_qkv)
    rope_kernel<<<(S_ * NH_ * 64 + 255) / 256, 256>>>(qkv, NH_, QKVN_);
    rope_kernel<<<(S_ * NKV_ * 64 + 255) / 256, 256>>>(qkv + HID_, NKV_, QKVN_);

    // roped Q/K -> single fp16 per-head; V -> single fp16 V^T
    heads_single<<<(S_ * NH_ * D_ + 255) / 256, 256>>>(qkv, QKVN_, qhat, NH_);
    heads_single<<<(S_ * NKV_ * D_ + 255) / 256, 256>>>(qkv + HID_, QKVN_, khat, NKV_);
    transpose_split<<<dim3(D_ / 32, S_ / 32, NKV_), dim3(32, 8)>>>(
        qkv + HID_ + NKV_ * D_, QKVN_, S_, D_, vthat, 0);

    // zero rowsum accumulator
    cudaMemsetAsync(rsum, 0, NH_ * S_ * sizeof(float));

    // e = fp16(exp(scale * QK^T)), single fp16 both sides, Kp = D
    mma_gemm<<<dim3(S_ / 128, S_ / 128, NH_), 256, SMEM_GEMM>>>(
        qhat, (size_t)S_ * D_, D_, khat, (size_t)S_ * D_, 2, D_,
        nullptr, e, (size_t)S_ * S_, S_, D_, 2, rsum);

    // H2O: invl1, colsum, topk
    invl_kernel<<<NH_ * S_ / 256, 256>>>(rsum, il1);
    colsum_kernel<<<dim3(S_ / 256, NH_), 256>>>();
    topk_kernel<<<NH_, 256>>>();

    // invl2
    rowsum2_kernel<<<dim3(S_ / 8, NH_), 256>>>();

    // fused masked PV -> aohat (single fp16)
    pv_mma<<<dim3(S_ / 128, NH_), 256, SMEM_PV>>>(vthat, e, il2, hbits, aohat);

    // output projection (single fp16 both sides, Kp = HID)
    mma_gemm<<<dim3(HID_ / 128, S_ / 128, 1), 256, SMEM_GEMM>>>(
        aohat, 0, HID_, wot, 0, 0, HID_,
        out, nullptr, 0, HID_, HID_, 0, nullptr);
}

// round 15
// speedup vs baseline: 5.3462x; 1.0994x over previous
#include <cuda_runtime.h>
#include <cuda_fp16.h>
#include <math.h>
#include <stdint.h>

#define S_    2048
#define HID_  2048
#define NH_   16
#define NKV_  4
#define D_    128
#define HB_   204
#define RB_   204
#define SCALE_ 0.08838834764831845f
#define L2E_  1.4426950408889634f
#define QKVN_ 3072

// ----------------------------- scratch ---------------------------------
__device__ float g_qkv[S_ * QKVN_];                 // [s][ q(2048) | k(512) | v(512) ]
__device__ __half g_e[(size_t)NH_ * S_ * S_];       // exp(score) fp16; zero above diagonal
__device__ float g_rowsum[NH_ * S_];
__device__ float g_invl1[NH_ * S_], g_invl2[NH_ * S_];
__device__ float g_colsum[NH_ * S_];
__device__ int   g_heavylist[NH_ * HB_];
__device__ uint32_t g_heavybits[NH_ * 64];

__device__ __half g_xh[(size_t)S_ * HID_];                // single fp16 hidden
__device__ __half g_wqkvt[(size_t)QKVN_ * HID_];          // (Wq|Wk|Wv)^T single fp16
__device__ __half g_wot[(size_t)HID_ * HID_];             // Wo^T single fp16
__device__ __half g_qhat[(size_t)NH_ * S_ * D_];          // single fp16 roped Q
__device__ __half g_khat[(size_t)NKV_ * S_ * D_];         // single fp16 roped K
__device__ __half g_vthat[(size_t)NKV_ * D_ * S_];        // single fp16 V^T
__device__ __half g_aohat[(size_t)S_ * HID_];             // single fp16 attention out

// ----------------------------- PTX helpers ------------------------------
__device__ __forceinline__ uint32_t smem_u32(const void* p) {
    uint32_t a;
    asm("{ .reg .u64 t; cvta.to.shared.u64 t, %1; cvt.u32.u64 %0, t; }" : "=r"(a) : "l"(p));
    return a;
}
__device__ __forceinline__ void cp16(uint32_t saddr, const void* gptr) {
    asm volatile("cp.async.cg.shared.global [%0], [%1], 16;" :: "r"(saddr), "l"(gptr));
}
__device__ __forceinline__ void cp_commit() { asm volatile("cp.async.commit_group;"); }
__device__ __forceinline__ void cp_wait0() { asm volatile("cp.async.wait_group 0;" ::: "memory"); }
__device__ __forceinline__ void cp_wait1() { asm volatile("cp.async.wait_group 1;" ::: "memory"); }

__device__ __forceinline__ void ldsm4(uint32_t& r0, uint32_t& r1, uint32_t& r2, uint32_t& r3,
                                      uint32_t addr) {
    asm volatile("ldmatrix.sync.aligned.m8n8.x4.shared.b16 {%0,%1,%2,%3}, [%4];"
                 : "=r"(r0), "=r"(r1), "=r"(r2), "=r"(r3) : "r"(addr));
}
__device__ __forceinline__ void mma16816(float* d, const uint32_t* a, const uint32_t* b) {
    asm volatile(
        "mma.sync.aligned.m16n8k16.row.col.f32.f16.f16.f32 "
        "{%0,%1,%2,%3}, {%4,%5,%6,%7}, {%8,%9}, {%0,%1,%2,%3};"
        : "+f"(d[0]), "+f"(d[1]), "+f"(d[2]), "+f"(d[3])
        : "r"(a[0]), "r"(a[1]), "r"(a[2]), "r"(a[3]), "r"(b[0]), "r"(b[1]));
}
__device__ __forceinline__ float fexp(float x) {   // e^x via MUFU
    float y;
    asm("ex2.approx.ftz.f32 %0, %1;" : "=f"(y) : "f"(x * L2E_));
    return y;
}
__device__ __forceinline__ float fexp2p3(float x) { // 2^x via FMA pipe, deg-3
    float n = rintf(x);
    float f = x - n;
    float p = 5.5490603e-2f;
    p = fmaf(p, f, 2.4022651e-1f);
    p = fmaf(p, f, 6.9315308e-1f);
    p = fmaf(p, f, 9.9999989e-1f);
    return p * __int_as_float(((int)n + 127) << 23);
}
__device__ __forceinline__ uint32_t packh(float p0, float p1) {
    __half2 h = __floats2half2_rn(p0, p1);
    return *(uint32_t*)&h;
}

// ------------------------- HMMA GEMM -------------------------
__device__ __forceinline__ void load_tile_async(uint32_t sbase, const __half* src,
                                                int ld, int row0, int kbase, int tid) {
#pragma unroll
    for (int t = 0; t < 4; t++) {
        int u = tid + t * 256;
        int row = u >> 3, seg = u & 7;
        uint32_t bo = (uint32_t)(row * 128 + seg * 16);
        bo ^= (bo >> 3) & 0x70;
        cp16(sbase + bo, src + (size_t)(row0 + row) * ld + kbase + seg * 8);
    }
}

// mode 0: plain fp32 store to C.
// mode 2: Eh = fp16(exp(scale*s)) for j<=i (0 above), hybrid exp, fused row sums.
__global__ __launch_bounds__(256, 2) void mma_gemm(
    const __half* __restrict__ A, size_t aStrideZ, int aLd,
    const __half* __restrict__ Bt, size_t bStrideZ, int bShift, int bLd,
    float* __restrict__ C, __half* __restrict__ Eh, size_t cStrideZ, int ldc,
    int Kp, int mode, float* __restrict__ rowsum) {
    int z = blockIdx.z;
    int i0 = blockIdx.y * 128, j0 = blockIdx.x * 128;
    if (mode == 2 && j0 > i0 + 127) return;   // fully above diagonal: skip

    const __half* Az = A + (size_t)z * aStrideZ;
    const __half* Bz = Bt + (size_t)(z >> bShift) * bStrideZ;
    int tid = threadIdx.x, wid = tid >> 5;
    uint32_t lane = tid & 31;

    extern __shared__ char dsm[];
    char* tile = (char*)(((uintptr_t)dsm + 1023) & ~(uintptr_t)1023);
    uint32_t sA[2] = { smem_u32(tile), smem_u32(tile) + 16384 };
    uint32_t sB[2] = { smem_u32(tile) + 32768, smem_u32(tile) + 49152 };

    int warp_m = wid >> 2;
    int warp_n = wid & 3;

    float acc[4][4][4];
#pragma unroll
    for (int i = 0; i < 4; i++)
#pragma unroll
        for (int j = 0; j < 4; j++)
#pragma unroll
            for (int r = 0; r < 4; r++) acc[i][j][r] = 0.f;

    load_tile_async(sA[0], Az, aLd, i0, 0, tid);
    load_tile_async(sB[0], Bz, bLd, j0, 0, tid);
    cp_commit();

    const int NC = Kp >> 6;
    for (int c = 0; c < NC; c++) {
        if (c + 1 < NC) {
            load_tile_async(sA[(c + 1) & 1], Az, aLd, i0, (c + 1) * 64, tid);
            load_tile_async(sB[(c + 1) & 1], Bz, bLd, j0, (c + 1) * 64, tid);
            cp_commit();
            cp_wait1();
        } else {
            cp_wait0();
        }
        __syncthreads();

        uint32_t a_base = sA[c & 1], b_base = sB[c & 1];
#pragma unroll
        for (int ks = 0; ks < 4; ks++) {
            uint32_t a[4][4], b[2][4];
#pragma unroll
            for (int mf = 0; mf < 4; mf++) {
                int row = 64 * warp_m + 16 * mf + (lane & 7) + (((lane >> 3) & 1) << 3);
                int colb = (16 * ks + (((lane >> 4) & 1) << 3)) * 2;
                uint32_t off = (uint32_t)(row * 128 + colb);
                off ^= (off >> 3) & 0x70;
                ldsm4(a[mf][0], a[mf][1], a[mf][2], a[mf][3], a_base + off);
            }
#pragma unroll
            for (int nf2 = 0; nf2 < 2; nf2++) {
                int row = 32 * warp_n + 16 * nf2 + (lane & 7) + (((lane >> 4) & 1) << 3);
                int colb = (16 * ks + (((lane >> 3) & 1) << 3)) * 2;
                uint32_t off = (uint32_t)(row * 128 + colb);
                off ^= (off >> 3) & 0x70;
                ldsm4(b[nf2][0], b[nf2][1], b[nf2][2], b[nf2][3], b_base + off);
            }
#pragma unroll
            for (int mf = 0; mf < 4; mf++)
#pragma unroll
                for (int nf = 0; nf < 4; nf++)
                    mma16816(acc[mf][nf], a[mf], &b[nf >> 1][(nf & 1) * 2]);
        }
        __syncthreads();
    }

    if (mode == 0) {
        float* Cz = C + (size_t)z * cStrideZ;
#pragma unroll
        for (int mf = 0; mf < 4; mf++) {
            int r0 = i0 + 64 * warp_m + 16 * mf + (int)(lane >> 2);
#pragma unroll
            for (int nf = 0; nf < 4; nf++) {
                int c0 = j0 + 32 * warp_n + 8 * nf + (int)(lane & 3) * 2;
                *(float2*)(Cz + (size_t)r0 * ldc + c0) = make_float2(acc[mf][nf][0], acc[mf][nf][1]);
                *(float2*)(Cz + (size_t)(r0 + 8) * ldc + c0) = make_float2(acc[mf][nf][2], acc[mf][nf][3]);
            }
        }
        return;
    }

    // mode 2: exp epilogue (10/16 MUFU + 6/16 deg-3 poly), fp16 store, fused row sums
    __half* Ez = Eh + (size_t)z * cStrideZ;
    const float cl = SCALE_ * L2E_;
    float rs0[4], rs1[4];
#pragma unroll
    for (int mf = 0; mf < 4; mf++) {
        int r0 = i0 + 64 * warp_m + 16 * mf + (int)(lane >> 2);
        float s0 = 0.f, s1 = 0.f;
#pragma unroll
        for (int nf = 0; nf < 4; nf++) {
            int c0 = j0 + 32 * warp_n + 8 * nf + (int)(lane & 3) * 2;
            float d0 = acc[mf][nf][0], d1 = acc[mf][nf][1];
            float d2 = acc[mf][nf][2], d3 = acc[mf][nf][3];
            if (nf < 2) {
                d0 = (c0     <= r0)     ? fexp(d0 * SCALE_) : 0.f;
                d1 = (c0 + 1 <= r0)     ? fexp(d1 * SCALE_) : 0.f;
                d2 = (c0     <= r0 + 8) ? fexp(d2 * SCALE_) : 0.f;
                d3 = (c0 + 1 <= r0 + 8) ? fexp(d3 * SCALE_) : 0.f;
            } else if (nf == 2) {
                d0 = (c0     <= r0)     ? fexp(d0 * SCALE_) : 0.f;
                d1 = (c0 + 1 <= r0)     ? fexp(d1 * SCALE_) : 0.f;
                d2 = (c0     <= r0 + 8) ? fexp2p3(d2 * cl) : 0.f;
                d3 = (c0 + 1 <= r0 + 8) ? fexp2p3(d3 * cl) : 0.f;
            } else {
                d0 = (c0     <= r0)     ? fexp2p3(d0 * cl) : 0.f;
                d1 = (c0 + 1 <= r0)     ? fexp2p3(d1 * cl) : 0.f;
                d2 = (c0     <= r0 + 8) ? fexp2p3(d2 * cl) : 0.f;
                d3 = (c0 + 1 <= r0 + 8) ? fexp2p3(d3 * cl) : 0.f;
            }
            __half2 h01 = __floats2half2_rn(d0, d1);
            __half2 h23 = __floats2half2_rn(d2, d3);
            *(uint32_t*)(Ez + (size_t)r0 * ldc + c0) = *(uint32_t*)&h01;
            *(uint32_t*)(Ez + (size_t)(r0 + 8) * ldc + c0) = *(uint32_t*)&h23;
            float2 f01 = __half22float2(h01);
            float2 f23 = __half22float2(h23);
            s0 += f01.x + f01.y;
            s1 += f23.x + f23.y;
        }
        rs0[mf] = s0; rs1[mf] = s1;
    }
    {
        float* rz = rowsum + (size_t)z * S_;
#pragma unroll
        for (int mf = 0; mf < 4; mf++) {
            float v0 = rs0[mf], v1 = rs1[mf];
            v0 += __shfl_xor_sync(0xFFFFFFFF, v0, 1);
            v0 += __shfl_xor_sync(0xFFFFFFFF, v0, 2);
            v1 += __shfl_xor_sync(0xFFFFFFFF, v1, 1);
            v1 += __shfl_xor_sync(0xFFFFFFFF, v1, 2);
            if ((lane & 3) == 0) {
                int r0 = i0 + 64 * warp_m + 16 * mf + (int)(lane >> 2);
                atomicAdd(rz + r0, v0);
                atomicAdd(rz + r0 + 8, v1);
            }
        }
    }
}

// ------------------ fused PV (masked P on the fly, single-pass fp16) --------------
__global__ __launch_bounds__(256, 2) void pv_mma(
    const __half* __restrict__ vthat,
    const __half* __restrict__ e, const float* __restrict__ invl2,
    const uint32_t* __restrict__ heavybits,
    __half* __restrict__ aohat) {
    int i0 = (int)(gridDim.x - 1 - blockIdx.x) * 128;   // heavy blocks first
    int h = blockIdx.y, kh = h >> 2;
    int tid = threadIdx.x, wid = tid >> 5;
    uint32_t lane = tid & 31;
    int warp_m = wid >> 2, warp_n = wid & 3;

    extern __shared__ char dsm[];
    char* tile = (char*)(((uintptr_t)dsm + 1023) & ~(uintptr_t)1023);
    char* pP = tile;
    uint32_t sP = smem_u32(pP);
    uint32_t sV[2] = { smem_u32(tile) + 16384, smem_u32(tile) + 32768 };

    __shared__ uint32_t sbits[64];
    if (tid < 64) sbits[tid] = heavybits[h * 64 + tid];

    int r = tid >> 1, half = tid & 1;
    int gi = i0 + r;
    float il = invl2[h * S_ + gi];
    const __half* erow = e + ((size_t)h * S_ + gi) * S_ + half * 32;
    const __half* Vz = vthat + (size_t)kh * D_ * S_;

    float acc[4][4][4];
#pragma unroll
    for (int i = 0; i < 4; i++)
#pragma unroll
        for (int j = 0; j < 4; j++)
#pragma unroll
            for (int q = 0; q < 4; q++) acc[i][j][q] = 0.f;

    const int NCH = (i0 >> 6) + 2;
    load_tile_async(sV[0], Vz, S_, 0, 0, tid);
    cp_commit();
    __syncthreads();

    for (int c = 0; c < NCH; c++) {
        int j0 = c * 64;
        bool pre = (c + 1 < NCH);
        if (pre) {
            load_tile_async(sV[(c + 1) & 1], Vz, S_, 0, (c + 1) * 64, tid);
            cp_commit();
        }
        uint32_t hib[16];
        const __half* ep = erow + j0;
        int gjb = j0 + half * 32;
#pragma unroll
        for (int w = 0; w < 4; w++) {
            uint4 ev = *(const uint4*)(ep + w * 8);
            float2 f0 = __half22float2(*(__half2*)&ev.x);
            float2 f1 = __half22float2(*(__half2*)&ev.y);
            float2 f2 = __half22float2(*(__half2*)&ev.z);
            float2 f3 = __half22float2(*(__half2*)&ev.w);
            float pv[8] = { f0.x, f0.y, f1.x, f1.y, f2.x, f2.y, f3.x, f3.y };
#pragma unroll
            for (int u = 0; u < 8; u++) {
                int gj = gjb + w * 8 + u;
                bool keep = (gj <= gi) &&
                            ((gi - gj <= RB_) || ((sbits[gj >> 5] >> (gj & 31)) & 1u));
                pv[u] = keep ? pv[u] * il : 0.f;
            }
            hib[w * 4 + 0] = packh(pv[0], pv[1]);
            hib[w * 4 + 1] = packh(pv[2], pv[3]);
            hib[w * 4 + 2] = packh(pv[4], pv[5]);
            hib[w * 4 + 3] = packh(pv[6], pv[7]);
        }
#pragma unroll
        for (int sg = 0; sg < 4; sg++) {
            uint32_t bo = (uint32_t)(r * 128 + half * 64 + sg * 16);
            bo ^= (bo >> 3) & 0x70;
            *(uint4*)(pP + bo) = make_uint4(hib[sg * 4], hib[sg * 4 + 1], hib[sg * 4 + 2], hib[sg * 4 + 3]);
        }
        if (pre) cp_wait1(); else cp_wait0();
        __syncthreads();

        uint32_t b_base = sV[c & 1];
#pragma unroll
        for (int ks = 0; ks < 4; ks++) {
            uint32_t a[4][4], b[2][4];
#pragma unroll
            for (int mf = 0; mf < 4; mf++) {
                int row = 64 * warp_m + 16 * mf + (lane & 7) + (((lane >> 3) & 1) << 3);
                int colb = (16 * ks + (((lane >> 4) & 1) << 3)) * 2;
                uint32_t off = (uint32_t)(row * 128 + colb);
                off ^= (off >> 3) & 0x70;
                ldsm4(a[mf][0], a[mf][1], a[mf][2], a[mf][3], sP + off);
            }
#pragma unroll
            for (int nf2 = 0; nf2 < 2; nf2++) {
                int row = 32 * warp_n + 16 * nf2 + (lane & 7) + (((lane >> 4) & 1) << 3);
                int colb = (16 * ks + (((lane >> 3) & 1) << 3)) * 2;
                uint32_t off = (uint32_t)(row * 128 + colb);
                off ^= (off >> 3) & 0x70;
                ldsm4(b[nf2][0], b[nf2][1], b[nf2][2], b[nf2][3], b_base + off);
            }
#pragma unroll
            for (int mf = 0; mf < 4; mf++)
#pragma unroll
                for (int nf = 0; nf < 4; nf++)
                    mma16816(acc[mf][nf], a[mf], &b[nf >> 1][(nf & 1) * 2]);
        }
        __syncthreads();
    }

#pragma unroll
    for (int mf = 0; mf < 4; mf++) {
        int r0 = i0 + 64 * warp_m + 16 * mf + (int)(lane >> 2);
#pragma unroll
        for (int nf = 0; nf < 4; nf++) {
            int c0 = 32 * warp_n + 8 * nf + (int)(lane & 3) * 2;
#pragma unroll
            for (int rr = 0; rr < 2; rr++) {
                uint32_t hi = packh(acc[mf][nf][rr * 2], acc[mf][nf][rr * 2 + 1]);
                size_t b0 = (size_t)(r0 + rr * 8) * HID_ + h * D_ + c0;
                *(uint32_t*)(aohat + b0) = hi;
            }
        }
    }
}

// ----------------------- conversion kernels -------------------
__global__ void tofp16_kernel(const float* __restrict__ A, __half* __restrict__ out, int n) {
    int idx = blockIdx.x * blockDim.x + threadIdx.x;
    if (idx < n) out[idx] = __float2half_rn(A[idx]);
}

// single fp16 per-head layout: out[h][s][d]
__global__ void heads_single(const float* __restrict__ src, int ld,
                             __half* __restrict__ out, int nh) {
    int idx = blockIdx.x * blockDim.x + threadIdx.x;
    if (idx >= S_ * nh * D_) return;
    int d = idx & 127;
    int h = (idx >> 7) % nh;
    int s = idx / (nh * D_);
    float x = src[(size_t)s * ld + h * D_ + d];
    out[((size_t)h * S_ + s) * D_ + d] = __float2half_rn(x);
}

// transpose + fp16 (single, width K)
__global__ void transpose_half(const float* __restrict__ src, int ldsrc, int K, int Nper,
                               __half* __restrict__ out) {
    int z = blockIdx.z;
    const float* s = src + (size_t)z * Nper;
    __half* o = out + (size_t)z * Nper * K;
    __shared__ float t[32][33];
    int k0 = blockIdx.y * 32, n0 = blockIdx.x * 32;
    int tx = threadIdx.x, ty = threadIdx.y;
#pragma unroll
    for (int r = 0; r < 4; r++) {
        int k = k0 + ty + 8 * r;
        t[ty + 8 * r][tx] = s[(size_t)k * ldsrc + n0 + tx];
    }
    __syncthreads();
#pragma unroll
    for (int r = 0; r < 4; r++) {
        int n = n0 + ty + 8 * r, k = k0 + tx;
        o[(size_t)n * K + k] = __float2half_rn(t[tx][ty + 8 * r]);
    }
}

// --------------------------------- RoPE ---------------------------------
__global__ void rope_kernel(float* x, int nh, int ld) {
    int idx = blockIdx.x * blockDim.x + threadIdx.x;
    if (idx >= S_ * nh * 64) return;
    int d = idx & 63;
    int rest = idx >> 6;
    int h = rest % nh;
    int s = rest / nh;
    float* base = x + (size_t)s * ld + h * 128;
    float x1 = base[d], x2 = base[d + 64];
    float inv = powf(10000.f, -(float)d * (1.f / 64.f));
    float ang = (float)s * inv;
    float c, sn;
    sincosf(ang, &sn, &c);
    base[d] = x1 * c - x2 * sn;
    base[d + 64] = x2 * c + x1 * sn;
}

// ------------------ invl1 = 1 / rowsum -----------------------------------
__global__ void invl_kernel(const float* __restrict__ rs, float* __restrict__ il) {
    int i = blockIdx.x * 256 + threadIdx.x;
    il[i] = 1.f / rs[i];
}

// coalesced column sums over fp16 e (rows above diagonal are exactly zero)
__global__ __launch_bounds__(256) void colsum_kernel() {
    int h = blockIdx.y;
    int j0 = blockIdx.x * 256;
    int j = j0 + threadIdx.x;
    const __half* base = g_e + (size_t)h * S_ * S_;
    __shared__ float il[S_];
    for (int i = j0 + threadIdx.x; i < S_; i += 256)
        il[i] = g_invl1[h * S_ + i];
    __syncthreads();
    float a0 = 0.f, a1 = 0.f, a2 = 0.f, a3 = 0.f;
    for (int i = j0; i < S_; i += 4) {
        a0 += __half2float(base[(size_t)(i    ) * S_ + j]) * il[i];
        a1 += __half2float(base[(size_t)(i + 1) * S_ + j]) * il[i + 1];
        a2 += __half2float(base[(size_t)(i + 2) * S_ + j]) * il[i + 2];
        a3 += __half2float(base[(size_t)(i + 3) * S_ + j]) * il[i + 3];
    }
    g_colsum[h * S_ + j] = (a0 + a1) + (a2 + a3);
}

__global__ __launch_bounds__(256) void topk_kernel() {
    int h = blockIdx.x;
    int tid = threadIdx.x;
    int lane = tid & 31, w = tid >> 5;
    __shared__ float vals[S_];
    __shared__ float wbv[8];
    __shared__ int wbi[8];
    __shared__ uint32_t bits[64];
    for (int j = tid; j < S_; j += 256) vals[j] = g_colsum[h * S_ + j];
    if (tid < 64) bits[tid] = 0;
    __syncthreads();
    for (int it = 0; it < HB_; it++) {
        float best = -INFINITY; int besti = 1 << 30;
        for (int j = tid; j < S_; j += 256) {
            float v = vals[j];
            if (v > best || (v == best && j < besti)) { best = v; besti = j; }
        }
#pragma unroll
        for (int off = 16; off > 0; off >>= 1) {
            float ov = __shfl_xor_sync(0xFFFFFFFF, best, off);
            int oi = __shfl_xor_sync(0xFFFFFFFF, besti, off);
            if (ov > best || (ov == best && oi < besti)) { best = ov; besti = oi; }
        }
        if (lane == 0) { wbv[w] = best; wbi[w] = besti; }
        __syncthreads();
        if (tid == 0) {
            float b = wbv[0]; int bi2 = wbi[0];
#pragma unroll
            for (int q = 1; q < 8; q++)
                if (wbv[q] > b || (wbv[q] == b && wbi[q] < bi2)) { b = wbv[q]; bi2 = wbi[q]; }
            g_heavylist[h * HB_ + it] = bi2;
            bits[bi2 >> 5] |= (1u << (bi2 & 31));
            vals[bi2] = -INFINITY;
        }
        __syncthreads();
    }
    if (tid < 64) g_heavybits[h * 64 + tid] = bits[tid];
}

// ------ pass-2: invl2 = 1/sum(e over band + heavy) ------
__global__ __launch_bounds__(256) void rowsum2_kernel() {
    int h = blockIdx.y;
    int tid = threadIdx.x;
    __shared__ int hl[HB_];
    for (int t = tid; t < HB_; t += 256) hl[t] = g_heavylist[h * HB_ + t];
    __syncthreads();

    int w = tid >> 5, lane = tid & 31;
    int i = blockIdx.x * 8 + w;
    const __half* erow = g_e + (size_t)(h * S_ + i) * S_;
    int lo = i - RB_; if (lo < 0) lo = 0;

    float l = 0.f;
    for (int j = lo + lane; j <= i; j += 32) l += __half2float(erow[j]);
    for (int t = lane; t < HB_; t += 32) {
        int j = hl[t];
        if (j < lo) l += __half2float(erow[j]);
    }
#pragma unroll
    for (int off = 16; off > 0; off >>= 1)
        l += __shfl_xor_sync(0xFFFFFFFF, l, off);
    if (lane == 0) g_invl2[h * S_ + i] = 1.f / l;
}

// ------------------------------ launcher ---------------------------------
extern "C" void kernel_launch(void* const* d_in, const int* in_sizes, int n_in,
                              void* d_out, int out_size) {
    const float* hidden = (const float*)d_in[0];
    const float* Wq = (const float*)d_in[1];
    const float* Wk = (const float*)d_in[2];
    const float* Wv = (const float*)d_in[3];
    const float* Wo = (const float*)d_in[4];
    float* out = (float*)d_out;

    float *qkv, *rsum, *il1, *il2;
    __half* e;
    uint32_t* hbits;
    __half *xh, *wqkvt, *wot, *qhat, *khat, *vthat, *aohat;
    cudaGetSymbolAddress((void**)&qkv, g_qkv);
    cudaGetSymbolAddress((void**)&e, g_e);
    cudaGetSymbolAddress((void**)&rsum, g_rowsum);
    cudaGetSymbolAddress((void**)&il1, g_invl1);
    cudaGetSymbolAddress((void**)&il2, g_invl2);
    cudaGetSymbolAddress((void**)&hbits, g_heavybits);
    cudaGetSymbolAddress((void**)&xh, g_xh);
    cudaGetSymbolAddress((void**)&wqkvt, g_wqkvt);
    cudaGetSymbolAddress((void**)&wot, g_wot);
    cudaGetSymbolAddress((void**)&qhat, g_qhat);
    cudaGetSymbolAddress((void**)&khat, g_khat);
    cudaGetSymbolAddress((void**)&vthat, g_vthat);
    cudaGetSymbolAddress((void**)&aohat, g_aohat);

    const int SMEM_GEMM = 66560;
    const int SMEM_PV = 50176;
    cudaFuncSetAttribute(mma_gemm, cudaFuncAttributeMaxDynamicSharedMemorySize, SMEM_GEMM);
    cudaFuncSetAttribute(pv_mma, cudaFuncAttributeMaxDynamicSharedMemorySize, SMEM_PV);

    // conversions (QKV mma is launch #6 -> ncu -s 5 capture)
    tofp16_kernel<<<(S_ * HID_ + 255) / 256, 256>>>(hidden, xh, S_ * HID_);
    transpose_half<<<dim3(HID_ / 32, HID_ / 32, 1), dim3(32, 8)>>>(Wq, HID_, HID_, HID_, wqkvt);
    transpose_half<<<dim3((NKV_ * D_) / 32, HID_ / 32, 1), dim3(32, 8)>>>(
        Wk, NKV_ * D_, HID_, NKV_ * D_, wqkvt + (size_t)HID_ * HID_);
    transpose_half<<<dim3((NKV_ * D_) / 32, HID_ / 32, 1), dim3(32, 8)>>>(
        Wv, NKV_ * D_, HID_, NKV_ * D_, wqkvt + (size_t)(HID_ + NKV_ * D_) * HID_);
    transpose_half<<<dim3(HID_ / 32, HID_ / 32, 1), dim3(32, 8)>>>(Wo, HID_, HID_, HID_, wot);

    // 6. fused QKV projection (single fp16, one GEMM: 2048x3072x2048)
    mma_gemm<<<dim3(QKVN_ / 128, S_ / 128, 1), 256, SMEM_GEMM>>>(
        xh, 0, HID_, wqkvt, 0, 0, HID_,
        qkv, nullptr, 0, QKVN_, HID_, 0, nullptr);

    // RoPE (in place inside g_qkv)
    rope_kernel<<<(S_ * NH_ * 64 + 255) / 256, 256>>>(qkv, NH_, QKVN_);
    rope_kernel<<<(S_ * NKV_ * 64 + 255) / 256, 256>>>(qkv + HID_, NKV_, QKVN_);

    // roped Q/K -> single fp16 per-head; V -> single fp16 V^T
    heads_single<<<(S_ * NH_ * D_ + 255) / 256, 256>>>(qkv, QKVN_, qhat, NH_);
    heads_single<<<(S_ * NKV_ * D_ + 255) / 256, 256>>>(qkv + HID_, QKVN_, khat, NKV_);
    transpose_half<<<dim3(D_ / 32, S_ / 32, NKV_), dim3(32, 8)>>>(
        qkv + HID_ + NKV_ * D_, QKVN_, S_, D_, vthat);

    // zero rowsum accumulator
    cudaMemsetAsync(rsum, 0, NH_ * S_ * sizeof(float));

    // e = fp16(exp(scale * QK^T)), single fp16 both sides, Kp = D
    mma_gemm<<<dim3(S_ / 128, S_ / 128, NH_), 256, SMEM_GEMM>>>(
        qhat, (size_t)S_ * D_, D_, khat, (size_t)S_ * D_, 2, D_,
        nullptr, e, (size_t)S_ * S_, S_, D_, 2, rsum);

    // H2O: invl1, colsum, topk
    invl_kernel<<<NH_ * S_ / 256, 256>>>(rsum, il1);
    colsum_kernel<<<dim3(S_ / 256, NH_), 256>>>();
    topk_kernel<<<NH_, 256>>>();

    // invl2
    rowsum2_kernel<<<dim3(S_ / 8, NH_), 256>>>();

    // fused masked PV -> aohat (single fp16)
    pv_mma<<<dim3(S_ / 128, NH_), 256, SMEM_PV>>>(vthat, e, il2, hbits, aohat);

    // output projection (single fp16 both sides, Kp = HID)
    mma_gemm<<<dim3(HID_ / 128, S_ / 128, 1), 256, SMEM_GEMM>>>(
        aohat, 0, HID_, wot, 0, 0, HID_,
        out, nullptr, 0, HID_, HID_, 0, nullptr);
}